// round 6
// baseline (speedup 1.0000x reference)
#include <cuda_runtime.h>
#include <cuda_bf16.h>
#include <math.h>
#include <stdint.h>

#define G   4096
#define NN  64
#define EE  256
#define FF  64
#define DD  128
#define EPN 32768

// ---------------- device scratch (static, no allocations) ----------------
__device__ float d_gembs[G * DD];
__device__ float d_deg[G];
__device__ float d_agg1[G * DD];
__device__ float d_h[G * 256];
__device__ float d_agg2[G * 256];
__device__ float d_mu[G * DD];
__device__ float d_ls[G * DD];
__device__ float d_zc[G * 256];
__device__ float d_zl1[G * 256];
__device__ float d_zl2[G * 256];
__device__ float d_sums[8];   // 0:pen 1:plog 2:nlog 3:kl
// transposed bf16 hi/lo weights [N][K]: Wg[0,8192) Wc1[8192,40960) Wmu[40960,73728)
// Wls[73728,106496) Wl1[106496,172032) Wl2[172032,237568) Wf1[237568,239616)
__device__ __nv_bfloat16 d_wth[239616];
__device__ __nv_bfloat16 d_wtl[239616];

// ---------------- helpers ----------------
__device__ __forceinline__ void mma_bf16(float* c, const uint32_t* a, const uint32_t* b) {
    asm volatile("mma.sync.aligned.m16n8k16.row.col.f32.bf16.bf16.f32 "
        "{%0,%1,%2,%3}, {%4,%5,%6,%7}, {%8,%9}, {%0,%1,%2,%3};"
        : "+f"(c[0]), "+f"(c[1]), "+f"(c[2]), "+f"(c[3])
        : "r"(a[0]), "r"(a[1]), "r"(a[2]), "r"(a[3]), "r"(b[0]), "r"(b[1]));
}
__device__ __forceinline__ void cvt_split2(float x, float y, uint32_t& hi, uint32_t& lo) {
    __nv_bfloat162 h = __floats2bfloat162_rn(x, y);
    float rx = x - __bfloat162float(h.x);
    float ry = y - __bfloat162float(h.y);
    __nv_bfloat162 l = __floats2bfloat162_rn(rx, ry);
    hi = *(uint32_t*)&h;
    lo = *(uint32_t*)&l;
}

// ---------------- zero scratch accumulators ----------------
__global__ void k_zero() {
    int i = blockIdx.x * blockDim.x + threadIdx.x;
    int stride = gridDim.x * blockDim.x;
    for (int j = i; j < G * 256; j += stride) d_agg2[j] = 0.f;
    for (int j = i; j < G * DD; j += stride) d_agg1[j] = 0.f;
    for (int j = i; j < G; j += stride) d_deg[j] = 0.f;
    if (i < 8) d_sums[i] = 0.f;
}

// ---------------- weight transpose + bf16 hi/lo split ----------------
__global__ void k_prepw(const float* __restrict__ W0, const float* __restrict__ W1,
                        const float* __restrict__ W2, const float* __restrict__ W3,
                        const float* __restrict__ W4, const float* __restrict__ W5,
                        const float* __restrict__ W6) {
    const float* Ws[7] = {W0, W1, W2, W3, W4, W5, W6};
    const int Ks[7] = {64, 128, 256, 256, 256, 256, 128};
    const int Ns[7] = {128, 256, 128, 128, 256, 256, 16};
    const int offs[8] = {0, 8192, 40960, 73728, 106496, 172032, 237568, 239616};
    int i = blockIdx.x * blockDim.x + threadIdx.x;
    if (i >= 239616) return;
    int s = 0;
    while (i >= offs[s + 1]) s++;
    int local = i - offs[s];
    int K = Ks[s], N = Ns[s];
    int n = local / K, k = local - n * K;
    float v = Ws[s][k * N + n];
    __nv_bfloat16 h = __float2bfloat16(v);
    d_wth[i] = h;
    d_wtl[i] = __float2bfloat16(v - __bfloat162float(h));
}

// ---------------- fully fused per-graph kernel (2 graphs / block) ----------------
// xw = x@Wg (HMMA split) -> CSR aggregate -> h (smem bf16 hi/lo) -> g_emb
// -> a1 = tanh(h@Wf1+b) (HMMA split) -> S softmax -> Laplacian penalty.
#define XST 132   // sxw row stride (floats)
#define HST 136   // h row stride (bf16)
__global__ void __launch_bounds__(256) k_xwagg(
    const float* __restrict__ x, const int* __restrict__ ei, const float* __restrict__ ew,
    const float* __restrict__ bg, const float* __restrict__ bf1,
    const float* __restrict__ Wf2, const float* __restrict__ bf2)
{
    extern __shared__ char dyn[];
    // region0 [0,67584): staging sAh|sAl|sBh|sBl each [128][40] bf16; then sxw [128][XST] f32
    __nv_bfloat16* sAh = (__nv_bfloat16*)dyn;
    __nv_bfloat16* sAl = sAh + 128 * 40;
    __nv_bfloat16* sBh = sAl + 128 * 40;
    __nv_bfloat16* sBl = sBh + 128 * 40;
    float* sxw = (float*)dyn;
    // region1 [67584, +69632): h as bf16 hi/lo [128][HST]
    __nv_bfloat16* shh = (__nv_bfloat16*)(dyn + 67584);
    __nv_bfloat16* shl = shh + 128 * HST;

    __shared__ int   esrc[512];
    __shared__ float enorm[512];
    __shared__ float sdeg[128], sdinv[128], sdeg2[128], sdv2[128];
    __shared__ int   scnt[128], sstart[132], spos[128];
    __shared__ float sS[256];
    __shared__ float sped[8];   // per-graph a00,a01,a10,a11

    int t = threadIdx.x, lane = t & 31, warp = t >> 5;
    int warpM = warp >> 2, warpN = warp & 3;
    size_t blockRow = (size_t)blockIdx.x * 128;
    const float* A = x + blockRow * 64;
    int g0 = blockIdx.x * 2;

    // ---- phase 1: edges, degrees, CSR ----
    int e_es[2], e_ed[2];
    float e_w[2];
#pragma unroll
    for (int j = 0; j < 2; j++) {
        e_es[j] = ei[(size_t)(g0 + j) * 512 + t];
        e_ed[j] = ei[(size_t)(g0 + j) * 512 + 256 + t];
        e_w[j]  = ew[(size_t)(g0 + j) * 256 + t];
    }
    if (t < 128) { sdeg[t] = 0.f; sdeg2[t] = 0.f; scnt[t] = 0; }
    if (t < 8) sped[t] = 0.f;
    __syncthreads();
#pragma unroll
    for (int j = 0; j < 2; j++) {
        atomicAdd(&sdeg[j * 64 + e_ed[j]], e_w[j]);
        atomicAdd(&sdeg2[j * 64 + e_es[j]], e_w[j]);
        atomicAdd(&scnt[j * 64 + e_ed[j]], 1);
    }
    __syncthreads();
    if (t < 128) {
        sdinv[t] = rsqrtf(sdeg[t] + 1.0f);
        float d2 = sdeg2[t];
        sdv2[t] = (d2 > 0.f) ? rsqrtf(fmaxf(d2, 1e-30f)) : 0.f;
    }
    if (t < 2) {
        int s = t * 256;
        for (int n = 0; n < 64; n++) { sstart[t * 65 + n] = s; s += scnt[t * 64 + n]; }
        sstart[t * 65 + 64] = s;
    }
    __syncthreads();
    if (t < 128) spos[t] = sstart[(t >> 6) * 65 + (t & 63)];
    __syncthreads();
#pragma unroll
    for (int j = 0; j < 2; j++) {
        int p = atomicAdd(&spos[j * 64 + e_ed[j]], 1);
        esrc[p]  = j * 64 + e_es[j];
        enorm[p] = sdinv[j * 64 + e_es[j]] * e_w[j] * sdinv[j * 64 + e_ed[j]];
    }
    // (first mma __syncthreads orders the fill)

    // ---- phase 2: HMMA xw = x @ Wg (K=64, split bf16) ----
    float acc[4][4][4];
#pragma unroll
    for (int mt = 0; mt < 4; mt++)
#pragma unroll
        for (int nt = 0; nt < 4; nt++)
#pragma unroll
            for (int j = 0; j < 4; j++) acc[mt][nt][j] = 0.f;

    int ldr = t >> 1, ldc = (t & 1) * 16;
    for (int kc = 0; kc < 64; kc += 32) {
        const float* Ar = A + (size_t)ldr * 64 + kc + ldc;
#pragma unroll
        for (int j = 0; j < 4; j++) {
            float4 v = *(const float4*)(Ar + j * 4);
            uint32_t h0, l0, h1, l1;
            cvt_split2(v.x, v.y, h0, l0);
            cvt_split2(v.z, v.w, h1, l1);
            *(uint32_t*)&sAh[ldr * 40 + ldc + j * 4]     = h0;
            *(uint32_t*)&sAh[ldr * 40 + ldc + j * 4 + 2] = h1;
            *(uint32_t*)&sAl[ldr * 40 + ldc + j * 4]     = l0;
            *(uint32_t*)&sAl[ldr * 40 + ldc + j * 4 + 2] = l1;
        }
        {
            const __nv_bfloat16* bh = d_wth + (size_t)ldr * 64 + kc + ldc;
            const __nv_bfloat16* bl = d_wtl + (size_t)ldr * 64 + kc + ldc;
            *(uint4*)&sBh[ldr * 40 + ldc]     = *(const uint4*)bh;
            *(uint4*)&sBh[ldr * 40 + ldc + 8] = *(const uint4*)(bh + 8);
            *(uint4*)&sBl[ldr * 40 + ldc]     = *(const uint4*)bl;
            *(uint4*)&sBl[ldr * 40 + ldc + 8] = *(const uint4*)(bl + 8);
        }
        __syncthreads();
#pragma unroll
        for (int ks = 0; ks < 32; ks += 16) {
            int kb = ks + (lane & 3) * 2;
            int ar = warpM * 64 + (lane >> 2);
            uint32_t ah[4][4], al[4][4];
#pragma unroll
            for (int mt = 0; mt < 4; mt++) {
                int r = ar + mt * 16;
                ah[mt][0] = *(const uint32_t*)&sAh[r * 40 + kb];
                ah[mt][1] = *(const uint32_t*)&sAh[(r + 8) * 40 + kb];
                ah[mt][2] = *(const uint32_t*)&sAh[r * 40 + kb + 8];
                ah[mt][3] = *(const uint32_t*)&sAh[(r + 8) * 40 + kb + 8];
                al[mt][0] = *(const uint32_t*)&sAl[r * 40 + kb];
                al[mt][1] = *(const uint32_t*)&sAl[(r + 8) * 40 + kb];
                al[mt][2] = *(const uint32_t*)&sAl[r * 40 + kb + 8];
                al[mt][3] = *(const uint32_t*)&sAl[(r + 8) * 40 + kb + 8];
            }
            uint32_t bhf[4][2], blf[4][2];
#pragma unroll
            for (int nt = 0; nt < 4; nt++) {
                int r = warpN * 32 + nt * 8 + (lane >> 2);
                bhf[nt][0] = *(const uint32_t*)&sBh[r * 40 + kb];
                bhf[nt][1] = *(const uint32_t*)&sBh[r * 40 + kb + 8];
                blf[nt][0] = *(const uint32_t*)&sBl[r * 40 + kb];
                blf[nt][1] = *(const uint32_t*)&sBl[r * 40 + kb + 8];
            }
#pragma unroll
            for (int mt = 0; mt < 4; mt++)
#pragma unroll
                for (int nt = 0; nt < 4; nt++) {
                    mma_bf16(acc[mt][nt], ah[mt], bhf[nt]);
                    mma_bf16(acc[mt][nt], ah[mt], blf[nt]);
                    mma_bf16(acc[mt][nt], al[mt], bhf[nt]);
                }
        }
        __syncthreads();
    }

    // ---- park xw in smem ----
#pragma unroll
    for (int mt = 0; mt < 4; mt++) {
        int r0 = warpM * 64 + mt * 16 + (lane >> 2);
#pragma unroll
        for (int nt = 0; nt < 4; nt++) {
            int cl = warpN * 32 + nt * 8 + (lane & 3) * 2;
            float2 v0, v1;
            v0.x = acc[mt][nt][0]; v0.y = acc[mt][nt][1];
            v1.x = acc[mt][nt][2]; v1.y = acc[mt][nt][3];
            *(float2*)&sxw[r0 * XST + cl] = v0;
            *(float2*)&sxw[(r0 + 8) * XST + cl] = v1;
        }
    }
    __syncthreads();

    // ---- phase 3: CSR aggregation -> h (bf16 split, smem) + g_emb ----
    {
        int gr = t >> 7, c = t & 127;
        float bias = bg[c];
        float gsum = 0.f;
#pragma unroll 4
        for (int n = 0; n < 64; n++) {
            float a2 = 0.f;
            int e0 = sstart[gr * 65 + n], e1 = sstart[gr * 65 + n + 1];
            for (int e = e0; e < e1; e++)
                a2 = fmaf(sxw[esrc[e] * XST + c], enorm[e], a2);
            float di = sdinv[gr * 64 + n];
            float hv = a2 + sxw[(gr * 64 + n) * XST + c] * di * di + bias;
            gsum += hv;
            int row = gr * 64 + n;
            __nv_bfloat16 hb = __float2bfloat16(hv);
            shh[row * HST + c] = hb;
            shl[row * HST + c] = __float2bfloat16(hv - __bfloat162float(hb));
        }
        d_gembs[(size_t)(g0 + gr) * 128 + c] = 0.5f * gsum;
    }
    __syncthreads();

    // ---- phase 4: a1 = tanh(h @ Wf1 + bf1), logits, softmax -> sS ----
    {
        int r = lane >> 2, kb2 = (lane & 3) * 2;
        float a16[2][4];
#pragma unroll
        for (int nt = 0; nt < 2; nt++)
#pragma unroll
            for (int j = 0; j < 4; j++) a16[nt][j] = 0.f;
        const __nv_bfloat16* Bh = d_wth + 237568;
        const __nv_bfloat16* Bl = d_wtl + 237568;
        int rowW = warp * 16;
#pragma unroll
        for (int ks = 0; ks < 8; ks++) {
            int k0 = ks * 16 + kb2;
            uint32_t ah[4], al[4];
            ah[0] = *(const uint32_t*)&shh[(rowW + r) * HST + k0];
            ah[1] = *(const uint32_t*)&shh[(rowW + r + 8) * HST + k0];
            ah[2] = *(const uint32_t*)&shh[(rowW + r) * HST + k0 + 8];
            ah[3] = *(const uint32_t*)&shh[(rowW + r + 8) * HST + k0 + 8];
            al[0] = *(const uint32_t*)&shl[(rowW + r) * HST + k0];
            al[1] = *(const uint32_t*)&shl[(rowW + r + 8) * HST + k0];
            al[2] = *(const uint32_t*)&shl[(rowW + r) * HST + k0 + 8];
            al[3] = *(const uint32_t*)&shl[(rowW + r + 8) * HST + k0 + 8];
#pragma unroll
            for (int nt = 0; nt < 2; nt++) {
                int n = nt * 8 + r;
                uint32_t bh[2], bl[2];
                bh[0] = *(const uint32_t*)(Bh + n * 128 + k0);
                bh[1] = *(const uint32_t*)(Bh + n * 128 + k0 + 8);
                bl[0] = *(const uint32_t*)(Bl + n * 128 + k0);
                bl[1] = *(const uint32_t*)(Bl + n * 128 + k0 + 8);
                mma_bf16(a16[nt], ah, bh);
                mma_bf16(a16[nt], ah, bl);
                mma_bf16(a16[nt], al, bh);
            }
        }
        // logits for rows rowW+r (vals 0,1) and rowW+r+8 (vals 2,3)
        float l0a = 0.f, l1a = 0.f, l0b = 0.f, l1b = 0.f;
#pragma unroll
        for (int nt = 0; nt < 2; nt++) {
            int c0 = nt * 8 + (lane & 3) * 2;
            float b0 = bf1[c0], b1 = bf1[c0 + 1];
            float w00 = Wf2[c0 * 2], w01 = Wf2[c0 * 2 + 1];
            float w10 = Wf2[c0 * 2 + 2], w11 = Wf2[c0 * 2 + 3];
            float t0 = tanhf(a16[nt][0] + b0), t1 = tanhf(a16[nt][1] + b1);
            float t2 = tanhf(a16[nt][2] + b0), t3 = tanhf(a16[nt][3] + b1);
            l0a = fmaf(t0, w00, fmaf(t1, w10, l0a));
            l1a = fmaf(t0, w01, fmaf(t1, w11, l1a));
            l0b = fmaf(t2, w00, fmaf(t3, w10, l0b));
            l1b = fmaf(t2, w01, fmaf(t3, w11, l1b));
        }
#pragma unroll
        for (int off = 1; off <= 2; off <<= 1) {
            l0a += __shfl_xor_sync(0xffffffffu, l0a, off);
            l1a += __shfl_xor_sync(0xffffffffu, l1a, off);
            l0b += __shfl_xor_sync(0xffffffffu, l0b, off);
            l1b += __shfl_xor_sync(0xffffffffu, l1b, off);
        }
        if ((lane & 3) == 0) {
            float b20 = bf2[0], b21 = bf2[1];
            float la0 = l0a + b20, la1 = l1a + b21;
            float m = fmaxf(la0, la1);
            float e0 = expf(la0 - m), e1 = expf(la1 - m);
            float inv = 1.f / (e0 + e1);
            sS[(rowW + r) * 2]     = e0 * inv;
            sS[(rowW + r) * 2 + 1] = e1 * inv;
            float lb0 = l0b + b20, lb1 = l1b + b21;
            float m2 = fmaxf(lb0, lb1);
            float f0 = expf(lb0 - m2), f1 = expf(lb1 - m2);
            float inv2 = 1.f / (f0 + f1);
            sS[(rowW + r + 8) * 2]     = f0 * inv2;
            sS[(rowW + r + 8) * 2 + 1] = f1 * inv2;
        }
    }
    __syncthreads();

    // ---- phase 5: Laplacian penalty (both graphs) ----
    {
        float p0[4] = {0, 0, 0, 0}, p1[4] = {0, 0, 0, 0};
        // node term: t < 128 -> node t (graph t>>6)
        if (t < 128) {
            float s0 = sS[t * 2], s1 = sS[t * 2 + 1];
            float v0 = s0 * s0, v1 = s0 * s1, v2 = s1 * s0, v3 = s1 * s1;
            if (t < 64) { p0[0] = v0; p0[1] = v1; p0[2] = v2; p0[3] = v3; }
            else        { p1[0] = v0; p1[1] = v1; p1[2] = v2; p1[3] = v3; }
        }
        // edge terms: edge t of graph0 (j=0) and graph1 (j=1)
#pragma unroll
        for (int j = 0; j < 2; j++) {
            int ns = j * 64 + e_es[j], nd = j * 64 + e_ed[j];
            float lw = -sdv2[ns] * e_w[j] * sdv2[nd];
            float q0 = sS[ns * 2], q1 = sS[ns * 2 + 1];
            float r0 = sS[nd * 2], r1 = sS[nd * 2 + 1];
            float* p = j ? p1 : p0;
            p[0] = fmaf(lw, q0 * r0, p[0]);
            p[1] = fmaf(lw, q0 * r1, p[1]);
            p[2] = fmaf(lw, q1 * r0, p[2]);
            p[3] = fmaf(lw, q1 * r1, p[3]);
        }
#pragma unroll
        for (int off = 16; off; off >>= 1) {
#pragma unroll
            for (int j = 0; j < 4; j++) {
                p0[j] += __shfl_down_sync(0xffffffffu, p0[j], off);
                p1[j] += __shfl_down_sync(0xffffffffu, p1[j], off);
            }
        }
        if (lane == 0) {
#pragma unroll
            for (int j = 0; j < 4; j++) {
                atomicAdd(&sped[j], p0[j]);
                atomicAdd(&sped[4 + j], p1[j]);
            }
        }
    }
    __syncthreads();
    if (t == 0) {
        float pen = 0.f;
#pragma unroll
        for (int j = 0; j < 2; j++) {
            float A00 = sped[j * 4], A01 = sped[j * 4 + 1];
            float A10 = sped[j * 4 + 2], A11 = sped[j * 4 + 3];
            float r0 = fmaxf(fabsf(A00) + fabsf(A01), 1e-12f);
            float r1 = fmaxf(fabsf(A10) + fabsf(A11), 1e-12f);
            float dd0 = A00 / r0 - 1.f, dd1 = A11 / r1 - 1.f;
            pen += 0.5f * (dd0 * dd0 + dd1 * dd1);
        }
        atomicAdd(&d_sums[0], pen);
    }
}

// ---------------- mma.sync GEMM (graph-level): C = act(A @ W + b) --------------
__global__ void __launch_bounds__(256) k_mma(
    int selA, int K, int wtoff,
    const float* __restrict__ bias, int selC, int Cs, int act)
{
    __shared__ __nv_bfloat16 sAh[128][40];
    __shared__ __nv_bfloat16 sAl[128][40];
    __shared__ __nv_bfloat16 sBh[128][40];
    __shared__ __nv_bfloat16 sBl[128][40];
    __shared__ float sbias[128];

    int t = threadIdx.x;
    const float* A = (selA == 1) ? d_agg1 : (selA == 2) ? d_agg2 : d_zc;
    float* C = (selC == 1) ? d_h : (selC == 2) ? d_mu
             : (selC == 3) ? d_ls : (selC == 4) ? d_zl1 : d_zl2;
    int rowBase = blockIdx.y * 128, colBase = blockIdx.x * 128;
    if (t < 128) sbias[t] = bias[colBase + t];

    int lane = t & 31, warp = t >> 5;
    int warpM = warp >> 2, warpN = warp & 3;

    float acc[4][4][4];
#pragma unroll
    for (int mt = 0; mt < 4; mt++)
#pragma unroll
        for (int nt = 0; nt < 4; nt++)
#pragma unroll
            for (int j = 0; j < 4; j++) acc[mt][nt][j] = 0.f;

    int ldr = t >> 1, ldc = (t & 1) * 16;

    for (int kc = 0; kc < K; kc += 32) {
        const float* Ar = A + (size_t)(rowBase + ldr) * K + kc + ldc;
#pragma unroll
        for (int j = 0; j < 4; j++) {
            float4 v = *(const float4*)(Ar + j * 4);
            uint32_t h0, l0, h1, l1;
            cvt_split2(v.x, v.y, h0, l0);
            cvt_split2(v.z, v.w, h1, l1);
            *(uint32_t*)&sAh[ldr][ldc + j * 4]     = h0;
            *(uint32_t*)&sAh[ldr][ldc + j * 4 + 2] = h1;
            *(uint32_t*)&sAl[ldr][ldc + j * 4]     = l0;
            *(uint32_t*)&sAl[ldr][ldc + j * 4 + 2] = l1;
        }
        {
            const __nv_bfloat16* bh = d_wth + wtoff + (size_t)(colBase + ldr) * K + kc + ldc;
            const __nv_bfloat16* bl = d_wtl + wtoff + (size_t)(colBase + ldr) * K + kc + ldc;
            *(uint4*)&sBh[ldr][ldc]     = *(const uint4*)bh;
            *(uint4*)&sBh[ldr][ldc + 8] = *(const uint4*)(bh + 8);
            *(uint4*)&sBl[ldr][ldc]     = *(const uint4*)bl;
            *(uint4*)&sBl[ldr][ldc + 8] = *(const uint4*)(bl + 8);
        }
        __syncthreads();
#pragma unroll
        for (int ks = 0; ks < 32; ks += 16) {
            int kb = ks + (lane & 3) * 2;
            int ar = warpM * 64 + (lane >> 2);
            uint32_t ah[4][4], al[4][4];
#pragma unroll
            for (int mt = 0; mt < 4; mt++) {
                int r = ar + mt * 16;
                ah[mt][0] = *(const uint32_t*)&sAh[r][kb];
                ah[mt][1] = *(const uint32_t*)&sAh[r + 8][kb];
                ah[mt][2] = *(const uint32_t*)&sAh[r][kb + 8];
                ah[mt][3] = *(const uint32_t*)&sAh[r + 8][kb + 8];
                al[mt][0] = *(const uint32_t*)&sAl[r][kb];
                al[mt][1] = *(const uint32_t*)&sAl[r + 8][kb];
                al[mt][2] = *(const uint32_t*)&sAl[r][kb + 8];
                al[mt][3] = *(const uint32_t*)&sAl[r + 8][kb + 8];
            }
            uint32_t bhf[4][2], blf[4][2];
#pragma unroll
            for (int nt = 0; nt < 4; nt++) {
                int r = warpN * 32 + nt * 8 + (lane >> 2);
                bhf[nt][0] = *(const uint32_t*)&sBh[r][kb];
                bhf[nt][1] = *(const uint32_t*)&sBh[r][kb + 8];
                blf[nt][0] = *(const uint32_t*)&sBl[r][kb];
                blf[nt][1] = *(const uint32_t*)&sBl[r][kb + 8];
            }
#pragma unroll
            for (int mt = 0; mt < 4; mt++)
#pragma unroll
                for (int nt = 0; nt < 4; nt++) {
                    mma_bf16(acc[mt][nt], ah[mt], bhf[nt]);
                    mma_bf16(acc[mt][nt], ah[mt], blf[nt]);
                    mma_bf16(acc[mt][nt], al[mt], bhf[nt]);
                }
        }
        __syncthreads();
    }

#pragma unroll
    for (int mt = 0; mt < 4; mt++) {
        int r0 = rowBase + warpM * 64 + mt * 16 + (lane >> 2);
#pragma unroll
        for (int nt = 0; nt < 4; nt++) {
            int cl = warpN * 32 + nt * 8 + (lane & 3) * 2;
            float b0 = sbias[cl], b1 = sbias[cl + 1];
            float2 v0, v1;
            v0.x = acc[mt][nt][0] + b0; v0.y = acc[mt][nt][1] + b1;
            v1.x = acc[mt][nt][2] + b0; v1.y = acc[mt][nt][3] + b1;
            if (act == 1) {
                v0.x = fmaxf(v0.x, 0.f); v0.y = fmaxf(v0.y, 0.f);
                v1.x = fmaxf(v1.x, 0.f); v1.y = fmaxf(v1.y, 0.f);
            } else if (act == 2) {
                v0.x = fminf(v0.x, 10.f); v0.y = fminf(v0.y, 10.f);
                v1.x = fminf(v1.x, 10.f); v1.y = fminf(v1.y, 10.f);
            }
            *(float2*)&C[(size_t)r0 * Cs + colBase + cl] = v0;
            *(float2*)&C[(size_t)(r0 + 8) * Cs + colBase + cl] = v1;
        }
    }
}

// ---------------- graph-level degree ----------------
__global__ void k_deg(const int* __restrict__ pe) {
    int i = blockIdx.x * blockDim.x + threadIdx.x;
    if (i < EPN) atomicAdd(&d_deg[pe[EPN + i]], 1.0f);
}
__global__ void k_dinv() {
    int i = blockIdx.x * blockDim.x + threadIdx.x;
    if (i < G) d_deg[i] = rsqrtf(d_deg[i] + 1.0f);
}

// ---------------- scatter (warp/edge) with fused self-loop term ----------------
__global__ void __launch_bounds__(256) k_scatter(const int* __restrict__ pe, int sel) {
    int tid = blockIdx.x * 256 + threadIdx.x;   // 0 .. EPN*32-1
    int gw = tid >> 5, lane = tid & 31;
    int a = pe[gw], b = pe[EPN + gw];
    float norm = d_deg[a] * d_deg[b];
    if (sel == 0) {
        const float* X = d_gembs + (size_t)a * DD;
        float* Ag = d_agg1 + (size_t)b * DD;
#pragma unroll
        for (int d = lane; d < DD; d += 32) atomicAdd(&Ag[d], X[d] * norm);
        if (tid < G * DD) {
            float di = d_deg[tid >> 7];
            atomicAdd(&d_agg1[tid], d_gembs[tid] * di * di);
        }
    } else {
        const float* X = d_h + (size_t)a * 256;
        float* Ag = d_agg2 + (size_t)b * 256;
#pragma unroll
        for (int d = lane; d < 256; d += 32) atomicAdd(&Ag[d], X[d] * norm);
        float di = d_deg[tid >> 8];
        atomicAdd(&d_agg2[tid], d_h[tid] * di * di);
    }
}

// ---------------- z, zc, KL ----------------
__global__ void __launch_bounds__(256) k_z(const float* __restrict__ eps_,
                                           const float* __restrict__ emb) {
    int i = blockIdx.x * 256 + threadIdx.x;
    float m = d_mu[i], l = d_ls[i];
    int n = i >> 7, d = i & 127;
    float z = m + eps_[i] * expf(l);
    d_zc[(size_t)n * 256 + d] = emb[i];
    d_zc[(size_t)n * 256 + 128 + d] = z;
    float klt = 1.f + 2.f * l - m * m - expf(2.f * l);
    for (int off = 16; off; off >>= 1) klt += __shfl_down_sync(0xffffffffu, klt, off);
    __shared__ float sw[8];
    if ((threadIdx.x & 31) == 0) sw[threadIdx.x >> 5] = klt;
    __syncthreads();
    if (threadIdx.x == 0) {
        float s = 0;
        for (int j = 0; j < 8; j++) s += sw[j];
        atomicAdd(&d_sums[3], s);
    }
}

// ---------------- edge predictions + log sums ----------------
__global__ void __launch_bounds__(256) k_pred(const int* __restrict__ pe,
                                              const int* __restrict__ ne,
                                              float* __restrict__ out) {
    int gw = (blockIdx.x * 256 + threadIdx.x) >> 5;
    int lane = threadIdx.x & 31;
    int wib = threadIdx.x >> 5;
    bool isneg = gw >= EPN;
    int i = isneg ? gw - EPN : gw;
    const int* e = isneg ? ne : pe;
    int a = e[i], b = e[EPN + i];
    const float4* ra = (const float4*)(d_zl1 + (size_t)a * 256);
    const float4* rb = (const float4*)(d_zl2 + (size_t)b * 256);
    float s = 0.f;
#pragma unroll
    for (int q = 0; q < 2; q++) {
        float4 u = ra[lane + 32 * q], v = rb[lane + 32 * q];
        s += u.x * v.x + u.y * v.y + u.z * v.z + u.w * v.w;
    }
    for (int off = 16; off; off >>= 1) s += __shfl_down_sync(0xffffffffu, s, off);
    __shared__ float sl[8];
    if (lane == 0) {
        float p = 1.f / (1.f + expf(-s));
        out[2 + gw] = p;
        sl[wib] = isneg ? logf(1.f - p + 1e-15f) : logf(p + 1e-15f);
    }
    __syncthreads();
    if (threadIdx.x == 0) {
        float tt = 0;
        for (int j = 0; j < 8; j++) tt += sl[j];
        atomicAdd(isneg ? &d_sums[2] : &d_sums[1], tt);
    }
}

__global__ void k_final(float* __restrict__ out) {
    float rec = -(d_sums[1] / (float)EPN) - (d_sums[2] / (float)EPN);
    float kl = -0.5f * d_sums[3] / (float)G;
    out[0] = rec + kl / (float)G;
    out[1] = d_sums[0] / (float)G;
}

// ---------------- launch ----------------
extern "C" void kernel_launch(void* const* d_in, const int* in_sizes, int n_in,
                              void* d_out, int out_size) {
    const float* x   = (const float*)d_in[0];
    const int*   ei  = (const int*)d_in[1];
    const float* ew  = (const float*)d_in[2];
    const int*   pe  = (const int*)d_in[3];
    const int*   ne  = (const int*)d_in[4];
    const float* eps_= (const float*)d_in[5];
    const float* Wg  = (const float*)d_in[6];
    const float* bg  = (const float*)d_in[7];
    const float* Wf1 = (const float*)d_in[8];
    const float* bf1 = (const float*)d_in[9];
    const float* Wf2 = (const float*)d_in[10];
    const float* bf2 = (const float*)d_in[11];
    const float* Wc1 = (const float*)d_in[12];
    const float* bc1 = (const float*)d_in[13];
    const float* Wmu = (const float*)d_in[14];
    const float* bmu = (const float*)d_in[15];
    const float* Wls = (const float*)d_in[16];
    const float* bls = (const float*)d_in[17];
    const float* emb = (const float*)d_in[18];
    const float* Wl1 = (const float*)d_in[19];
    const float* bl1 = (const float*)d_in[20];
    const float* Wl2 = (const float*)d_in[21];
    const float* bl2 = (const float*)d_in[22];
    float* out = (float*)d_out;

    const int dyn_xw = 67584 + 2 * 128 * HST * 2;   // 137216
    cudaFuncSetAttribute(k_xwagg, cudaFuncAttributeMaxDynamicSharedMemorySize, dyn_xw);

    k_zero<<<1024, 256>>>();
    k_prepw<<<234, 1024>>>(Wg, Wc1, Wmu, Wls, Wl1, Wl2, Wf1);
    k_xwagg<<<G / 2, 256, dyn_xw>>>(x, ei, ew, bg, bf1, Wf2, bf2);
    k_deg<<<EPN / 256, 256>>>(pe);
    k_dinv<<<G / 256, 256>>>();
    k_scatter<<<EPN * 32 / 256, 256>>>(pe, 0);
    // h = relu(agg1 @ Wc1 + bc1)   [4096x128]@[128x256]
    k_mma<<<dim3(2, 32), 256>>>(1, 128, 8192, bc1, 1, 256, 1);
    k_scatter<<<EPN * 32 / 256, 256>>>(pe, 1);
    // mu / logstd    [4096x256]@[256x128]
    k_mma<<<dim3(1, 32), 256>>>(2, 256, 40960, bmu, 2, 128, 0);
    k_mma<<<dim3(1, 32), 256>>>(2, 256, 73728, bls, 3, 128, 2);
    k_z<<<G * DD / 256, 256>>>(eps_, emb);
    // zl1 / zl2      [4096x256]@[256x256]
    k_mma<<<dim3(2, 32), 256>>>(3, 256, 106496, bl1, 4, 256, 0);
    k_mma<<<dim3(2, 32), 256>>>(3, 256, 172032, bl2, 5, 256, 0);
    k_pred<<<2 * EPN * 32 / 256, 256>>>(pe, ne, out);
    k_final<<<1, 1>>>(out);
}

// round 7
// speedup vs baseline: 1.3727x; 1.3727x over previous
#include <cuda_runtime.h>
#include <cuda_bf16.h>
#include <math.h>
#include <stdint.h>

#define G   4096
#define NN  64
#define EE  256
#define FF  64
#define DD  128
#define EPN 32768

// ---------------- device scratch (static, no allocations) ----------------
__device__ float d_gembs[G * DD];
__device__ float d_deg[G];
__device__ float d_agg1[G * DD];
__device__ float d_h[G * 256];
__device__ float d_agg2[G * 256];
__device__ float d_mu[G * DD];
__device__ float d_ls[G * DD];
__device__ float d_zc[G * 256];
__device__ float d_zl1[G * 256];
__device__ float d_zl2[G * 256];
__device__ float d_sums[8];   // 0:pen 1:plog 2:nlog 3:kl
// transposed bf16 hi/lo weights [N][K]: Wg[0,8192) Wc1[8192,40960) Wmu[40960,73728)
// Wls[73728,106496) Wl1[106496,172032) Wl2[172032,237568) Wf1[237568,239616)
__device__ __nv_bfloat16 d_wth[239616];
__device__ __nv_bfloat16 d_wtl[239616];

// ---------------- helpers ----------------
__device__ __forceinline__ void mma_bf16(float* c, const uint32_t* a, const uint32_t* b) {
    asm volatile("mma.sync.aligned.m16n8k16.row.col.f32.bf16.bf16.f32 "
        "{%0,%1,%2,%3}, {%4,%5,%6,%7}, {%8,%9}, {%0,%1,%2,%3};"
        : "+f"(c[0]), "+f"(c[1]), "+f"(c[2]), "+f"(c[3])
        : "r"(a[0]), "r"(a[1]), "r"(a[2]), "r"(a[3]), "r"(b[0]), "r"(b[1]));
}
__device__ __forceinline__ void cvt_split2(float x, float y, uint32_t& hi, uint32_t& lo) {
    __nv_bfloat162 h = __floats2bfloat162_rn(x, y);
    float rx = x - __bfloat162float(h.x);
    float ry = y - __bfloat162float(h.y);
    __nv_bfloat162 l = __floats2bfloat162_rn(rx, ry);
    hi = *(uint32_t*)&h;
    lo = *(uint32_t*)&l;
}

// ---------------- zero scratch accumulators ----------------
__global__ void k_zero() {
    int i = blockIdx.x * blockDim.x + threadIdx.x;
    int stride = gridDim.x * blockDim.x;
    for (int j = i; j < G * 256; j += stride) d_agg2[j] = 0.f;
    for (int j = i; j < G * DD; j += stride) d_agg1[j] = 0.f;
    for (int j = i; j < G; j += stride) d_deg[j] = 0.f;
    if (i < 8) d_sums[i] = 0.f;
}

// ---------------- weight transpose + bf16 hi/lo split ----------------
__global__ void k_prepw(const float* __restrict__ W0, const float* __restrict__ W1,
                        const float* __restrict__ W2, const float* __restrict__ W3,
                        const float* __restrict__ W4, const float* __restrict__ W5,
                        const float* __restrict__ W6) {
    const float* Ws[7] = {W0, W1, W2, W3, W4, W5, W6};
    const int Ks[7] = {64, 128, 256, 256, 256, 256, 128};
    const int Ns[7] = {128, 256, 128, 128, 256, 256, 16};
    const int offs[8] = {0, 8192, 40960, 73728, 106496, 172032, 237568, 239616};
    int i = blockIdx.x * blockDim.x + threadIdx.x;
    if (i >= 239616) return;
    int s = 0;
    while (i >= offs[s + 1]) s++;
    int local = i - offs[s];
    int K = Ks[s], N = Ns[s];
    int n = local / K, k = local - n * K;
    float v = Ws[s][k * N + n];
    __nv_bfloat16 h = __float2bfloat16(v);
    d_wth[i] = h;
    d_wtl[i] = __float2bfloat16(v - __bfloat162float(h));
}

// ---------------- fully fused per-graph kernel (1 graph / block) ----------------
// xw = x@Wg (HMMA split, M=64) -> CSR aggregate -> h (smem bf16 hi/lo) -> g_emb
// -> a1 = tanh(h@Wf1+b) (HMMA split, 4 warps) -> S softmax -> Laplacian penalty.
// dyn smem 68608 B -> 3 CTAs/SM.
#define XST 132   // sxw row stride (floats)
#define HST 136   // h row stride (bf16)
__global__ void __launch_bounds__(256, 3) k_xwagg(
    const float* __restrict__ x, const int* __restrict__ ei, const float* __restrict__ ew,
    const float* __restrict__ bg, const float* __restrict__ bf1,
    const float* __restrict__ Wf2, const float* __restrict__ bf2)
{
    extern __shared__ char dyn[];
    // region0 [0,33792): staging sAh[64*40]|sAl[64*40]|sBh[128*40]|sBl[128*40] bf16;
    //                    then (aliased) sxw [64][XST] f32
    __nv_bfloat16* sAh = (__nv_bfloat16*)dyn;
    __nv_bfloat16* sAl = sAh + 64 * 40;
    __nv_bfloat16* sBh = sAl + 64 * 40;
    __nv_bfloat16* sBl = sBh + 128 * 40;
    float* sxw = (float*)dyn;
    // region1 [33792, +34816): h as bf16 hi/lo [64][HST]
    __nv_bfloat16* shh = (__nv_bfloat16*)(dyn + 33792);
    __nv_bfloat16* shl = shh + 64 * HST;

    __shared__ int   esrc[EE];
    __shared__ float enorm[EE];
    __shared__ float sdeg[NN], sdinv[NN], sdeg2[NN], sdv2[NN];
    __shared__ int   scnt[NN], sstart[NN + 1], spos[NN];
    __shared__ float sS[NN * 2];
    __shared__ float sgpart[DD];
    __shared__ float sped[4];

    int t = threadIdx.x, lane = t & 31, warp = t >> 5;
    int warpM = warp >> 2, warpN = warp & 3;   // 2 x 4
    int g = blockIdx.x;
    const float* A = x + (size_t)g * NN * FF;

    // ---- phase 1: edges, degrees, CSR ----
    int e_es = ei[(size_t)g * 512 + t];
    int e_ed = ei[(size_t)g * 512 + 256 + t];
    float e_w = ew[(size_t)g * 256 + t];
    if (t < NN) { sdeg[t] = 0.f; sdeg2[t] = 0.f; scnt[t] = 0; }
    if (t < 4) sped[t] = 0.f;
    __syncthreads();
    atomicAdd(&sdeg[e_ed], e_w);
    atomicAdd(&sdeg2[e_es], e_w);
    atomicAdd(&scnt[e_ed], 1);
    __syncthreads();
    if (t < NN) {
        sdinv[t] = rsqrtf(sdeg[t] + 1.0f);
        float d2 = sdeg2[t];
        sdv2[t] = (d2 > 0.f) ? rsqrtf(fmaxf(d2, 1e-30f)) : 0.f;
    }
    if (t == 0) {
        int s = 0;
        for (int n = 0; n < NN; n++) { sstart[n] = s; s += scnt[n]; }
        sstart[NN] = s;
    }
    __syncthreads();
    if (t < NN) spos[t] = sstart[t];
    __syncthreads();
    {
        int p = atomicAdd(&spos[e_ed], 1);
        esrc[p]  = e_es;
        enorm[p] = sdinv[e_es] * e_w * sdinv[e_ed];
    }
    // (first mma __syncthreads orders the fill)

    // ---- phase 2: HMMA xw = x @ Wg (64x128x64, split bf16) ----
    float acc[2][4][4];
#pragma unroll
    for (int mt = 0; mt < 2; mt++)
#pragma unroll
        for (int nt = 0; nt < 4; nt++)
#pragma unroll
            for (int j = 0; j < 4; j++) acc[mt][nt][j] = 0.f;

    int lar = t >> 2, lac = (t & 3) * 8;     // A: 64 rows x 32 cols, 8/thread
    int lbr = t >> 1, lbc = (t & 1) * 16;    // B: 128 rows x 32 cols, 16/thread
    for (int kc = 0; kc < 64; kc += 32) {
        {
            const float* Ar = A + (size_t)lar * 64 + kc + lac;
            float4 v0 = *(const float4*)Ar;
            float4 v1 = *(const float4*)(Ar + 4);
            uint32_t h0, l0, h1, l1, h2, l2, h3, l3;
            cvt_split2(v0.x, v0.y, h0, l0);
            cvt_split2(v0.z, v0.w, h1, l1);
            cvt_split2(v1.x, v1.y, h2, l2);
            cvt_split2(v1.z, v1.w, h3, l3);
            *(uint32_t*)&sAh[lar * 40 + lac]     = h0;
            *(uint32_t*)&sAh[lar * 40 + lac + 2] = h1;
            *(uint32_t*)&sAh[lar * 40 + lac + 4] = h2;
            *(uint32_t*)&sAh[lar * 40 + lac + 6] = h3;
            *(uint32_t*)&sAl[lar * 40 + lac]     = l0;
            *(uint32_t*)&sAl[lar * 40 + lac + 2] = l1;
            *(uint32_t*)&sAl[lar * 40 + lac + 4] = l2;
            *(uint32_t*)&sAl[lar * 40 + lac + 6] = l3;
        }
        {
            const __nv_bfloat16* bh = d_wth + (size_t)lbr * 64 + kc + lbc;
            const __nv_bfloat16* bl = d_wtl + (size_t)lbr * 64 + kc + lbc;
            *(uint4*)&sBh[lbr * 40 + lbc]     = *(const uint4*)bh;
            *(uint4*)&sBh[lbr * 40 + lbc + 8] = *(const uint4*)(bh + 8);
            *(uint4*)&sBl[lbr * 40 + lbc]     = *(const uint4*)bl;
            *(uint4*)&sBl[lbr * 40 + lbc + 8] = *(const uint4*)(bl + 8);
        }
        __syncthreads();
#pragma unroll
        for (int ks = 0; ks < 32; ks += 16) {
            int kb = ks + (lane & 3) * 2;
            uint32_t ah[2][4], al[2][4];
#pragma unroll
            for (int mt = 0; mt < 2; mt++) {
                int r = warpM * 32 + mt * 16 + (lane >> 2);
                ah[mt][0] = *(const uint32_t*)&sAh[r * 40 + kb];
                ah[mt][1] = *(const uint32_t*)&sAh[(r + 8) * 40 + kb];
                ah[mt][2] = *(const uint32_t*)&sAh[r * 40 + kb + 8];
                ah[mt][3] = *(const uint32_t*)&sAh[(r + 8) * 40 + kb + 8];
                al[mt][0] = *(const uint32_t*)&sAl[r * 40 + kb];
                al[mt][1] = *(const uint32_t*)&sAl[(r + 8) * 40 + kb];
                al[mt][2] = *(const uint32_t*)&sAl[r * 40 + kb + 8];
                al[mt][3] = *(const uint32_t*)&sAl[(r + 8) * 40 + kb + 8];
            }
            uint32_t bhf[4][2], blf[4][2];
#pragma unroll
            for (int nt = 0; nt < 4; nt++) {
                int r = warpN * 32 + nt * 8 + (lane >> 2);
                bhf[nt][0] = *(const uint32_t*)&sBh[r * 40 + kb];
                bhf[nt][1] = *(const uint32_t*)&sBh[r * 40 + kb + 8];
                blf[nt][0] = *(const uint32_t*)&sBl[r * 40 + kb];
                blf[nt][1] = *(const uint32_t*)&sBl[r * 40 + kb + 8];
            }
#pragma unroll
            for (int mt = 0; mt < 2; mt++)
#pragma unroll
                for (int nt = 0; nt < 4; nt++) {
                    mma_bf16(acc[mt][nt], ah[mt], bhf[nt]);
                    mma_bf16(acc[mt][nt], ah[mt], blf[nt]);
                    mma_bf16(acc[mt][nt], al[mt], bhf[nt]);
                }
        }
        __syncthreads();
    }

    // ---- park xw in smem (aliases staging) ----
#pragma unroll
    for (int mt = 0; mt < 2; mt++) {
        int r0 = warpM * 32 + mt * 16 + (lane >> 2);
#pragma unroll
        for (int nt = 0; nt < 4; nt++) {
            int cl = warpN * 32 + nt * 8 + (lane & 3) * 2;
            float2 v0, v1;
            v0.x = acc[mt][nt][0]; v0.y = acc[mt][nt][1];
            v1.x = acc[mt][nt][2]; v1.y = acc[mt][nt][3];
            *(float2*)&sxw[r0 * XST + cl] = v0;
            *(float2*)&sxw[(r0 + 8) * XST + cl] = v1;
        }
    }
    __syncthreads();

    // ---- phase 3: CSR aggregation -> h (bf16 split, smem) + g_emb ----
    {
        int half = t >> 7, c = t & 127;
        float bias = bg[c];
        float gsum = 0.f;
#pragma unroll 4
        for (int n0 = 0; n0 < 32; n0++) {
            int n = half * 32 + n0;
            float a2 = 0.f;
            int e0 = sstart[n], e1 = sstart[n + 1];
            for (int e = e0; e < e1; e++)
                a2 = fmaf(sxw[esrc[e] * XST + c], enorm[e], a2);
            float di = sdinv[n];
            float hv = a2 + sxw[n * XST + c] * di * di + bias;
            gsum += hv;
            __nv_bfloat16 hb = __float2bfloat16(hv);
            shh[n * HST + c] = hb;
            shl[n * HST + c] = __float2bfloat16(hv - __bfloat162float(hb));
        }
        if (half == 1) sgpart[c] = gsum;
        __syncthreads();
        if (half == 0)
            d_gembs[(size_t)g * 128 + c] = 0.5f * (gsum + sgpart[c]);
    }
    __syncthreads();

    // ---- phase 4: a1 = tanh(h @ Wf1 + bf1), logits, softmax -> sS (warps 0-3) ----
    if (warp < 4) {
        int r = lane >> 2, kb2 = (lane & 3) * 2;
        int rowW = warp * 16;
        float a16[2][4];
#pragma unroll
        for (int nt = 0; nt < 2; nt++)
#pragma unroll
            for (int j = 0; j < 4; j++) a16[nt][j] = 0.f;
        const __nv_bfloat16* Bh = d_wth + 237568;
        const __nv_bfloat16* Bl = d_wtl + 237568;
#pragma unroll
        for (int ks = 0; ks < 8; ks++) {
            int k0 = ks * 16 + kb2;
            uint32_t ah[4], al[4];
            ah[0] = *(const uint32_t*)&shh[(rowW + r) * HST + k0];
            ah[1] = *(const uint32_t*)&shh[(rowW + r + 8) * HST + k0];
            ah[2] = *(const uint32_t*)&shh[(rowW + r) * HST + k0 + 8];
            ah[3] = *(const uint32_t*)&shh[(rowW + r + 8) * HST + k0 + 8];
            al[0] = *(const uint32_t*)&shl[(rowW + r) * HST + k0];
            al[1] = *(const uint32_t*)&shl[(rowW + r + 8) * HST + k0];
            al[2] = *(const uint32_t*)&shl[(rowW + r) * HST + k0 + 8];
            al[3] = *(const uint32_t*)&shl[(rowW + r + 8) * HST + k0 + 8];
#pragma unroll
            for (int nt = 0; nt < 2; nt++) {
                int n = nt * 8 + r;
                uint32_t bh[2], bl[2];
                bh[0] = *(const uint32_t*)(Bh + n * 128 + k0);
                bh[1] = *(const uint32_t*)(Bh + n * 128 + k0 + 8);
                bl[0] = *(const uint32_t*)(Bl + n * 128 + k0);
                bl[1] = *(const uint32_t*)(Bl + n * 128 + k0 + 8);
                mma_bf16(a16[nt], ah, bh);
                mma_bf16(a16[nt], ah, bl);
                mma_bf16(a16[nt], al, bh);
            }
        }
        float l0a = 0.f, l1a = 0.f, l0b = 0.f, l1b = 0.f;
#pragma unroll
        for (int nt = 0; nt < 2; nt++) {
            int c0 = nt * 8 + (lane & 3) * 2;
            float b0 = bf1[c0], b1 = bf1[c0 + 1];
            float w00 = Wf2[c0 * 2], w01 = Wf2[c0 * 2 + 1];
            float w10 = Wf2[c0 * 2 + 2], w11 = Wf2[c0 * 2 + 3];
            float t0 = tanhf(a16[nt][0] + b0), t1 = tanhf(a16[nt][1] + b1);
            float t2 = tanhf(a16[nt][2] + b0), t3 = tanhf(a16[nt][3] + b1);
            l0a = fmaf(t0, w00, fmaf(t1, w10, l0a));
            l1a = fmaf(t0, w01, fmaf(t1, w11, l1a));
            l0b = fmaf(t2, w00, fmaf(t3, w10, l0b));
            l1b = fmaf(t2, w01, fmaf(t3, w11, l1b));
        }
#pragma unroll
        for (int off = 1; off <= 2; off <<= 1) {
            l0a += __shfl_xor_sync(0xffffffffu, l0a, off);
            l1a += __shfl_xor_sync(0xffffffffu, l1a, off);
            l0b += __shfl_xor_sync(0xffffffffu, l0b, off);
            l1b += __shfl_xor_sync(0xffffffffu, l1b, off);
        }
        if ((lane & 3) == 0) {
            float b20 = bf2[0], b21 = bf2[1];
            float la0 = l0a + b20, la1 = l1a + b21;
            float m = fmaxf(la0, la1);
            float e0 = expf(la0 - m), e1 = expf(la1 - m);
            float inv = 1.f / (e0 + e1);
            sS[(rowW + r) * 2]     = e0 * inv;
            sS[(rowW + r) * 2 + 1] = e1 * inv;
            float lb0 = l0b + b20, lb1 = l1b + b21;
            float m2 = fmaxf(lb0, lb1);
            float f0 = expf(lb0 - m2), f1 = expf(lb1 - m2);
            float inv2 = 1.f / (f0 + f1);
            sS[(rowW + r + 8) * 2]     = f0 * inv2;
            sS[(rowW + r + 8) * 2 + 1] = f1 * inv2;
        }
    }
    __syncthreads();

    // ---- phase 5: Laplacian penalty ----
    {
        float p[4] = {0, 0, 0, 0};
        if (t < NN) {
            float s0 = sS[t * 2], s1 = sS[t * 2 + 1];
            p[0] = s0 * s0; p[1] = s0 * s1; p[2] = s1 * s0; p[3] = s1 * s1;
        }
        {
            float lw = -sdv2[e_es] * e_w * sdv2[e_ed];
            float q0 = sS[e_es * 2], q1 = sS[e_es * 2 + 1];
            float r0 = sS[e_ed * 2], r1 = sS[e_ed * 2 + 1];
            p[0] = fmaf(lw, q0 * r0, p[0]);
            p[1] = fmaf(lw, q0 * r1, p[1]);
            p[2] = fmaf(lw, q1 * r0, p[2]);
            p[3] = fmaf(lw, q1 * r1, p[3]);
        }
#pragma unroll
        for (int off = 16; off; off >>= 1)
#pragma unroll
            for (int j = 0; j < 4; j++)
                p[j] += __shfl_down_sync(0xffffffffu, p[j], off);
        if (lane == 0) {
#pragma unroll
            for (int j = 0; j < 4; j++) atomicAdd(&sped[j], p[j]);
        }
    }
    __syncthreads();
    if (t == 0) {
        float A00 = sped[0], A01 = sped[1], A10 = sped[2], A11 = sped[3];
        float r0 = fmaxf(fabsf(A00) + fabsf(A01), 1e-12f);
        float r1 = fmaxf(fabsf(A10) + fabsf(A11), 1e-12f);
        float dd0 = A00 / r0 - 1.f, dd1 = A11 / r1 - 1.f;
        atomicAdd(&d_sums[0], 0.5f * (dd0 * dd0 + dd1 * dd1));
    }
}

// ---------------- mma.sync GEMM (graph-level): C = act(A @ W + b) --------------
__global__ void __launch_bounds__(256) k_mma(
    int selA, int K, int wtoff,
    const float* __restrict__ bias, int selC, int Cs, int act)
{
    __shared__ __nv_bfloat16 sAh[128][40];
    __shared__ __nv_bfloat16 sAl[128][40];
    __shared__ __nv_bfloat16 sBh[128][40];
    __shared__ __nv_bfloat16 sBl[128][40];
    __shared__ float sbias[128];

    int t = threadIdx.x;
    const float* A = (selA == 1) ? d_agg1 : (selA == 2) ? d_agg2 : d_zc;
    float* C = (selC == 1) ? d_h : (selC == 2) ? d_mu
             : (selC == 3) ? d_ls : (selC == 4) ? d_zl1 : d_zl2;
    int rowBase = blockIdx.y * 128, colBase = blockIdx.x * 128;
    if (t < 128) sbias[t] = bias[colBase + t];

    int lane = t & 31, warp = t >> 5;
    int warpM = warp >> 2, warpN = warp & 3;

    float acc[4][4][4];
#pragma unroll
    for (int mt = 0; mt < 4; mt++)
#pragma unroll
        for (int nt = 0; nt < 4; nt++)
#pragma unroll
            for (int j = 0; j < 4; j++) acc[mt][nt][j] = 0.f;

    int ldr = t >> 1, ldc = (t & 1) * 16;

    for (int kc = 0; kc < K; kc += 32) {
        const float* Ar = A + (size_t)(rowBase + ldr) * K + kc + ldc;
#pragma unroll
        for (int j = 0; j < 4; j++) {
            float4 v = *(const float4*)(Ar + j * 4);
            uint32_t h0, l0, h1, l1;
            cvt_split2(v.x, v.y, h0, l0);
            cvt_split2(v.z, v.w, h1, l1);
            *(uint32_t*)&sAh[ldr][ldc + j * 4]     = h0;
            *(uint32_t*)&sAh[ldr][ldc + j * 4 + 2] = h1;
            *(uint32_t*)&sAl[ldr][ldc + j * 4]     = l0;
            *(uint32_t*)&sAl[ldr][ldc + j * 4 + 2] = l1;
        }
        {
            const __nv_bfloat16* bh = d_wth + wtoff + (size_t)(colBase + ldr) * K + kc + ldc;
            const __nv_bfloat16* bl = d_wtl + wtoff + (size_t)(colBase + ldr) * K + kc + ldc;
            *(uint4*)&sBh[ldr][ldc]     = *(const uint4*)bh;
            *(uint4*)&sBh[ldr][ldc + 8] = *(const uint4*)(bh + 8);
            *(uint4*)&sBl[ldr][ldc]     = *(const uint4*)bl;
            *(uint4*)&sBl[ldr][ldc + 8] = *(const uint4*)(bl + 8);
        }
        __syncthreads();
#pragma unroll
        for (int ks = 0; ks < 32; ks += 16) {
            int kb = ks + (lane & 3) * 2;
            int ar = warpM * 64 + (lane >> 2);
            uint32_t ah[4][4], al[4][4];
#pragma unroll
            for (int mt = 0; mt < 4; mt++) {
                int r = ar + mt * 16;
                ah[mt][0] = *(const uint32_t*)&sAh[r][kb];
                ah[mt][1] = *(const uint32_t*)&sAh[r + 8][kb];
                ah[mt][2] = *(const uint32_t*)&sAh[r][kb + 8];
                ah[mt][3] = *(const uint32_t*)&sAh[r + 8][kb + 8];
                al[mt][0] = *(const uint32_t*)&sAl[r][kb];
                al[mt][1] = *(const uint32_t*)&sAl[r + 8][kb];
                al[mt][2] = *(const uint32_t*)&sAl[r][kb + 8];
                al[mt][3] = *(const uint32_t*)&sAl[r + 8][kb + 8];
            }
            uint32_t bhf[4][2], blf[4][2];
#pragma unroll
            for (int nt = 0; nt < 4; nt++) {
                int r = warpN * 32 + nt * 8 + (lane >> 2);
                bhf[nt][0] = *(const uint32_t*)&sBh[r][kb];
                bhf[nt][1] = *(const uint32_t*)&sBh[r][kb + 8];
                blf[nt][0] = *(const uint32_t*)&sBl[r][kb];
                blf[nt][1] = *(const uint32_t*)&sBl[r][kb + 8];
            }
#pragma unroll
            for (int mt = 0; mt < 4; mt++)
#pragma unroll
                for (int nt = 0; nt < 4; nt++) {
                    mma_bf16(acc[mt][nt], ah[mt], bhf[nt]);
                    mma_bf16(acc[mt][nt], ah[mt], blf[nt]);
                    mma_bf16(acc[mt][nt], al[mt], bhf[nt]);
                }
        }
        __syncthreads();
    }

#pragma unroll
    for (int mt = 0; mt < 4; mt++) {
        int r0 = rowBase + warpM * 64 + mt * 16 + (lane >> 2);
#pragma unroll
        for (int nt = 0; nt < 4; nt++) {
            int cl = warpN * 32 + nt * 8 + (lane & 3) * 2;
            float b0 = sbias[cl], b1 = sbias[cl + 1];
            float2 v0, v1;
            v0.x = acc[mt][nt][0] + b0; v0.y = acc[mt][nt][1] + b1;
            v1.x = acc[mt][nt][2] + b0; v1.y = acc[mt][nt][3] + b1;
            if (act == 1) {
                v0.x = fmaxf(v0.x, 0.f); v0.y = fmaxf(v0.y, 0.f);
                v1.x = fmaxf(v1.x, 0.f); v1.y = fmaxf(v1.y, 0.f);
            } else if (act == 2) {
                v0.x = fminf(v0.x, 10.f); v0.y = fminf(v0.y, 10.f);
                v1.x = fminf(v1.x, 10.f); v1.y = fminf(v1.y, 10.f);
            }
            *(float2*)&C[(size_t)r0 * Cs + colBase + cl] = v0;
            *(float2*)&C[(size_t)(r0 + 8) * Cs + colBase + cl] = v1;
        }
    }
}

// ---------------- graph-level degree ----------------
__global__ void k_deg(const int* __restrict__ pe) {
    int i = blockIdx.x * blockDim.x + threadIdx.x;
    if (i < EPN) atomicAdd(&d_deg[pe[EPN + i]], 1.0f);
}
__global__ void k_dinv() {
    int i = blockIdx.x * blockDim.x + threadIdx.x;
    if (i < G) d_deg[i] = rsqrtf(d_deg[i] + 1.0f);
}

// ---------------- scatter (warp/edge) with fused self-loop term ----------------
__global__ void __launch_bounds__(256) k_scatter(const int* __restrict__ pe, int sel) {
    int tid = blockIdx.x * 256 + threadIdx.x;   // 0 .. EPN*32-1
    int gw = tid >> 5, lane = tid & 31;
    int a = pe[gw], b = pe[EPN + gw];
    float norm = d_deg[a] * d_deg[b];
    if (sel == 0) {
        const float* X = d_gembs + (size_t)a * DD;
        float* Ag = d_agg1 + (size_t)b * DD;
#pragma unroll
        for (int d = lane; d < DD; d += 32) atomicAdd(&Ag[d], X[d] * norm);
        if (tid < G * DD) {
            float di = d_deg[tid >> 7];
            atomicAdd(&d_agg1[tid], d_gembs[tid] * di * di);
        }
    } else {
        const float* X = d_h + (size_t)a * 256;
        float* Ag = d_agg2 + (size_t)b * 256;
#pragma unroll
        for (int d = lane; d < 256; d += 32) atomicAdd(&Ag[d], X[d] * norm);
        float di = d_deg[tid >> 8];
        atomicAdd(&d_agg2[tid], d_h[tid] * di * di);
    }
}

// ---------------- z, zc, KL ----------------
__global__ void __launch_bounds__(256) k_z(const float* __restrict__ eps_,
                                           const float* __restrict__ emb) {
    int i = blockIdx.x * 256 + threadIdx.x;
    float m = d_mu[i], l = d_ls[i];
    int n = i >> 7, d = i & 127;
    float z = m + eps_[i] * expf(l);
    d_zc[(size_t)n * 256 + d] = emb[i];
    d_zc[(size_t)n * 256 + 128 + d] = z;
    float klt = 1.f + 2.f * l - m * m - expf(2.f * l);
    for (int off = 16; off; off >>= 1) klt += __shfl_down_sync(0xffffffffu, klt, off);
    __shared__ float sw[8];
    if ((threadIdx.x & 31) == 0) sw[threadIdx.x >> 5] = klt;
    __syncthreads();
    if (threadIdx.x == 0) {
        float s = 0;
        for (int j = 0; j < 8; j++) s += sw[j];
        atomicAdd(&d_sums[3], s);
    }
}

// ---------------- edge predictions + log sums ----------------
__global__ void __launch_bounds__(256) k_pred(const int* __restrict__ pe,
                                              const int* __restrict__ ne,
                                              float* __restrict__ out) {
    int gw = (blockIdx.x * 256 + threadIdx.x) >> 5;
    int lane = threadIdx.x & 31;
    int wib = threadIdx.x >> 5;
    bool isneg = gw >= EPN;
    int i = isneg ? gw - EPN : gw;
    const int* e = isneg ? ne : pe;
    int a = e[i], b = e[EPN + i];
    const float4* ra = (const float4*)(d_zl1 + (size_t)a * 256);
    const float4* rb = (const float4*)(d_zl2 + (size_t)b * 256);
    float s = 0.f;
#pragma unroll
    for (int q = 0; q < 2; q++) {
        float4 u = ra[lane + 32 * q], v = rb[lane + 32 * q];
        s += u.x * v.x + u.y * v.y + u.z * v.z + u.w * v.w;
    }
    for (int off = 16; off; off >>= 1) s += __shfl_down_sync(0xffffffffu, s, off);
    __shared__ float sl[8];
    if (lane == 0) {
        float p = 1.f / (1.f + expf(-s));
        out[2 + gw] = p;
        sl[wib] = isneg ? logf(1.f - p + 1e-15f) : logf(p + 1e-15f);
    }
    __syncthreads();
    if (threadIdx.x == 0) {
        float tt = 0;
        for (int j = 0; j < 8; j++) tt += sl[j];
        atomicAdd(isneg ? &d_sums[2] : &d_sums[1], tt);
    }
}

__global__ void k_final(float* __restrict__ out) {
    float rec = -(d_sums[1] / (float)EPN) - (d_sums[2] / (float)EPN);
    float kl = -0.5f * d_sums[3] / (float)G;
    out[0] = rec + kl / (float)G;
    out[1] = d_sums[0] / (float)G;
}

// ---------------- launch ----------------
extern "C" void kernel_launch(void* const* d_in, const int* in_sizes, int n_in,
                              void* d_out, int out_size) {
    const float* x   = (const float*)d_in[0];
    const int*   ei  = (const int*)d_in[1];
    const float* ew  = (const float*)d_in[2];
    const int*   pe  = (const int*)d_in[3];
    const int*   ne  = (const int*)d_in[4];
    const float* eps_= (const float*)d_in[5];
    const float* Wg  = (const float*)d_in[6];
    const float* bg  = (const float*)d_in[7];
    const float* Wf1 = (const float*)d_in[8];
    const float* bf1 = (const float*)d_in[9];
    const float* Wf2 = (const float*)d_in[10];
    const float* bf2 = (const float*)d_in[11];
    const float* Wc1 = (const float*)d_in[12];
    const float* bc1 = (const float*)d_in[13];
    const float* Wmu = (const float*)d_in[14];
    const float* bmu = (const float*)d_in[15];
    const float* Wls = (const float*)d_in[16];
    const float* bls = (const float*)d_in[17];
    const float* emb = (const float*)d_in[18];
    const float* Wl1 = (const float*)d_in[19];
    const float* bl1 = (const float*)d_in[20];
    const float* Wl2 = (const float*)d_in[21];
    const float* bl2 = (const float*)d_in[22];
    float* out = (float*)d_out;

    const int dyn_xw = 33792 + 2 * 64 * HST * 2;   // 68608 -> 3 CTAs/SM
    cudaFuncSetAttribute(k_xwagg, cudaFuncAttributeMaxDynamicSharedMemorySize, dyn_xw);

    k_zero<<<1024, 256>>>();
    k_prepw<<<234, 1024>>>(Wg, Wc1, Wmu, Wls, Wl1, Wl2, Wf1);
    k_xwagg<<<G, 256, dyn_xw>>>(x, ei, ew, bg, bf1, Wf2, bf2);
    k_deg<<<EPN / 256, 256>>>(pe);
    k_dinv<<<G / 256, 256>>>();
    k_scatter<<<EPN * 32 / 256, 256>>>(pe, 0);
    // h = relu(agg1 @ Wc1 + bc1)   [4096x128]@[128x256]
    k_mma<<<dim3(2, 32), 256>>>(1, 128, 8192, bc1, 1, 256, 1);
    k_scatter<<<EPN * 32 / 256, 256>>>(pe, 1);
    // mu / logstd    [4096x256]@[256x128]
    k_mma<<<dim3(1, 32), 256>>>(2, 256, 40960, bmu, 2, 128, 0);
    k_mma<<<dim3(1, 32), 256>>>(2, 256, 73728, bls, 3, 128, 2);
    k_z<<<G * DD / 256, 256>>>(eps_, emb);
    // zl1 / zl2      [4096x256]@[256x256]
    k_mma<<<dim3(2, 32), 256>>>(3, 256, 106496, bl1, 4, 256, 0);
    k_mma<<<dim3(2, 32), 256>>>(3, 256, 172032, bl2, 5, 256, 0);
    k_pred<<<2 * EPN * 32 / 256, 256>>>(pe, ne, out);
    k_final<<<1, 1>>>(out);
}

// round 9
// speedup vs baseline: 1.5177x; 1.1056x over previous
#include <cuda_runtime.h>
#include <cuda_bf16.h>
#include <math.h>
#include <stdint.h>

#define G   4096
#define NN  64
#define EE  256
#define FF  64
#define DD  128
#define EPN 32768

// ---------------- device scratch (static, no allocations) ----------------
__device__ float d_gembs[G * DD];
__device__ float d_deg[G];
__device__ float d_agg1[G * DD];
__device__ float d_h[G * 256];
__device__ float d_agg2[G * 256];
__device__ float d_mu[G * DD];
__device__ float d_ls[G * DD];
__device__ float d_zc[G * 256];
__device__ float d_zl1[G * 256];
__device__ float d_zl2[G * 256];
__device__ float d_sums[8];   // 0:pen 1:plog 2:nlog 3:kl
// transposed bf16 hi/lo weights [N][K]: Wg[0,8192) Wc1[8192,40960) Wmu[40960,73728)
// Wls[73728,106496) Wl1[106496,172032) Wl2[172032,237568) Wf1[237568,239616)
__device__ __nv_bfloat16 d_wth[239616];
__device__ __nv_bfloat16 d_wtl[239616];

// ---------------- helpers ----------------
__device__ __forceinline__ void mma_bf16(float* c, const uint32_t* a, const uint32_t* b) {
    asm volatile("mma.sync.aligned.m16n8k16.row.col.f32.bf16.bf16.f32 "
        "{%0,%1,%2,%3}, {%4,%5,%6,%7}, {%8,%9}, {%0,%1,%2,%3};"
        : "+f"(c[0]), "+f"(c[1]), "+f"(c[2]), "+f"(c[3])
        : "r"(a[0]), "r"(a[1]), "r"(a[2]), "r"(a[3]), "r"(b[0]), "r"(b[1]));
}
__device__ __forceinline__ void cvt_split2(float x, float y, uint32_t& hi, uint32_t& lo) {
    __nv_bfloat162 h = __floats2bfloat162_rn(x, y);
    float rx = x - __bfloat162float(h.x);
    float ry = y - __bfloat162float(h.y);
    __nv_bfloat162 l = __floats2bfloat162_rn(rx, ry);
    hi = *(uint32_t*)&h;
    lo = *(uint32_t*)&l;
}

// ---------------- zero scratch accumulators ----------------
__global__ void k_zero() {
    int i = blockIdx.x * blockDim.x + threadIdx.x;
    int stride = gridDim.x * blockDim.x;
    for (int j = i; j < G * 256; j += stride) d_agg2[j] = 0.f;
    for (int j = i; j < G * DD; j += stride) d_agg1[j] = 0.f;
    for (int j = i; j < G; j += stride) d_deg[j] = 0.f;
    if (i < 8) d_sums[i] = 0.f;
}

// ---------------- weight transpose + bf16 hi/lo split ----------------
__global__ void k_prepw(const float* __restrict__ W0, const float* __restrict__ W1,
                        const float* __restrict__ W2, const float* __restrict__ W3,
                        const float* __restrict__ W4, const float* __restrict__ W5,
                        const float* __restrict__ W6) {
    const float* Ws[7] = {W0, W1, W2, W3, W4, W5, W6};
    const int Ks[7] = {64, 128, 256, 256, 256, 256, 128};
    const int Ns[7] = {128, 256, 128, 128, 256, 256, 16};
    const int offs[8] = {0, 8192, 40960, 73728, 106496, 172032, 237568, 239616};
    int i = blockIdx.x * blockDim.x + threadIdx.x;
    if (i >= 239616) return;
    int s = 0;
    while (i >= offs[s + 1]) s++;
    int local = i - offs[s];
    int K = Ks[s], N = Ns[s];
    int n = local / K, k = local - n * K;
    float v = Ws[s][k * N + n];
    __nv_bfloat16 h = __float2bfloat16(v);
    d_wth[i] = h;
    d_wtl[i] = __float2bfloat16(v - __bfloat162float(h));
}

// ---------------- fully fused per-graph kernel (1 graph / block) ----------------
// xw^T = Wg^T @ x^T (HMMA split) -> dense-N GCN aggregation as HMMA GEMM
// -> h (smem bf16 hi/lo) -> g_emb -> a1 = tanh(h@Wf1+b) (HMMA) -> S -> penalty.
// dyn smem 68608 B -> 3 CTAs/SM.
#define TST 68    // stride for xw^T and N (bf16)
#define HST 136   // h row stride (bf16)
__global__ void __launch_bounds__(256, 3) k_xwagg(
    const float* __restrict__ x, const int* __restrict__ ei, const float* __restrict__ ew,
    const float* __restrict__ bg, const float* __restrict__ bf1,
    const float* __restrict__ Wf2, const float* __restrict__ bf2)
{
    extern __shared__ char dyn[];
    // R0 [0,34816): staging sXh[64*40]|sXl|sWh[128*40]|sWl (30720 B);
    //               then sxwT hi/lo [128][TST]; then h hi/lo [64][HST]
    __nv_bfloat16* sXh = (__nv_bfloat16*)dyn;
    __nv_bfloat16* sXl = sXh + 64 * 40;
    __nv_bfloat16* sWh = sXl + 64 * 40;
    __nv_bfloat16* sWl = sWh + 128 * 40;
    __nv_bfloat16* sTh = (__nv_bfloat16*)dyn;       // [128][TST]
    __nv_bfloat16* sTl = sTh + 128 * TST;
    __nv_bfloat16* shh = (__nv_bfloat16*)dyn;       // [64][HST]
    __nv_bfloat16* shl = shh + 64 * HST;
    // R1 [34816,+16384): dense N f32 [64][64]
    float* Nf = (float*)(dyn + 34816);
    // R2 [51200,+17408): N bf16 hi/lo [64][TST]
    __nv_bfloat16* sNh = (__nv_bfloat16*)(dyn + 51200);
    __nv_bfloat16* sNl = sNh + 64 * TST;

    __shared__ float sdeg[NN], sdinv[NN], sdeg2[NN], sdv2[NN];
    __shared__ float sbias[DD];
    __shared__ float sS[NN * 2];
    __shared__ float sgpart[DD];
    __shared__ float sped[4];

    int t = threadIdx.x, lane = t & 31, warp = t >> 5;
    int g = blockIdx.x;
    const float* A = x + (size_t)g * NN * FF;

    // ---- phase 0/1: edges, degrees, dense N ----
    int e_es = ei[(size_t)g * 512 + t];
    int e_ed = ei[(size_t)g * 512 + 256 + t];
    float e_w = ew[(size_t)g * 256 + t];
    if (t < NN) { sdeg[t] = 0.f; sdeg2[t] = 0.f; }
    if (t < DD) sbias[t] = bg[t];
    if (t < 4) sped[t] = 0.f;
#pragma unroll
    for (int j = 0; j < 16; j++) Nf[t + j * 256] = 0.f;
    __syncthreads();
    atomicAdd(&sdeg[e_ed], e_w);
    atomicAdd(&sdeg2[e_es], e_w);
    __syncthreads();
    if (t < NN) {
        sdinv[t] = rsqrtf(sdeg[t] + 1.0f);
        float d2 = sdeg2[t];
        sdv2[t] = (d2 > 0.f) ? rsqrtf(fmaxf(d2, 1e-30f)) : 0.f;
    }
    __syncthreads();
    atomicAdd(&Nf[e_ed * 64 + e_es], sdinv[e_es] * e_w * sdinv[e_ed]);
    if (t < NN) atomicAdd(&Nf[t * 65], sdinv[t] * sdinv[t]);
    // (phase-2 syncs order these before the N conversion below)

    // ---- phase 2: HMMA xw^T = Wg^T @ x^T  (M=128 c, N=64 s, K=64 f) ----
    int warpC = warp >> 1, warpS = warp & 1;   // 4 x 2
    float acc[2][4][4];
#pragma unroll
    for (int mt = 0; mt < 2; mt++)
#pragma unroll
        for (int nt = 0; nt < 4; nt++)
#pragma unroll
            for (int j = 0; j < 4; j++) acc[mt][nt][j] = 0.f;

    int lar = t >> 2, lac = (t & 3) * 8;     // x loader: 64 rows x 32 cols, 8/thread
    int lbr = t >> 1, lbc = (t & 1) * 16;    // W loader: 128 rows x 32 cols, 16/thread
    for (int kc = 0; kc < 64; kc += 32) {
        {
            const float* Ar = A + (size_t)lar * 64 + kc + lac;
            float4 v0 = *(const float4*)Ar;
            float4 v1 = *(const float4*)(Ar + 4);
            uint32_t h0, l0, h1, l1, h2, l2, h3, l3;
            cvt_split2(v0.x, v0.y, h0, l0);
            cvt_split2(v0.z, v0.w, h1, l1);
            cvt_split2(v1.x, v1.y, h2, l2);
            cvt_split2(v1.z, v1.w, h3, l3);
            *(uint32_t*)&sXh[lar * 40 + lac]     = h0;
            *(uint32_t*)&sXh[lar * 40 + lac + 2] = h1;
            *(uint32_t*)&sXh[lar * 40 + lac + 4] = h2;
            *(uint32_t*)&sXh[lar * 40 + lac + 6] = h3;
            *(uint32_t*)&sXl[lar * 40 + lac]     = l0;
            *(uint32_t*)&sXl[lar * 40 + lac + 2] = l1;
            *(uint32_t*)&sXl[lar * 40 + lac + 4] = l2;
            *(uint32_t*)&sXl[lar * 40 + lac + 6] = l3;
        }
        {
            const __nv_bfloat16* bh = d_wth + (size_t)lbr * 64 + kc + lbc;
            const __nv_bfloat16* bl = d_wtl + (size_t)lbr * 64 + kc + lbc;
            *(uint4*)&sWh[lbr * 40 + lbc]     = *(const uint4*)bh;
            *(uint4*)&sWh[lbr * 40 + lbc + 8] = *(const uint4*)(bh + 8);
            *(uint4*)&sWl[lbr * 40 + lbc]     = *(const uint4*)bl;
            *(uint4*)&sWl[lbr * 40 + lbc + 8] = *(const uint4*)(bl + 8);
        }
        __syncthreads();
#pragma unroll
        for (int ks = 0; ks < 32; ks += 16) {
            int kb = ks + (lane & 3) * 2;
            uint32_t ah[2][4], al[2][4];
#pragma unroll
            for (int mt = 0; mt < 2; mt++) {
                int r = warpC * 32 + mt * 16 + (lane >> 2);
                ah[mt][0] = *(const uint32_t*)&sWh[r * 40 + kb];
                ah[mt][1] = *(const uint32_t*)&sWh[(r + 8) * 40 + kb];
                ah[mt][2] = *(const uint32_t*)&sWh[r * 40 + kb + 8];
                ah[mt][3] = *(const uint32_t*)&sWh[(r + 8) * 40 + kb + 8];
                al[mt][0] = *(const uint32_t*)&sWl[r * 40 + kb];
                al[mt][1] = *(const uint32_t*)&sWl[(r + 8) * 40 + kb];
                al[mt][2] = *(const uint32_t*)&sWl[r * 40 + kb + 8];
                al[mt][3] = *(const uint32_t*)&sWl[(r + 8) * 40 + kb + 8];
            }
            uint32_t bhf[4][2], blf[4][2];
#pragma unroll
            for (int nt = 0; nt < 4; nt++) {
                int r = warpS * 32 + nt * 8 + (lane >> 2);
                bhf[nt][0] = *(const uint32_t*)&sXh[r * 40 + kb];
                bhf[nt][1] = *(const uint32_t*)&sXh[r * 40 + kb + 8];
                blf[nt][0] = *(const uint32_t*)&sXl[r * 40 + kb];
                blf[nt][1] = *(const uint32_t*)&sXl[r * 40 + kb + 8];
            }
#pragma unroll
            for (int mt = 0; mt < 2; mt++)
#pragma unroll
                for (int nt = 0; nt < 4; nt++) {
                    mma_bf16(acc[mt][nt], ah[mt], bhf[nt]);
                    mma_bf16(acc[mt][nt], ah[mt], blf[nt]);
                    mma_bf16(acc[mt][nt], al[mt], bhf[nt]);
                }
        }
        __syncthreads();
    }

    // ---- phase 2b: store xw^T (bf16 split) to R0 + convert N to bf16 split ----
#pragma unroll
    for (int mt = 0; mt < 2; mt++) {
        int c0 = warpC * 32 + mt * 16 + (lane >> 2);
#pragma unroll
        for (int nt = 0; nt < 4; nt++) {
            int s0 = warpS * 32 + nt * 8 + (lane & 3) * 2;
            uint32_t hA, lA, hB, lB;
            cvt_split2(acc[mt][nt][0], acc[mt][nt][1], hA, lA);
            cvt_split2(acc[mt][nt][2], acc[mt][nt][3], hB, lB);
            *(uint32_t*)&sTh[c0 * TST + s0]       = hA;
            *(uint32_t*)&sTl[c0 * TST + s0]       = lA;
            *(uint32_t*)&sTh[(c0 + 8) * TST + s0] = hB;
            *(uint32_t*)&sTl[(c0 + 8) * TST + s0] = lB;
        }
    }
#pragma unroll
    for (int j = 0; j < 16; j++) {
        int i = t + j * 256;
        int row = i >> 6, col = i & 63;
        float v = Nf[i];
        __nv_bfloat16 hb = __float2bfloat16(v);
        sNh[row * TST + col] = hb;
        sNl[row * TST + col] = __float2bfloat16(v - __bfloat162float(hb));
    }
    __syncthreads();

    // ---- phase 3: HMMA h = N @ xw  (M=64 n, N=128 c, K=64 s) ----
    int warpM = warp >> 2, warpN = warp & 3;   // 2 x 4
    float acc2[2][4][4];
#pragma unroll
    for (int mt = 0; mt < 2; mt++)
#pragma unroll
        for (int nt = 0; nt < 4; nt++)
#pragma unroll
            for (int j = 0; j < 4; j++) acc2[mt][nt][j] = 0.f;
#pragma unroll
    for (int ks = 0; ks < 4; ks++) {
        int kb = ks * 16 + (lane & 3) * 2;
        uint32_t ah[2][4], al[2][4];
#pragma unroll
        for (int mt = 0; mt < 2; mt++) {
            int r = warpM * 32 + mt * 16 + (lane >> 2);
            ah[mt][0] = *(const uint32_t*)&sNh[r * TST + kb];
            ah[mt][1] = *(const uint32_t*)&sNh[(r + 8) * TST + kb];
            ah[mt][2] = *(const uint32_t*)&sNh[r * TST + kb + 8];
            ah[mt][3] = *(const uint32_t*)&sNh[(r + 8) * TST + kb + 8];
            al[mt][0] = *(const uint32_t*)&sNl[r * TST + kb];
            al[mt][1] = *(const uint32_t*)&sNl[(r + 8) * TST + kb];
            al[mt][2] = *(const uint32_t*)&sNl[r * TST + kb + 8];
            al[mt][3] = *(const uint32_t*)&sNl[(r + 8) * TST + kb + 8];
        }
        uint32_t bhf[4][2], blf[4][2];
#pragma unroll
        for (int nt = 0; nt < 4; nt++) {
            int r = warpN * 32 + nt * 8 + (lane >> 2);
            bhf[nt][0] = *(const uint32_t*)&sTh[r * TST + kb];
            bhf[nt][1] = *(const uint32_t*)&sTh[r * TST + kb + 8];
            blf[nt][0] = *(const uint32_t*)&sTl[r * TST + kb];
            blf[nt][1] = *(const uint32_t*)&sTl[r * TST + kb + 8];
        }
#pragma unroll
        for (int mt = 0; mt < 2; mt++)
#pragma unroll
            for (int nt = 0; nt < 4; nt++) {
                mma_bf16(acc2[mt][nt], ah[mt], bhf[nt]);
                mma_bf16(acc2[mt][nt], ah[mt], blf[nt]);
                mma_bf16(acc2[mt][nt], al[mt], bhf[nt]);
            }
    }
    __syncthreads();   // all xw^T reads done before h overwrites R0

    // ---- phase 3b: h epilogue -> smem bf16 split (+bias) ----
#pragma unroll
    for (int mt = 0; mt < 2; mt++) {
        int n0 = warpM * 32 + mt * 16 + (lane >> 2);
#pragma unroll
        for (int nt = 0; nt < 4; nt++) {
            int c0 = warpN * 32 + nt * 8 + (lane & 3) * 2;
            float b0 = sbias[c0], b1 = sbias[c0 + 1];
            uint32_t hA, lA, hB, lB;
            cvt_split2(acc2[mt][nt][0] + b0, acc2[mt][nt][1] + b1, hA, lA);
            cvt_split2(acc2[mt][nt][2] + b0, acc2[mt][nt][3] + b1, hB, lB);
            *(uint32_t*)&shh[n0 * HST + c0]       = hA;
            *(uint32_t*)&shl[n0 * HST + c0]       = lA;
            *(uint32_t*)&shh[(n0 + 8) * HST + c0] = hB;
            *(uint32_t*)&shl[(n0 + 8) * HST + c0] = lB;
        }
    }
    __syncthreads();

    // ---- phase 3c: g_emb = 0.5 * sum_n h[n][c] ----
    {
        int half = t >> 7, c = t & 127;
        float gsum = 0.f;
#pragma unroll
        for (int n0 = 0; n0 < 32; n0++) {
            int n = half * 32 + n0;
            gsum += __bfloat162float(shh[n * HST + c]) + __bfloat162float(shl[n * HST + c]);
        }
        if (half == 1) sgpart[c] = gsum;
        __syncthreads();
        if (half == 0)
            d_gembs[(size_t)g * 128 + c] = 0.5f * (gsum + sgpart[c]);
    }
    __syncthreads();

    // ---- phase 4: a1 = tanh(h @ Wf1 + bf1), logits, softmax -> sS (warps 0-3) ----
    if (warp < 4) {
        int r = lane >> 2, kb2 = (lane & 3) * 2;
        int rowW = warp * 16;
        float a16[2][4];
#pragma unroll
        for (int nt = 0; nt < 2; nt++)
#pragma unroll
            for (int j = 0; j < 4; j++) a16[nt][j] = 0.f;
        const __nv_bfloat16* Bh = d_wth + 237568;
        const __nv_bfloat16* Bl = d_wtl + 237568;
#pragma unroll
        for (int ks = 0; ks < 8; ks++) {
            int k0 = ks * 16 + kb2;
            uint32_t ah[4], al[4];
            ah[0] = *(const uint32_t*)&shh[(rowW + r) * HST + k0];
            ah[1] = *(const uint32_t*)&shh[(rowW + r + 8) * HST + k0];
            ah[2] = *(const uint32_t*)&shh[(rowW + r) * HST + k0 + 8];
            ah[3] = *(const uint32_t*)&shh[(rowW + r + 8) * HST + k0 + 8];
            al[0] = *(const uint32_t*)&shl[(rowW + r) * HST + k0];
            al[1] = *(const uint32_t*)&shl[(rowW + r + 8) * HST + k0];
            al[2] = *(const uint32_t*)&shl[(rowW + r) * HST + k0 + 8];
            al[3] = *(const uint32_t*)&shl[(rowW + r + 8) * HST + k0 + 8];
#pragma unroll
            for (int nt = 0; nt < 2; nt++) {
                int n = nt * 8 + r;
                uint32_t bh[2], bl[2];
                bh[0] = *(const uint32_t*)(Bh + n * 128 + k0);
                bh[1] = *(const uint32_t*)(Bh + n * 128 + k0 + 8);
                bl[0] = *(const uint32_t*)(Bl + n * 128 + k0);
                bl[1] = *(const uint32_t*)(Bl + n * 128 + k0 + 8);
                mma_bf16(a16[nt], ah, bh);
                mma_bf16(a16[nt], ah, bl);
                mma_bf16(a16[nt], al, bh);
            }
        }
        float l0a = 0.f, l1a = 0.f, l0b = 0.f, l1b = 0.f;
#pragma unroll
        for (int nt = 0; nt < 2; nt++) {
            int c0 = nt * 8 + (lane & 3) * 2;
            float b0 = bf1[c0], b1 = bf1[c0 + 1];
            float w00 = Wf2[c0 * 2], w01 = Wf2[c0 * 2 + 1];
            float w10 = Wf2[c0 * 2 + 2], w11 = Wf2[c0 * 2 + 3];
            float t0 = tanhf(a16[nt][0] + b0), t1 = tanhf(a16[nt][1] + b1);
            float t2 = tanhf(a16[nt][2] + b0), t3 = tanhf(a16[nt][3] + b1);
            l0a = fmaf(t0, w00, fmaf(t1, w10, l0a));
            l1a = fmaf(t0, w01, fmaf(t1, w11, l1a));
            l0b = fmaf(t2, w00, fmaf(t3, w10, l0b));
            l1b = fmaf(t2, w01, fmaf(t3, w11, l1b));
        }
#pragma unroll
        for (int off = 1; off <= 2; off <<= 1) {
            l0a += __shfl_xor_sync(0xffffffffu, l0a, off);
            l1a += __shfl_xor_sync(0xffffffffu, l1a, off);
            l0b += __shfl_xor_sync(0xffffffffu, l0b, off);
            l1b += __shfl_xor_sync(0xffffffffu, l1b, off);
        }
        if ((lane & 3) == 0) {
            float b20 = bf2[0], b21 = bf2[1];
            float la0 = l0a + b20, la1 = l1a + b21;
            float m = fmaxf(la0, la1);
            float e0 = expf(la0 - m), e1 = expf(la1 - m);
            float inv = 1.f / (e0 + e1);
            sS[(rowW + r) * 2]     = e0 * inv;
            sS[(rowW + r) * 2 + 1] = e1 * inv;
            float lb0 = l0b + b20, lb1 = l1b + b21;
            float m2 = fmaxf(lb0, lb1);
            float f0 = expf(lb0 - m2), f1 = expf(lb1 - m2);
            float inv2 = 1.f / (f0 + f1);
            sS[(rowW + r + 8) * 2]     = f0 * inv2;
            sS[(rowW + r + 8) * 2 + 1] = f1 * inv2;
        }
    }
    __syncthreads();

    // ---- phase 5: Laplacian penalty ----
    {
        float p[4] = {0, 0, 0, 0};
        if (t < NN) {
            float s0 = sS[t * 2], s1 = sS[t * 2 + 1];
            p[0] = s0 * s0; p[1] = s0 * s1; p[2] = s1 * s0; p[3] = s1 * s1;
        }
        {
            float lw = -sdv2[e_es] * e_w * sdv2[e_ed];
            float q0 = sS[e_es * 2], q1 = sS[e_es * 2 + 1];
            float r0 = sS[e_ed * 2], r1 = sS[e_ed * 2 + 1];
            p[0] = fmaf(lw, q0 * r0, p[0]);
            p[1] = fmaf(lw, q0 * r1, p[1]);
            p[2] = fmaf(lw, q1 * r0, p[2]);
            p[3] = fmaf(lw, q1 * r1, p[3]);
        }
#pragma unroll
        for (int off = 16; off; off >>= 1)
#pragma unroll
            for (int j = 0; j < 4; j++)
                p[j] += __shfl_down_sync(0xffffffffu, p[j], off);
        if (lane == 0) {
#pragma unroll
            for (int j = 0; j < 4; j++) atomicAdd(&sped[j], p[j]);
        }
    }
    __syncthreads();
    if (t == 0) {
        float A00 = sped[0], A01 = sped[1], A10 = sped[2], A11 = sped[3];
        float r0 = fmaxf(fabsf(A00) + fabsf(A01), 1e-12f);
        float r1 = fmaxf(fabsf(A10) + fabsf(A11), 1e-12f);
        float dd0 = A00 / r0 - 1.f, dd1 = A11 / r1 - 1.f;
        atomicAdd(&d_sums[0], 0.5f * (dd0 * dd0 + dd1 * dd1));
    }
}

// ---------------- mma.sync GEMM (graph-level): C = act(A @ W + b) --------------
__global__ void __launch_bounds__(256) k_mma(
    int selA, int K, int wtoff,
    const float* __restrict__ bias, int selC, int Cs, int act)
{
    __shared__ __nv_bfloat16 sAh[128][40];
    __shared__ __nv_bfloat16 sAl[128][40];
    __shared__ __nv_bfloat16 sBh[128][40];
    __shared__ __nv_bfloat16 sBl[128][40];
    __shared__ float sbias[128];

    int t = threadIdx.x;
    const float* A = (selA == 1) ? d_agg1 : (selA == 2) ? d_agg2 : d_zc;
    float* C = (selC == 1) ? d_h : (selC == 2) ? d_mu
             : (selC == 3) ? d_ls : (selC == 4) ? d_zl1 : d_zl2;
    int rowBase = blockIdx.y * 128, colBase = blockIdx.x * 128;
    if (t < 128) sbias[t] = bias[colBase + t];

    int lane = t & 31, warp = t >> 5;
    int warpM = warp >> 2, warpN = warp & 3;

    float acc[4][4][4];
#pragma unroll
    for (int mt = 0; mt < 4; mt++)
#pragma unroll
        for (int nt = 0; nt < 4; nt++)
#pragma unroll
            for (int j = 0; j < 4; j++) acc[mt][nt][j] = 0.f;

    int ldr = t >> 1, ldc = (t & 1) * 16;

    for (int kc = 0; kc < K; kc += 32) {
        const float* Ar = A + (size_t)(rowBase + ldr) * K + kc + ldc;
#pragma unroll
        for (int j = 0; j < 4; j++) {
            float4 v = *(const float4*)(Ar + j * 4);
            uint32_t h0, l0, h1, l1;
            cvt_split2(v.x, v.y, h0, l0);
            cvt_split2(v.z, v.w, h1, l1);
            *(uint32_t*)&sAh[ldr][ldc + j * 4]     = h0;
            *(uint32_t*)&sAh[ldr][ldc + j * 4 + 2] = h1;
            *(uint32_t*)&sAl[ldr][ldc + j * 4]     = l0;
            *(uint32_t*)&sAl[ldr][ldc + j * 4 + 2] = l1;
        }
        {
            const __nv_bfloat16* bh = d_wth + wtoff + (size_t)(colBase + ldr) * K + kc + ldc;
            const __nv_bfloat16* bl = d_wtl + wtoff + (size_t)(colBase + ldr) * K + kc + ldc;
            *(uint4*)&sBh[ldr][ldc]     = *(const uint4*)bh;
            *(uint4*)&sBh[ldr][ldc + 8] = *(const uint4*)(bh + 8);
            *(uint4*)&sBl[ldr][ldc]     = *(const uint4*)bl;
            *(uint4*)&sBl[ldr][ldc + 8] = *(const uint4*)(bl + 8);
        }
        __syncthreads();
#pragma unroll
        for (int ks = 0; ks < 32; ks += 16) {
            int kb = ks + (lane & 3) * 2;
            int ar = warpM * 64 + (lane >> 2);
            uint32_t ah[4][4], al[4][4];
#pragma unroll
            for (int mt = 0; mt < 4; mt++) {
                int r = ar + mt * 16;
                ah[mt][0] = *(const uint32_t*)&sAh[r][kb];
                ah[mt][1] = *(const uint32_t*)&sAh[r + 8][kb];
                ah[mt][2] = *(const uint32_t*)&sAh[r][kb + 8];
                ah[mt][3] = *(const uint32_t*)&sAh[r + 8][kb + 8];
                al[mt][0] = *(const uint32_t*)&sAl[r][kb];
                al[mt][1] = *(const uint32_t*)&sAl[r + 8][kb];
                al[mt][2] = *(const uint32_t*)&sAl[r][kb + 8];
                al[mt][3] = *(const uint32_t*)&sAl[r + 8][kb + 8];
            }
            uint32_t bhf[4][2], blf[4][2];
#pragma unroll
            for (int nt = 0; nt < 4; nt++) {
                int r = warpN * 32 + nt * 8 + (lane >> 2);
                bhf[nt][0] = *(const uint32_t*)&sBh[r][kb];
                bhf[nt][1] = *(const uint32_t*)&sBh[r][kb + 8];
                blf[nt][0] = *(const uint32_t*)&sBl[r][kb];
                blf[nt][1] = *(const uint32_t*)&sBl[r][kb + 8];
            }
#pragma unroll
            for (int mt = 0; mt < 4; mt++)
#pragma unroll
                for (int nt = 0; nt < 4; nt++) {
                    mma_bf16(acc[mt][nt], ah[mt], bhf[nt]);
                    mma_bf16(acc[mt][nt], ah[mt], blf[nt]);
                    mma_bf16(acc[mt][nt], al[mt], bhf[nt]);
                }
        }
        __syncthreads();
    }

#pragma unroll
    for (int mt = 0; mt < 4; mt++) {
        int r0 = rowBase + warpM * 64 + mt * 16 + (lane >> 2);
#pragma unroll
        for (int nt = 0; nt < 4; nt++) {
            int cl = warpN * 32 + nt * 8 + (lane & 3) * 2;
            float b0 = sbias[cl], b1 = sbias[cl + 1];
            float2 v0, v1;
            v0.x = acc[mt][nt][0] + b0; v0.y = acc[mt][nt][1] + b1;
            v1.x = acc[mt][nt][2] + b0; v1.y = acc[mt][nt][3] + b1;
            if (act == 1) {
                v0.x = fmaxf(v0.x, 0.f); v0.y = fmaxf(v0.y, 0.f);
                v1.x = fmaxf(v1.x, 0.f); v1.y = fmaxf(v1.y, 0.f);
            } else if (act == 2) {
                v0.x = fminf(v0.x, 10.f); v0.y = fminf(v0.y, 10.f);
                v1.x = fminf(v1.x, 10.f); v1.y = fminf(v1.y, 10.f);
            }
            *(float2*)&C[(size_t)r0 * Cs + colBase + cl] = v0;
            *(float2*)&C[(size_t)(r0 + 8) * Cs + colBase + cl] = v1;
        }
    }
}

// ---------------- graph-level degree ----------------
__global__ void k_deg(const int* __restrict__ pe) {
    int i = blockIdx.x * blockDim.x + threadIdx.x;
    if (i < EPN) atomicAdd(&d_deg[pe[EPN + i]], 1.0f);
}
__global__ void k_dinv() {
    int i = blockIdx.x * blockDim.x + threadIdx.x;
    if (i < G) d_deg[i] = rsqrtf(d_deg[i] + 1.0f);
}

// ---------------- scatter (warp/edge) with fused self-loop term ----------------
__global__ void __launch_bounds__(256) k_scatter(const int* __restrict__ pe, int sel) {
    int tid = blockIdx.x * 256 + threadIdx.x;   // 0 .. EPN*32-1
    int gw = tid >> 5, lane = tid & 31;
    int a = pe[gw], b = pe[EPN + gw];
    float norm = d_deg[a] * d_deg[b];
    if (sel == 0) {
        const float* X = d_gembs + (size_t)a * DD;
        float* Ag = d_agg1 + (size_t)b * DD;
#pragma unroll
        for (int d = lane; d < DD; d += 32) atomicAdd(&Ag[d], X[d] * norm);
        if (tid < G * DD) {
            float di = d_deg[tid >> 7];
            atomicAdd(&d_agg1[tid], d_gembs[tid] * di * di);
        }
    } else {
        const float* X = d_h + (size_t)a * 256;
        float* Ag = d_agg2 + (size_t)b * 256;
#pragma unroll
        for (int d = lane; d < 256; d += 32) atomicAdd(&Ag[d], X[d] * norm);
        float di = d_deg[tid >> 8];
        atomicAdd(&d_agg2[tid], d_h[tid] * di * di);
    }
}

// ---------------- z, zc, KL ----------------
__global__ void __launch_bounds__(256) k_z(const float* __restrict__ eps_,
                                           const float* __restrict__ emb) {
    int i = blockIdx.x * 256 + threadIdx.x;
    float m = d_mu[i], l = d_ls[i];
    int n = i >> 7, d = i & 127;
    float z = m + eps_[i] * expf(l);
    d_zc[(size_t)n * 256 + d] = emb[i];
    d_zc[(size_t)n * 256 + 128 + d] = z;
    float klt = 1.f + 2.f * l - m * m - expf(2.f * l);
    for (int off = 16; off; off >>= 1) klt += __shfl_down_sync(0xffffffffu, klt, off);
    __shared__ float sw[8];
    if ((threadIdx.x & 31) == 0) sw[threadIdx.x >> 5] = klt;
    __syncthreads();
    if (threadIdx.x == 0) {
        float s = 0;
        for (int j = 0; j < 8; j++) s += sw[j];
        atomicAdd(&d_sums[3], s);
    }
}

// ---------------- edge predictions + log sums ----------------
__global__ void __launch_bounds__(256) k_pred(const int* __restrict__ pe,
                                              const int* __restrict__ ne,
                                              float* __restrict__ out) {
    int gw = (blockIdx.x * 256 + threadIdx.x) >> 5;
    int lane = threadIdx.x & 31;
    int wib = threadIdx.x >> 5;
    bool isneg = gw >= EPN;
    int i = isneg ? gw - EPN : gw;
    const int* e = isneg ? ne : pe;
    int a = e[i], b = e[EPN + i];
    const float4* ra = (const float4*)(d_zl1 + (size_t)a * 256);
    const float4* rb = (const float4*)(d_zl2 + (size_t)b * 256);
    float s = 0.f;
#pragma unroll
    for (int q = 0; q < 2; q++) {
        float4 u = ra[lane + 32 * q], v = rb[lane + 32 * q];
        s += u.x * v.x + u.y * v.y + u.z * v.z + u.w * v.w;
    }
    for (int off = 16; off; off >>= 1) s += __shfl_down_sync(0xffffffffu, s, off);
    __shared__ float sl[8];
    if (lane == 0) {
        float p = 1.f / (1.f + expf(-s));
        out[2 + gw] = p;
        sl[wib] = isneg ? logf(1.f - p + 1e-15f) : logf(p + 1e-15f);
    }
    __syncthreads();
    if (threadIdx.x == 0) {
        float tt = 0;
        for (int j = 0; j < 8; j++) tt += sl[j];
        atomicAdd(isneg ? &d_sums[2] : &d_sums[1], tt);
    }
}

__global__ void k_final(float* __restrict__ out) {
    float rec = -(d_sums[1] / (float)EPN) - (d_sums[2] / (float)EPN);
    float kl = -0.5f * d_sums[3] / (float)G;
    out[0] = rec + kl / (float)G;
    out[1] = d_sums[0] / (float)G;
}

// ---------------- launch ----------------
extern "C" void kernel_launch(void* const* d_in, const int* in_sizes, int n_in,
                              void* d_out, int out_size) {
    const float* x   = (const float*)d_in[0];
    const int*   ei  = (const int*)d_in[1];
    const float* ew  = (const float*)d_in[2];
    const int*   pe  = (const int*)d_in[3];
    const int*   ne  = (const int*)d_in[4];
    const float* eps_= (const float*)d_in[5];
    const float* Wg  = (const float*)d_in[6];
    const float* bg  = (const float*)d_in[7];
    const float* Wf1 = (const float*)d_in[8];
    const float* bf1 = (const float*)d_in[9];
    const float* Wf2 = (const float*)d_in[10];
    const float* bf2 = (const float*)d_in[11];
    const float* Wc1 = (const float*)d_in[12];
    const float* bc1 = (const float*)d_in[13];
    const float* Wmu = (const float*)d_in[14];
    const float* bmu = (const float*)d_in[15];
    const float* Wls = (const float*)d_in[16];
    const float* bls = (const float*)d_in[17];
    const float* emb = (const float*)d_in[18];
    const float* Wl1 = (const float*)d_in[19];
    const float* bl1 = (const float*)d_in[20];
    const float* Wl2 = (const float*)d_in[21];
    const float* bl2 = (const float*)d_in[22];
    float* out = (float*)d_out;

    const int dyn_xw = 34816 + 16384 + 17408;   // 68608 -> 3 CTAs/SM
    cudaFuncSetAttribute(k_xwagg, cudaFuncAttributeMaxDynamicSharedMemorySize, dyn_xw);

    k_zero<<<1024, 256>>>();
    k_prepw<<<234, 1024>>>(Wg, Wc1, Wmu, Wls, Wl1, Wl2, Wf1);
    k_xwagg<<<G, 256, dyn_xw>>>(x, ei, ew, bg, bf1, Wf2, bf2);
    k_deg<<<EPN / 256, 256>>>(pe);
    k_dinv<<<G / 256, 256>>>();
    k_scatter<<<EPN * 32 / 256, 256>>>(pe, 0);
    // h = relu(agg1 @ Wc1 + bc1)   [4096x128]@[128x256]
    k_mma<<<dim3(2, 32), 256>>>(1, 128, 8192, bc1, 1, 256, 1);
    k_scatter<<<EPN * 32 / 256, 256>>>(pe, 1);
    // mu / logstd    [4096x256]@[256x128]
    k_mma<<<dim3(1, 32), 256>>>(2, 256, 40960, bmu, 2, 128, 0);
    k_mma<<<dim3(1, 32), 256>>>(2, 256, 73728, bls, 3, 128, 2);
    k_z<<<G * DD / 256, 256>>>(eps_, emb);
    // zl1 / zl2      [4096x256]@[256x256]
    k_mma<<<dim3(2, 32), 256>>>(3, 256, 106496, bl1, 4, 256, 0);
    k_mma<<<dim3(2, 32), 256>>>(3, 256, 172032, bl2, 5, 256, 0);
    k_pred<<<2 * EPN * 32 / 256, 256>>>(pe, ne, out);
    k_final<<<1, 1>>>(out);
}

// round 10
// speedup vs baseline: 1.7461x; 1.1505x over previous
#include <cuda_runtime.h>
#include <cuda_bf16.h>
#include <math.h>
#include <stdint.h>

#define G   4096
#define NN  64
#define EE  256
#define FF  64
#define DD  128
#define EPN 32768

// ---------------- device scratch (static, no allocations) ----------------
__device__ float d_gembs[G * DD];
__device__ float d_deg[G];
__device__ float d_agg1[G * DD];
__device__ float d_h[G * 256];
__device__ float d_agg2[G * 256];
__device__ float d_mu[G * DD];
__device__ float d_ls[G * DD];
__device__ float d_zc[G * 256];
__device__ float d_zl1[G * 256];
__device__ float d_zl2[G * 256];
__device__ float d_sums[8];   // 0:pen 1:plog 2:nlog 3:kl
// transposed bf16 hi/lo weights [N][K]: Wg[0,8192) Wc1[8192,40960) Wmu[40960,73728)
// Wls[73728,106496) Wl1[106496,172032) Wl2[172032,237568) Wf1[237568,239616)
__device__ __nv_bfloat16 d_wth[239616];
__device__ __nv_bfloat16 d_wtl[239616];

// ---------------- helpers ----------------
__device__ __forceinline__ void mma_bf16(float* c, const uint32_t* a, const uint32_t* b) {
    asm volatile("mma.sync.aligned.m16n8k16.row.col.f32.bf16.bf16.f32 "
        "{%0,%1,%2,%3}, {%4,%5,%6,%7}, {%8,%9}, {%0,%1,%2,%3};"
        : "+f"(c[0]), "+f"(c[1]), "+f"(c[2]), "+f"(c[3])
        : "r"(a[0]), "r"(a[1]), "r"(a[2]), "r"(a[3]), "r"(b[0]), "r"(b[1]));
}
__device__ __forceinline__ void cvt_split2(float x, float y, uint32_t& hi, uint32_t& lo) {
    __nv_bfloat162 h = __floats2bfloat162_rn(x, y);
    float rx = x - __bfloat162float(h.x);
    float ry = y - __bfloat162float(h.y);
    __nv_bfloat162 l = __floats2bfloat162_rn(rx, ry);
    hi = *(uint32_t*)&h;
    lo = *(uint32_t*)&l;
}

// ---------------- zero scratch accumulators + graph-level degree ----------------
__global__ void k_zero(const int* __restrict__ pe) {
    int i = blockIdx.x * blockDim.x + threadIdx.x;
    int stride = gridDim.x * blockDim.x;
    for (int j = i; j < G * 256; j += stride) d_agg2[j] = 0.f;
    for (int j = i; j < G * DD; j += stride) d_agg1[j] = 0.f;
    for (int j = i; j < G; j += stride) d_deg[j] = 0.f;
    if (i < 8) d_sums[i] = 0.f;
}
__global__ void k_deg(const int* __restrict__ pe) {
    int i = blockIdx.x * blockDim.x + threadIdx.x;
    if (i < EPN) atomicAdd(&d_deg[pe[EPN + i]], 1.0f);
}
__global__ void k_dinv() {
    int i = blockIdx.x * blockDim.x + threadIdx.x;
    if (i < G) d_deg[i] = rsqrtf(d_deg[i] + 1.0f);
}

// ---------------- weight transpose + bf16 hi/lo split ----------------
__global__ void k_prepw(const float* __restrict__ W0, const float* __restrict__ W1,
                        const float* __restrict__ W2, const float* __restrict__ W3,
                        const float* __restrict__ W4, const float* __restrict__ W5,
                        const float* __restrict__ W6) {
    const float* Ws[7] = {W0, W1, W2, W3, W4, W5, W6};
    const int Ks[7] = {64, 128, 256, 256, 256, 256, 128};
    const int Ns[7] = {128, 256, 128, 128, 256, 256, 16};
    const int offs[8] = {0, 8192, 40960, 73728, 106496, 172032, 237568, 239616};
    int i = blockIdx.x * blockDim.x + threadIdx.x;
    if (i >= 239616) return;
    int s = 0;
    while (i >= offs[s + 1]) s++;
    int local = i - offs[s];
    int K = Ks[s], N = Ns[s];
    int n = local / K, k = local - n * K;
    float v = Ws[s][k * N + n];
    __nv_bfloat16 h = __float2bfloat16(v);
    d_wth[i] = h;
    d_wtl[i] = __float2bfloat16(v - __bfloat162float(h));
}

// ---------------- fully fused per-graph kernel (1 graph / block) ----------------
// xw^T = Wg^T @ x^T (HMMA split) -> dense-N GCN aggregation as HMMA GEMM
// -> h (smem bf16 hi/lo) -> g_emb -> a1 = tanh(h@Wf1+b) (HMMA) -> S -> penalty.
// dyn smem 68608 B -> 3 CTAs/SM.
#define TST 68    // stride for xw^T and N (bf16)
#define HST 136   // h row stride (bf16)
__global__ void __launch_bounds__(256, 3) k_xwagg(
    const float* __restrict__ x, const int* __restrict__ ei, const float* __restrict__ ew,
    const float* __restrict__ bg, const float* __restrict__ bf1,
    const float* __restrict__ Wf2, const float* __restrict__ bf2)
{
    extern __shared__ char dyn[];
    __nv_bfloat16* sXh = (__nv_bfloat16*)dyn;
    __nv_bfloat16* sXl = sXh + 64 * 40;
    __nv_bfloat16* sWh = sXl + 64 * 40;
    __nv_bfloat16* sWl = sWh + 128 * 40;
    __nv_bfloat16* sTh = (__nv_bfloat16*)dyn;       // [128][TST]
    __nv_bfloat16* sTl = sTh + 128 * TST;
    __nv_bfloat16* shh = (__nv_bfloat16*)dyn;       // [64][HST]
    __nv_bfloat16* shl = shh + 64 * HST;
    float* Nf = (float*)(dyn + 34816);              // [64][64] f32
    __nv_bfloat16* sNh = (__nv_bfloat16*)(dyn + 51200);
    __nv_bfloat16* sNl = sNh + 64 * TST;

    __shared__ float sdeg[NN], sdinv[NN], sdeg2[NN], sdv2[NN];
    __shared__ float sbias[DD];
    __shared__ float sS[NN * 2];
    __shared__ float sgpart[DD];
    __shared__ float sped[4];

    int t = threadIdx.x, lane = t & 31, warp = t >> 5;
    int g = blockIdx.x;
    const float* A = x + (size_t)g * NN * FF;

    // ---- phase 0/1: edges, degrees, dense N ----
    int e_es = ei[(size_t)g * 512 + t];
    int e_ed = ei[(size_t)g * 512 + 256 + t];
    float e_w = ew[(size_t)g * 256 + t];
    if (t < NN) { sdeg[t] = 0.f; sdeg2[t] = 0.f; }
    if (t < DD) sbias[t] = bg[t];
    if (t < 4) sped[t] = 0.f;
#pragma unroll
    for (int j = 0; j < 16; j++) Nf[t + j * 256] = 0.f;
    __syncthreads();
    atomicAdd(&sdeg[e_ed], e_w);
    atomicAdd(&sdeg2[e_es], e_w);
    __syncthreads();
    if (t < NN) {
        sdinv[t] = rsqrtf(sdeg[t] + 1.0f);
        float d2 = sdeg2[t];
        sdv2[t] = (d2 > 0.f) ? rsqrtf(fmaxf(d2, 1e-30f)) : 0.f;
    }
    __syncthreads();
    atomicAdd(&Nf[e_ed * 64 + e_es], sdinv[e_es] * e_w * sdinv[e_ed]);
    if (t < NN) atomicAdd(&Nf[t * 65], sdinv[t] * sdinv[t]);

    // ---- phase 2: HMMA xw^T = Wg^T @ x^T  (M=128 c, N=64 s, K=64 f) ----
    int warpC = warp >> 1, warpS = warp & 1;   // 4 x 2
    float acc[2][4][4];
#pragma unroll
    for (int mt = 0; mt < 2; mt++)
#pragma unroll
        for (int nt = 0; nt < 4; nt++)
#pragma unroll
            for (int j = 0; j < 4; j++) acc[mt][nt][j] = 0.f;

    int lar = t >> 2, lac = (t & 3) * 8;
    int lbr = t >> 1, lbc = (t & 1) * 16;
    for (int kc = 0; kc < 64; kc += 32) {
        {
            const float* Ar = A + (size_t)lar * 64 + kc + lac;
            float4 v0 = *(const float4*)Ar;
            float4 v1 = *(const float4*)(Ar + 4);
            uint32_t h0, l0, h1, l1, h2, l2, h3, l3;
            cvt_split2(v0.x, v0.y, h0, l0);
            cvt_split2(v0.z, v0.w, h1, l1);
            cvt_split2(v1.x, v1.y, h2, l2);
            cvt_split2(v1.z, v1.w, h3, l3);
            *(uint32_t*)&sXh[lar * 40 + lac]     = h0;
            *(uint32_t*)&sXh[lar * 40 + lac + 2] = h1;
            *(uint32_t*)&sXh[lar * 40 + lac + 4] = h2;
            *(uint32_t*)&sXh[lar * 40 + lac + 6] = h3;
            *(uint32_t*)&sXl[lar * 40 + lac]     = l0;
            *(uint32_t*)&sXl[lar * 40 + lac + 2] = l1;
            *(uint32_t*)&sXl[lar * 40 + lac + 4] = l2;
            *(uint32_t*)&sXl[lar * 40 + lac + 6] = l3;
        }
        {
            const __nv_bfloat16* bh = d_wth + (size_t)lbr * 64 + kc + lbc;
            const __nv_bfloat16* bl = d_wtl + (size_t)lbr * 64 + kc + lbc;
            *(uint4*)&sWh[lbr * 40 + lbc]     = *(const uint4*)bh;
            *(uint4*)&sWh[lbr * 40 + lbc + 8] = *(const uint4*)(bh + 8);
            *(uint4*)&sWl[lbr * 40 + lbc]     = *(const uint4*)bl;
            *(uint4*)&sWl[lbr * 40 + lbc + 8] = *(const uint4*)(bl + 8);
        }
        __syncthreads();
#pragma unroll
        for (int ks = 0; ks < 32; ks += 16) {
            int kb = ks + (lane & 3) * 2;
            uint32_t ah[2][4], al[2][4];
#pragma unroll
            for (int mt = 0; mt < 2; mt++) {
                int r = warpC * 32 + mt * 16 + (lane >> 2);
                ah[mt][0] = *(const uint32_t*)&sWh[r * 40 + kb];
                ah[mt][1] = *(const uint32_t*)&sWh[(r + 8) * 40 + kb];
                ah[mt][2] = *(const uint32_t*)&sWh[r * 40 + kb + 8];
                ah[mt][3] = *(const uint32_t*)&sWh[(r + 8) * 40 + kb + 8];
                al[mt][0] = *(const uint32_t*)&sWl[r * 40 + kb];
                al[mt][1] = *(const uint32_t*)&sWl[(r + 8) * 40 + kb];
                al[mt][2] = *(const uint32_t*)&sWl[r * 40 + kb + 8];
                al[mt][3] = *(const uint32_t*)&sWl[(r + 8) * 40 + kb + 8];
            }
            uint32_t bhf[4][2], blf[4][2];
#pragma unroll
            for (int nt = 0; nt < 4; nt++) {
                int r = warpS * 32 + nt * 8 + (lane >> 2);
                bhf[nt][0] = *(const uint32_t*)&sXh[r * 40 + kb];
                bhf[nt][1] = *(const uint32_t*)&sXh[r * 40 + kb + 8];
                blf[nt][0] = *(const uint32_t*)&sXl[r * 40 + kb];
                blf[nt][1] = *(const uint32_t*)&sXl[r * 40 + kb + 8];
            }
#pragma unroll
            for (int mt = 0; mt < 2; mt++)
#pragma unroll
                for (int nt = 0; nt < 4; nt++) {
                    mma_bf16(acc[mt][nt], ah[mt], bhf[nt]);
                    mma_bf16(acc[mt][nt], ah[mt], blf[nt]);
                    mma_bf16(acc[mt][nt], al[mt], bhf[nt]);
                }
        }
        __syncthreads();
    }

    // ---- phase 2b: store xw^T (bf16 split) + convert N to bf16 split ----
#pragma unroll
    for (int mt = 0; mt < 2; mt++) {
        int c0 = warpC * 32 + mt * 16 + (lane >> 2);
#pragma unroll
        for (int nt = 0; nt < 4; nt++) {
            int s0 = warpS * 32 + nt * 8 + (lane & 3) * 2;
            uint32_t hA, lA, hB, lB;
            cvt_split2(acc[mt][nt][0], acc[mt][nt][1], hA, lA);
            cvt_split2(acc[mt][nt][2], acc[mt][nt][3], hB, lB);
            *(uint32_t*)&sTh[c0 * TST + s0]       = hA;
            *(uint32_t*)&sTl[c0 * TST + s0]       = lA;
            *(uint32_t*)&sTh[(c0 + 8) * TST + s0] = hB;
            *(uint32_t*)&sTl[(c0 + 8) * TST + s0] = lB;
        }
    }
#pragma unroll
    for (int j = 0; j < 16; j++) {
        int i = t + j * 256;
        int row = i >> 6, col = i & 63;
        float v = Nf[i];
        __nv_bfloat16 hb = __float2bfloat16(v);
        sNh[row * TST + col] = hb;
        sNl[row * TST + col] = __float2bfloat16(v - __bfloat162float(hb));
    }
    __syncthreads();

    // ---- phase 3: HMMA h = N @ xw  (M=64 n, N=128 c, K=64 s) ----
    int warpM = warp >> 2, warpN = warp & 3;
    float acc2[2][4][4];
#pragma unroll
    for (int mt = 0; mt < 2; mt++)
#pragma unroll
        for (int nt = 0; nt < 4; nt++)
#pragma unroll
            for (int j = 0; j < 4; j++) acc2[mt][nt][j] = 0.f;
#pragma unroll
    for (int ks = 0; ks < 4; ks++) {
        int kb = ks * 16 + (lane & 3) * 2;
        uint32_t ah[2][4], al[2][4];
#pragma unroll
        for (int mt = 0; mt < 2; mt++) {
            int r = warpM * 32 + mt * 16 + (lane >> 2);
            ah[mt][0] = *(const uint32_t*)&sNh[r * TST + kb];
            ah[mt][1] = *(const uint32_t*)&sNh[(r + 8) * TST + kb];
            ah[mt][2] = *(const uint32_t*)&sNh[r * TST + kb + 8];
            ah[mt][3] = *(const uint32_t*)&sNh[(r + 8) * TST + kb + 8];
            al[mt][0] = *(const uint32_t*)&sNl[r * TST + kb];
            al[mt][1] = *(const uint32_t*)&sNl[(r + 8) * TST + kb];
            al[mt][2] = *(const uint32_t*)&sNl[r * TST + kb + 8];
            al[mt][3] = *(const uint32_t*)&sNl[(r + 8) * TST + kb + 8];
        }
        uint32_t bhf[4][2], blf[4][2];
#pragma unroll
        for (int nt = 0; nt < 4; nt++) {
            int r = warpN * 32 + nt * 8 + (lane >> 2);
            bhf[nt][0] = *(const uint32_t*)&sTh[r * TST + kb];
            bhf[nt][1] = *(const uint32_t*)&sTh[r * TST + kb + 8];
            blf[nt][0] = *(const uint32_t*)&sTl[r * TST + kb];
            blf[nt][1] = *(const uint32_t*)&sTl[r * TST + kb + 8];
        }
#pragma unroll
        for (int mt = 0; mt < 2; mt++)
#pragma unroll
            for (int nt = 0; nt < 4; nt++) {
                mma_bf16(acc2[mt][nt], ah[mt], bhf[nt]);
                mma_bf16(acc2[mt][nt], ah[mt], blf[nt]);
                mma_bf16(acc2[mt][nt], al[mt], bhf[nt]);
            }
    }
    __syncthreads();

    // ---- phase 3b: h epilogue -> smem bf16 split (+bias) ----
#pragma unroll
    for (int mt = 0; mt < 2; mt++) {
        int n0 = warpM * 32 + mt * 16 + (lane >> 2);
#pragma unroll
        for (int nt = 0; nt < 4; nt++) {
            int c0 = warpN * 32 + nt * 8 + (lane & 3) * 2;
            float b0 = sbias[c0], b1 = sbias[c0 + 1];
            uint32_t hA, lA, hB, lB;
            cvt_split2(acc2[mt][nt][0] + b0, acc2[mt][nt][1] + b1, hA, lA);
            cvt_split2(acc2[mt][nt][2] + b0, acc2[mt][nt][3] + b1, hB, lB);
            *(uint32_t*)&shh[n0 * HST + c0]       = hA;
            *(uint32_t*)&shl[n0 * HST + c0]       = lA;
            *(uint32_t*)&shh[(n0 + 8) * HST + c0] = hB;
            *(uint32_t*)&shl[(n0 + 8) * HST + c0] = lB;
        }
    }
    __syncthreads();

    // ---- phase 3c: g_emb = 0.5 * sum_n h[n][c] ----
    {
        int half = t >> 7, c = t & 127;
        float gsum = 0.f;
#pragma unroll
        for (int n0 = 0; n0 < 32; n0++) {
            int n = half * 32 + n0;
            gsum += __bfloat162float(shh[n * HST + c]) + __bfloat162float(shl[n * HST + c]);
        }
        if (half == 1) sgpart[c] = gsum;
        __syncthreads();
        if (half == 0)
            d_gembs[(size_t)g * 128 + c] = 0.5f * (gsum + sgpart[c]);
    }
    __syncthreads();

    // ---- phase 4: a1 = tanh(h @ Wf1 + bf1), logits, softmax -> sS (warps 0-3) ----
    if (warp < 4) {
        int r = lane >> 2, kb2 = (lane & 3) * 2;
        int rowW = warp * 16;
        float a16[2][4];
#pragma unroll
        for (int nt = 0; nt < 2; nt++)
#pragma unroll
            for (int j = 0; j < 4; j++) a16[nt][j] = 0.f;
        const __nv_bfloat16* Bh = d_wth + 237568;
        const __nv_bfloat16* Bl = d_wtl + 237568;
#pragma unroll
        for (int ks = 0; ks < 8; ks++) {
            int k0 = ks * 16 + kb2;
            uint32_t ah[4], al[4];
            ah[0] = *(const uint32_t*)&shh[(rowW + r) * HST + k0];
            ah[1] = *(const uint32_t*)&shh[(rowW + r + 8) * HST + k0];
            ah[2] = *(const uint32_t*)&shh[(rowW + r) * HST + k0 + 8];
            ah[3] = *(const uint32_t*)&shh[(rowW + r + 8) * HST + k0 + 8];
            al[0] = *(const uint32_t*)&shl[(rowW + r) * HST + k0];
            al[1] = *(const uint32_t*)&shl[(rowW + r + 8) * HST + k0];
            al[2] = *(const uint32_t*)&shl[(rowW + r) * HST + k0 + 8];
            al[3] = *(const uint32_t*)&shl[(rowW + r + 8) * HST + k0 + 8];
#pragma unroll
            for (int nt = 0; nt < 2; nt++) {
                int n = nt * 8 + r;
                uint32_t bh[2], bl[2];
                bh[0] = *(const uint32_t*)(Bh + n * 128 + k0);
                bh[1] = *(const uint32_t*)(Bh + n * 128 + k0 + 8);
                bl[0] = *(const uint32_t*)(Bl + n * 128 + k0);
                bl[1] = *(const uint32_t*)(Bl + n * 128 + k0 + 8);
                mma_bf16(a16[nt], ah, bh);
                mma_bf16(a16[nt], ah, bl);
                mma_bf16(a16[nt], al, bh);
            }
        }
        float l0a = 0.f, l1a = 0.f, l0b = 0.f, l1b = 0.f;
#pragma unroll
        for (int nt = 0; nt < 2; nt++) {
            int c0 = nt * 8 + (lane & 3) * 2;
            float b0 = bf1[c0], b1 = bf1[c0 + 1];
            float w00 = Wf2[c0 * 2], w01 = Wf2[c0 * 2 + 1];
            float w10 = Wf2[c0 * 2 + 2], w11 = Wf2[c0 * 2 + 3];
            float t0 = tanhf(a16[nt][0] + b0), t1 = tanhf(a16[nt][1] + b1);
            float t2 = tanhf(a16[nt][2] + b0), t3 = tanhf(a16[nt][3] + b1);
            l0a = fmaf(t0, w00, fmaf(t1, w10, l0a));
            l1a = fmaf(t0, w01, fmaf(t1, w11, l1a));
            l0b = fmaf(t2, w00, fmaf(t3, w10, l0b));
            l1b = fmaf(t2, w01, fmaf(t3, w11, l1b));
        }
#pragma unroll
        for (int off = 1; off <= 2; off <<= 1) {
            l0a += __shfl_xor_sync(0xffffffffu, l0a, off);
            l1a += __shfl_xor_sync(0xffffffffu, l1a, off);
            l0b += __shfl_xor_sync(0xffffffffu, l0b, off);
            l1b += __shfl_xor_sync(0xffffffffu, l1b, off);
        }
        if ((lane & 3) == 0) {
            float b20 = bf2[0], b21 = bf2[1];
            float la0 = l0a + b20, la1 = l1a + b21;
            float m = fmaxf(la0, la1);
            float e0 = expf(la0 - m), e1 = expf(la1 - m);
            float inv = 1.f / (e0 + e1);
            sS[(rowW + r) * 2]     = e0 * inv;
            sS[(rowW + r) * 2 + 1] = e1 * inv;
            float lb0 = l0b + b20, lb1 = l1b + b21;
            float m2 = fmaxf(lb0, lb1);
            float f0 = expf(lb0 - m2), f1 = expf(lb1 - m2);
            float inv2 = 1.f / (f0 + f1);
            sS[(rowW + r + 8) * 2]     = f0 * inv2;
            sS[(rowW + r + 8) * 2 + 1] = f1 * inv2;
        }
    }
    __syncthreads();

    // ---- phase 5: Laplacian penalty ----
    {
        float p[4] = {0, 0, 0, 0};
        if (t < NN) {
            float s0 = sS[t * 2], s1 = sS[t * 2 + 1];
            p[0] = s0 * s0; p[1] = s0 * s1; p[2] = s1 * s0; p[3] = s1 * s1;
        }
        {
            float lw = -sdv2[e_es] * e_w * sdv2[e_ed];
            float q0 = sS[e_es * 2], q1 = sS[e_es * 2 + 1];
            float r0 = sS[e_ed * 2], r1 = sS[e_ed * 2 + 1];
            p[0] = fmaf(lw, q0 * r0, p[0]);
            p[1] = fmaf(lw, q0 * r1, p[1]);
            p[2] = fmaf(lw, q1 * r0, p[2]);
            p[3] = fmaf(lw, q1 * r1, p[3]);
        }
#pragma unroll
        for (int off = 16; off; off >>= 1)
#pragma unroll
            for (int j = 0; j < 4; j++)
                p[j] += __shfl_down_sync(0xffffffffu, p[j], off);
        if (lane == 0) {
#pragma unroll
            for (int j = 0; j < 4; j++) atomicAdd(&sped[j], p[j]);
        }
    }
    __syncthreads();
    if (t == 0) {
        float A00 = sped[0], A01 = sped[1], A10 = sped[2], A11 = sped[3];
        float r0 = fmaxf(fabsf(A00) + fabsf(A01), 1e-12f);
        float r1 = fmaxf(fabsf(A10) + fabsf(A11), 1e-12f);
        float dd0 = A00 / r0 - 1.f, dd1 = A11 / r1 - 1.f;
        atomicAdd(&d_sums[0], 0.5f * (dd0 * dd0 + dd1 * dd1));
    }
}

// ---------------- dual-output mma.sync GEMM: C = act(A @ W + b) ----------------
// blockIdx.x < nx0 -> set 0, else set 1 (colBase rebased).
__global__ void __launch_bounds__(256) k_mma(
    int selA, int K, int nx0,
    int wtoff0, int wtoff1,
    const float* __restrict__ b0v, const float* __restrict__ b1v,
    int selC0, int selC1, int Cs, int act0, int act1)
{
    __shared__ __nv_bfloat16 sAh[128][40];
    __shared__ __nv_bfloat16 sAl[128][40];
    __shared__ __nv_bfloat16 sBh[128][40];
    __shared__ __nv_bfloat16 sBl[128][40];
    __shared__ float sbias[128];

    int t = threadIdx.x;
    const float* A = (selA == 1) ? d_agg1 : (selA == 2) ? d_agg2 : d_zc;
    int bx = blockIdx.x;
    int hsel = bx >= nx0;
    int colBase = (bx - (hsel ? nx0 : 0)) * 128;
    int wtoff = hsel ? wtoff1 : wtoff0;
    const float* bias = hsel ? b1v : b0v;
    int act = hsel ? act1 : act0;
    int selC = hsel ? selC1 : selC0;
    float* C = (selC == 1) ? d_h : (selC == 2) ? d_mu
             : (selC == 3) ? d_ls : (selC == 4) ? d_zl1 : d_zl2;
    int rowBase = blockIdx.y * 128;
    if (t < 128) sbias[t] = bias[colBase + t];

    int lane = t & 31, warp = t >> 5;
    int warpM = warp >> 2, warpN = warp & 3;

    float acc[4][4][4];
#pragma unroll
    for (int mt = 0; mt < 4; mt++)
#pragma unroll
        for (int nt = 0; nt < 4; nt++)
#pragma unroll
            for (int j = 0; j < 4; j++) acc[mt][nt][j] = 0.f;

    int ldr = t >> 1, ldc = (t & 1) * 16;

    for (int kc = 0; kc < K; kc += 32) {
        const float* Ar = A + (size_t)(rowBase + ldr) * K + kc + ldc;
#pragma unroll
        for (int j = 0; j < 4; j++) {
            float4 v = *(const float4*)(Ar + j * 4);
            uint32_t h0, l0, h1, l1;
            cvt_split2(v.x, v.y, h0, l0);
            cvt_split2(v.z, v.w, h1, l1);
            *(uint32_t*)&sAh[ldr][ldc + j * 4]     = h0;
            *(uint32_t*)&sAh[ldr][ldc + j * 4 + 2] = h1;
            *(uint32_t*)&sAl[ldr][ldc + j * 4]     = l0;
            *(uint32_t*)&sAl[ldr][ldc + j * 4 + 2] = l1;
        }
        {
            const __nv_bfloat16* bh = d_wth + wtoff + (size_t)(colBase + ldr) * K + kc + ldc;
            const __nv_bfloat16* bl = d_wtl + wtoff + (size_t)(colBase + ldr) * K + kc + ldc;
            *(uint4*)&sBh[ldr][ldc]     = *(const uint4*)bh;
            *(uint4*)&sBh[ldr][ldc + 8] = *(const uint4*)(bh + 8);
            *(uint4*)&sBl[ldr][ldc]     = *(const uint4*)bl;
            *(uint4*)&sBl[ldr][ldc + 8] = *(const uint4*)(bl + 8);
        }
        __syncthreads();
#pragma unroll
        for (int ks = 0; ks < 32; ks += 16) {
            int kb = ks + (lane & 3) * 2;
            int ar = warpM * 64 + (lane >> 2);
            uint32_t ah[4][4], al[4][4];
#pragma unroll
            for (int mt = 0; mt < 4; mt++) {
                int r = ar + mt * 16;
                ah[mt][0] = *(const uint32_t*)&sAh[r][kb];
                ah[mt][1] = *(const uint32_t*)&sAh[r + 8][kb];
                ah[mt][2] = *(const uint32_t*)&sAh[r][kb + 8];
                ah[mt][3] = *(const uint32_t*)&sAh[r + 8][kb + 8];
                al[mt][0] = *(const uint32_t*)&sAl[r][kb];
                al[mt][1] = *(const uint32_t*)&sAl[r + 8][kb];
                al[mt][2] = *(const uint32_t*)&sAl[r][kb + 8];
                al[mt][3] = *(const uint32_t*)&sAl[r + 8][kb + 8];
            }
            uint32_t bhf[4][2], blf[4][2];
#pragma unroll
            for (int nt = 0; nt < 4; nt++) {
                int r = warpN * 32 + nt * 8 + (lane >> 2);
                bhf[nt][0] = *(const uint32_t*)&sBh[r][kb];
                bhf[nt][1] = *(const uint32_t*)&sBh[r][kb + 8];
                blf[nt][0] = *(const uint32_t*)&sBl[r][kb];
                blf[nt][1] = *(const uint32_t*)&sBl[r][kb + 8];
            }
#pragma unroll
            for (int mt = 0; mt < 4; mt++)
#pragma unroll
                for (int nt = 0; nt < 4; nt++) {
                    mma_bf16(acc[mt][nt], ah[mt], bhf[nt]);
                    mma_bf16(acc[mt][nt], ah[mt], blf[nt]);
                    mma_bf16(acc[mt][nt], al[mt], bhf[nt]);
                }
        }
        __syncthreads();
    }

#pragma unroll
    for (int mt = 0; mt < 4; mt++) {
        int r0 = rowBase + warpM * 64 + mt * 16 + (lane >> 2);
#pragma unroll
        for (int nt = 0; nt < 4; nt++) {
            int cl = warpN * 32 + nt * 8 + (lane & 3) * 2;
            float b0 = sbias[cl], b1 = sbias[cl + 1];
            float2 v0, v1;
            v0.x = acc[mt][nt][0] + b0; v0.y = acc[mt][nt][1] + b1;
            v1.x = acc[mt][nt][2] + b0; v1.y = acc[mt][nt][3] + b1;
            if (act == 1) {
                v0.x = fmaxf(v0.x, 0.f); v0.y = fmaxf(v0.y, 0.f);
                v1.x = fmaxf(v1.x, 0.f); v1.y = fmaxf(v1.y, 0.f);
            } else if (act == 2) {
                v0.x = fminf(v0.x, 10.f); v0.y = fminf(v0.y, 10.f);
                v1.x = fminf(v1.x, 10.f); v1.y = fminf(v1.y, 10.f);
            }
            *(float2*)&C[(size_t)r0 * Cs + colBase + cl] = v0;
            *(float2*)&C[(size_t)(r0 + 8) * Cs + colBase + cl] = v1;
        }
    }
}

// ---------------- scatter (warp/edge), float4 vector atomics ----------------
__global__ void __launch_bounds__(256) k_scatter(const int* __restrict__ pe, int sel) {
    int tid = blockIdx.x * 256 + threadIdx.x;   // 0 .. EPN*32-1
    int gw = tid >> 5, lane = tid & 31;
    int a = pe[gw], b = pe[EPN + gw];
    float norm = d_deg[a] * d_deg[b];
    if (sel == 0) {
        const float4* X = (const float4*)(d_gembs + (size_t)a * DD);
        float4* Ag = (float4*)(d_agg1 + (size_t)b * DD);
        float4 v = X[lane];
        v.x *= norm; v.y *= norm; v.z *= norm; v.w *= norm;
        atomicAdd(&Ag[lane], v);
        if (tid < G * DD / 4) {                 // self-loop, float4
            float di = d_deg[tid >> 5];
            float d2 = di * di;
            float4 s = ((const float4*)d_gembs)[tid];
            s.x *= d2; s.y *= d2; s.z *= d2; s.w *= d2;
            atomicAdd(&((float4*)d_agg1)[tid], s);
        }
    } else {
        const float4* X = (const float4*)(d_h + (size_t)a * 256);
        float4* Ag = (float4*)(d_agg2 + (size_t)b * 256);
#pragma unroll
        for (int q = 0; q < 2; q++) {
            float4 v = X[lane + 32 * q];
            v.x *= norm; v.y *= norm; v.z *= norm; v.w *= norm;
            atomicAdd(&Ag[lane + 32 * q], v);
        }
        if (tid < G * 256 / 4) {                // self-loop, float4
            float di = d_deg[tid >> 6];
            float d2 = di * di;
            float4 s = ((const float4*)d_h)[tid];
            s.x *= d2; s.y *= d2; s.z *= d2; s.w *= d2;
            atomicAdd(&((float4*)d_agg2)[tid], s);
        }
    }
}

// ---------------- z, zc, KL ----------------
__global__ void __launch_bounds__(256) k_z(const float* __restrict__ eps_,
                                           const float* __restrict__ emb) {
    int i = blockIdx.x * 256 + threadIdx.x;
    float m = d_mu[i], l = d_ls[i];
    int n = i >> 7, d = i & 127;
    float z = m + eps_[i] * expf(l);
    d_zc[(size_t)n * 256 + d] = emb[i];
    d_zc[(size_t)n * 256 + 128 + d] = z;
    float klt = 1.f + 2.f * l - m * m - expf(2.f * l);
    for (int off = 16; off; off >>= 1) klt += __shfl_down_sync(0xffffffffu, klt, off);
    __shared__ float sw[8];
    if ((threadIdx.x & 31) == 0) sw[threadIdx.x >> 5] = klt;
    __syncthreads();
    if (threadIdx.x == 0) {
        float s = 0;
        for (int j = 0; j < 8; j++) s += sw[j];
        atomicAdd(&d_sums[3], s);
    }
}

// ---------------- edge predictions + log sums ----------------
__global__ void __launch_bounds__(256) k_pred(const int* __restrict__ pe,
                                              const int* __restrict__ ne,
                                              float* __restrict__ out) {
    int gw = (blockIdx.x * 256 + threadIdx.x) >> 5;
    int lane = threadIdx.x & 31;
    int wib = threadIdx.x >> 5;
    bool isneg = gw >= EPN;
    int i = isneg ? gw - EPN : gw;
    const int* e = isneg ? ne : pe;
    int a = e[i], b = e[EPN + i];
    const float4* ra = (const float4*)(d_zl1 + (size_t)a * 256);
    const float4* rb = (const float4*)(d_zl2 + (size_t)b * 256);
    float s = 0.f;
#pragma unroll
    for (int q = 0; q < 2; q++) {
        float4 u = ra[lane + 32 * q], v = rb[lane + 32 * q];
        s += u.x * v.x + u.y * v.y + u.z * v.z + u.w * v.w;
    }
    for (int off = 16; off; off >>= 1) s += __shfl_down_sync(0xffffffffu, s, off);
    __shared__ float sl[8];
    if (lane == 0) {
        float p = 1.f / (1.f + expf(-s));
        out[2 + gw] = p;
        sl[wib] = isneg ? logf(1.f - p + 1e-15f) : logf(p + 1e-15f);
    }
    __syncthreads();
    if (threadIdx.x == 0) {
        float tt = 0;
        for (int j = 0; j < 8; j++) tt += sl[j];
        atomicAdd(isneg ? &d_sums[2] : &d_sums[1], tt);
    }
}

__global__ void k_final(float* __restrict__ out) {
    float rec = -(d_sums[1] / (float)EPN) - (d_sums[2] / (float)EPN);
    float kl = -0.5f * d_sums[3] / (float)G;
    out[0] = rec + kl / (float)G;
    out[1] = d_sums[0] / (float)G;
}

// ---------------- launch ----------------
extern "C" void kernel_launch(void* const* d_in, const int* in_sizes, int n_in,
                              void* d_out, int out_size) {
    const float* x   = (const float*)d_in[0];
    const int*   ei  = (const int*)d_in[1];
    const float* ew  = (const float*)d_in[2];
    const int*   pe  = (const int*)d_in[3];
    const int*   ne  = (const int*)d_in[4];
    const float* eps_= (const float*)d_in[5];
    const float* Wg  = (const float*)d_in[6];
    const float* bg  = (const float*)d_in[7];
    const float* Wf1 = (const float*)d_in[8];
    const float* bf1 = (const float*)d_in[9];
    const float* Wf2 = (const float*)d_in[10];
    const float* bf2 = (const float*)d_in[11];
    const float* Wc1 = (const float*)d_in[12];
    const float* bc1 = (const float*)d_in[13];
    const float* Wmu = (const float*)d_in[14];
    const float* bmu = (const float*)d_in[15];
    const float* Wls = (const float*)d_in[16];
    const float* bls = (const float*)d_in[17];
    const float* emb = (const float*)d_in[18];
    const float* Wl1 = (const float*)d_in[19];
    const float* bl1 = (const float*)d_in[20];
    const float* Wl2 = (const float*)d_in[21];
    const float* bl2 = (const float*)d_in[22];
    float* out = (float*)d_out;

    const int dyn_xw = 34816 + 16384 + 17408;   // 68608 -> 3 CTAs/SM
    cudaFuncSetAttribute(k_xwagg, cudaFuncAttributeMaxDynamicSharedMemorySize, dyn_xw);

    k_zero<<<1024, 256>>>(pe);
    k_prepw<<<234, 1024>>>(Wg, Wc1, Wmu, Wls, Wl1, Wl2, Wf1);
    k_deg<<<EPN / 256, 256>>>(pe);
    k_xwagg<<<G, 256, dyn_xw>>>(x, ei, ew, bg, bf1, Wf2, bf2);
    k_dinv<<<G / 256, 256>>>();
    k_scatter<<<EPN * 32 / 256, 256>>>(pe, 0);
    // h = relu(agg1 @ Wc1 + bc1)   [4096x128]@[128x256]
    k_mma<<<dim3(2, 32), 256>>>(1, 128, 2, 8192, 8192, bc1, bc1, 1, 1, 256, 1, 1);
    k_scatter<<<EPN * 32 / 256, 256>>>(pe, 1);
    // mu | ls   [4096x256]@[256x128] x2 in one launch
    k_mma<<<dim3(2, 32), 256>>>(2, 256, 1, 40960, 73728, bmu, bls, 2, 3, 128, 0, 2);
    k_z<<<G * DD / 256, 256>>>(eps_, emb);
    // zl1 | zl2   [4096x256]@[256x256] x2 in one launch
    k_mma<<<dim3(4, 32), 256>>>(3, 256, 2, 106496, 172032, bl1, bl2, 4, 5, 256, 0, 0);
    k_pred<<<2 * EPN * 32 / 256, 256>>>(pe, ne, out);
    k_final<<<1, 1>>>(out);
}

// round 11
// speedup vs baseline: 1.7925x; 1.0266x over previous
#include <cuda_runtime.h>
#include <cuda_bf16.h>
#include <math.h>
#include <stdint.h>

#define G   4096
#define NN  64
#define EE  256
#define FF  64
#define DD  128
#define EPN 32768

// ---------------- device scratch (static, no allocations) ----------------
__device__ float d_gembs[G * DD];
__device__ float d_deg[G];
__device__ float d_agg1[G * DD];
__device__ float d_h[G * 256];
__device__ float d_agg2[G * 256];
__device__ float d_mu[G * DD];
__device__ float d_ls[G * DD];
__device__ float d_zc[G * 256];
__device__ float d_zl1[G * 256];
__device__ float d_zl2[G * 256];
__device__ float d_sums[8];   // 0:pen 1:plog 2:nlog 3:kl
// transposed bf16 hi/lo weights [N][K]: Wg[0,8192) Wc1[8192,40960) Wmu[40960,73728)
// Wls[73728,106496) Wl1[106496,172032) Wl2[172032,237568) Wf1[237568,239616)
__device__ __nv_bfloat16 d_wth[239616];
__device__ __nv_bfloat16 d_wtl[239616];

// ---------------- helpers ----------------
__device__ __forceinline__ void mma_bf16(float* c, const uint32_t* a, const uint32_t* b) {
    asm volatile("mma.sync.aligned.m16n8k16.row.col.f32.bf16.bf16.f32 "
        "{%0,%1,%2,%3}, {%4,%5,%6,%7}, {%8,%9}, {%0,%1,%2,%3};"
        : "+f"(c[0]), "+f"(c[1]), "+f"(c[2]), "+f"(c[3])
        : "r"(a[0]), "r"(a[1]), "r"(a[2]), "r"(a[3]), "r"(b[0]), "r"(b[1]));
}
__device__ __forceinline__ void cvt_split2(float x, float y, uint32_t& hi, uint32_t& lo) {
    __nv_bfloat162 h = __floats2bfloat162_rn(x, y);
    float rx = x - __bfloat162float(h.x);
    float ry = y - __bfloat162float(h.y);
    __nv_bfloat162 l = __floats2bfloat162_rn(rx, ry);
    hi = *(uint32_t*)&h;
    lo = *(uint32_t*)&l;
}

// ---------------- zero scratch accumulators + graph-level degree ----------------
__global__ void k_zero(const int* __restrict__ pe) {
    int i = blockIdx.x * blockDim.x + threadIdx.x;
    int stride = gridDim.x * blockDim.x;
    for (int j = i; j < G * 256; j += stride) d_agg2[j] = 0.f;
    for (int j = i; j < G * DD; j += stride) d_agg1[j] = 0.f;
    for (int j = i; j < G; j += stride) d_deg[j] = 0.f;
    if (i < 8) d_sums[i] = 0.f;
}
__global__ void k_deg(const int* __restrict__ pe) {
    int i = blockIdx.x * blockDim.x + threadIdx.x;
    if (i < EPN) atomicAdd(&d_deg[pe[EPN + i]], 1.0f);
}
__global__ void k_dinv() {
    int i = blockIdx.x * blockDim.x + threadIdx.x;
    if (i < G) d_deg[i] = rsqrtf(d_deg[i] + 1.0f);
}

// ---------------- weight transpose + bf16 hi/lo split ----------------
__global__ void k_prepw(const float* __restrict__ W0, const float* __restrict__ W1,
                        const float* __restrict__ W2, const float* __restrict__ W3,
                        const float* __restrict__ W4, const float* __restrict__ W5,
                        const float* __restrict__ W6) {
    const float* Ws[7] = {W0, W1, W2, W3, W4, W5, W6};
    const int Ks[7] = {64, 128, 256, 256, 256, 256, 128};
    const int Ns[7] = {128, 256, 128, 128, 256, 256, 16};
    const int offs[8] = {0, 8192, 40960, 73728, 106496, 172032, 237568, 239616};
    int i = blockIdx.x * blockDim.x + threadIdx.x;
    if (i >= 239616) return;
    int s = 0;
    while (i >= offs[s + 1]) s++;
    int local = i - offs[s];
    int K = Ks[s], N = Ns[s];
    int n = local / K, k = local - n * K;
    float v = Ws[s][k * N + n];
    __nv_bfloat16 h = __float2bfloat16(v);
    d_wth[i] = h;
    d_wtl[i] = __float2bfloat16(v - __bfloat162float(h));
}

// ---------------- fully fused per-graph kernel (1 graph / block) ----------------
// xw^T = Wg^T @ x^T (HMMA split) -> dense-N GCN aggregation as HMMA GEMM
// -> h (smem bf16 hi/lo) -> g_emb (fragment-side) -> a1 head -> S -> penalty.
// dyn smem 71680 B -> 3 CTAs/SM. TST=72 => conflict-free (4r+q bank tiling).
#define TST 72    // stride for xw^T and N (bf16)
#define HST 136   // h row stride (bf16)
__global__ void __launch_bounds__(256, 3) k_xwagg(
    const float* __restrict__ x, const int* __restrict__ ei, const float* __restrict__ ew,
    const float* __restrict__ bg, const float* __restrict__ bf1,
    const float* __restrict__ Wf2, const float* __restrict__ bf2)
{
    extern __shared__ char dyn[];
    __nv_bfloat16* sXh = (__nv_bfloat16*)dyn;
    __nv_bfloat16* sXl = sXh + 64 * 40;
    __nv_bfloat16* sWh = sXl + 64 * 40;
    __nv_bfloat16* sWl = sWh + 128 * 40;
    __nv_bfloat16* sTh = (__nv_bfloat16*)dyn;       // [128][TST]
    __nv_bfloat16* sTl = sTh + 128 * TST;
    __nv_bfloat16* shh = (__nv_bfloat16*)dyn;       // [64][HST]
    __nv_bfloat16* shl = shh + 64 * HST;
    float* Nf = (float*)(dyn + 36864);              // [64][64] f32
    __nv_bfloat16* sNh = (__nv_bfloat16*)(dyn + 53248);
    __nv_bfloat16* sNl = sNh + 64 * TST;

    __shared__ float sdeg[NN], sdinv[NN], sdeg2[NN], sdv2[NN];
    __shared__ float sbias[DD];
    __shared__ float sS[NN * 2];
    __shared__ float sgpart[DD];
    __shared__ float sped[4];

    int t = threadIdx.x, lane = t & 31, warp = t >> 5;
    int g = blockIdx.x;
    const float* A = x + (size_t)g * NN * FF;

    // ---- phase 0/1: edges, degrees, dense N ----
    int e_es = ei[(size_t)g * 512 + t];
    int e_ed = ei[(size_t)g * 512 + 256 + t];
    float e_w = ew[(size_t)g * 256 + t];
    if (t < NN) { sdeg[t] = 0.f; sdeg2[t] = 0.f; }
    if (t < DD) { sbias[t] = bg[t]; sgpart[t] = 0.f; }
    if (t < 4) sped[t] = 0.f;
#pragma unroll
    for (int j = 0; j < 16; j++) Nf[t + j * 256] = 0.f;
    __syncthreads();
    atomicAdd(&sdeg[e_ed], e_w);
    atomicAdd(&sdeg2[e_es], e_w);
    __syncthreads();
    if (t < NN) {
        sdinv[t] = rsqrtf(sdeg[t] + 1.0f);
        float d2 = sdeg2[t];
        sdv2[t] = (d2 > 0.f) ? rsqrtf(fmaxf(d2, 1e-30f)) : 0.f;
    }
    __syncthreads();
    atomicAdd(&Nf[e_ed * 64 + e_es], sdinv[e_es] * e_w * sdinv[e_ed]);
    if (t < NN) atomicAdd(&Nf[t * 65], sdinv[t] * sdinv[t]);

    // ---- phase 2: HMMA xw^T = Wg^T @ x^T  (M=128 c, N=64 s, K=64 f) ----
    int warpC = warp >> 1, warpS = warp & 1;   // 4 x 2
    float acc[2][4][4];
#pragma unroll
    for (int mt = 0; mt < 2; mt++)
#pragma unroll
        for (int nt = 0; nt < 4; nt++)
#pragma unroll
            for (int j = 0; j < 4; j++) acc[mt][nt][j] = 0.f;

    int lar = t >> 2, lac = (t & 3) * 8;
    int lbr = t >> 1, lbc = (t & 1) * 16;
    for (int kc = 0; kc < 64; kc += 32) {
        {
            const float* Ar = A + (size_t)lar * 64 + kc + lac;
            float4 v0 = *(const float4*)Ar;
            float4 v1 = *(const float4*)(Ar + 4);
            uint32_t h0, l0, h1, l1, h2, l2, h3, l3;
            cvt_split2(v0.x, v0.y, h0, l0);
            cvt_split2(v0.z, v0.w, h1, l1);
            cvt_split2(v1.x, v1.y, h2, l2);
            cvt_split2(v1.z, v1.w, h3, l3);
            *(uint32_t*)&sXh[lar * 40 + lac]     = h0;
            *(uint32_t*)&sXh[lar * 40 + lac + 2] = h1;
            *(uint32_t*)&sXh[lar * 40 + lac + 4] = h2;
            *(uint32_t*)&sXh[lar * 40 + lac + 6] = h3;
            *(uint32_t*)&sXl[lar * 40 + lac]     = l0;
            *(uint32_t*)&sXl[lar * 40 + lac + 2] = l1;
            *(uint32_t*)&sXl[lar * 40 + lac + 4] = l2;
            *(uint32_t*)&sXl[lar * 40 + lac + 6] = l3;
        }
        {
            const __nv_bfloat16* bh = d_wth + (size_t)lbr * 64 + kc + lbc;
            const __nv_bfloat16* bl = d_wtl + (size_t)lbr * 64 + kc + lbc;
            *(uint4*)&sWh[lbr * 40 + lbc]     = *(const uint4*)bh;
            *(uint4*)&sWh[lbr * 40 + lbc + 8] = *(const uint4*)(bh + 8);
            *(uint4*)&sWl[lbr * 40 + lbc]     = *(const uint4*)bl;
            *(uint4*)&sWl[lbr * 40 + lbc + 8] = *(const uint4*)(bl + 8);
        }
        __syncthreads();
#pragma unroll
        for (int ks = 0; ks < 32; ks += 16) {
            int kb = ks + (lane & 3) * 2;
            uint32_t ah[2][4], al[2][4];
#pragma unroll
            for (int mt = 0; mt < 2; mt++) {
                int r = warpC * 32 + mt * 16 + (lane >> 2);
                ah[mt][0] = *(const uint32_t*)&sWh[r * 40 + kb];
                ah[mt][1] = *(const uint32_t*)&sWh[(r + 8) * 40 + kb];
                ah[mt][2] = *(const uint32_t*)&sWh[r * 40 + kb + 8];
                ah[mt][3] = *(const uint32_t*)&sWh[(r + 8) * 40 + kb + 8];
                al[mt][0] = *(const uint32_t*)&sWl[r * 40 + kb];
                al[mt][1] = *(const uint32_t*)&sWl[(r + 8) * 40 + kb];
                al[mt][2] = *(const uint32_t*)&sWl[r * 40 + kb + 8];
                al[mt][3] = *(const uint32_t*)&sWl[(r + 8) * 40 + kb + 8];
            }
            uint32_t bhf[4][2], blf[4][2];
#pragma unroll
            for (int nt = 0; nt < 4; nt++) {
                int r = warpS * 32 + nt * 8 + (lane >> 2);
                bhf[nt][0] = *(const uint32_t*)&sXh[r * 40 + kb];
                bhf[nt][1] = *(const uint32_t*)&sXh[r * 40 + kb + 8];
                blf[nt][0] = *(const uint32_t*)&sXl[r * 40 + kb];
                blf[nt][1] = *(const uint32_t*)&sXl[r * 40 + kb + 8];
            }
#pragma unroll
            for (int mt = 0; mt < 2; mt++)
#pragma unroll
                for (int nt = 0; nt < 4; nt++) {
                    mma_bf16(acc[mt][nt], ah[mt], bhf[nt]);
                    mma_bf16(acc[mt][nt], ah[mt], blf[nt]);
                    mma_bf16(acc[mt][nt], al[mt], bhf[nt]);
                }
        }
        __syncthreads();
    }

    // ---- phase 2b: store xw^T (bf16 split) + convert N to bf16 split ----
#pragma unroll
    for (int mt = 0; mt < 2; mt++) {
        int c0 = warpC * 32 + mt * 16 + (lane >> 2);
#pragma unroll
        for (int nt = 0; nt < 4; nt++) {
            int s0 = warpS * 32 + nt * 8 + (lane & 3) * 2;
            uint32_t hA, lA, hB, lB;
            cvt_split2(acc[mt][nt][0], acc[mt][nt][1], hA, lA);
            cvt_split2(acc[mt][nt][2], acc[mt][nt][3], hB, lB);
            *(uint32_t*)&sTh[c0 * TST + s0]       = hA;
            *(uint32_t*)&sTl[c0 * TST + s0]       = lA;
            *(uint32_t*)&sTh[(c0 + 8) * TST + s0] = hB;
            *(uint32_t*)&sTl[(c0 + 8) * TST + s0] = lB;
        }
    }
#pragma unroll
    for (int j = 0; j < 16; j++) {
        int i = t + j * 256;
        int row = i >> 6, col = i & 63;
        float v = Nf[i];
        __nv_bfloat16 hb = __float2bfloat16(v);
        sNh[row * TST + col] = hb;
        sNl[row * TST + col] = __float2bfloat16(v - __bfloat162float(hb));
    }
    __syncthreads();

    // ---- phase 3: HMMA h = N @ xw  (M=64 n, N=128 c, K=64 s) ----
    int warpM = warp >> 2, warpN = warp & 3;
    float acc2[2][4][4];
#pragma unroll
    for (int mt = 0; mt < 2; mt++)
#pragma unroll
        for (int nt = 0; nt < 4; nt++)
#pragma unroll
            for (int j = 0; j < 4; j++) acc2[mt][nt][j] = 0.f;
#pragma unroll
    for (int ks = 0; ks < 4; ks++) {
        int kb = ks * 16 + (lane & 3) * 2;
        uint32_t ah[2][4], al[2][4];
#pragma unroll
        for (int mt = 0; mt < 2; mt++) {
            int r = warpM * 32 + mt * 16 + (lane >> 2);
            ah[mt][0] = *(const uint32_t*)&sNh[r * TST + kb];
            ah[mt][1] = *(const uint32_t*)&sNh[(r + 8) * TST + kb];
            ah[mt][2] = *(const uint32_t*)&sNh[r * TST + kb + 8];
            ah[mt][3] = *(const uint32_t*)&sNh[(r + 8) * TST + kb + 8];
            al[mt][0] = *(const uint32_t*)&sNl[r * TST + kb];
            al[mt][1] = *(const uint32_t*)&sNl[(r + 8) * TST + kb];
            al[mt][2] = *(const uint32_t*)&sNl[r * TST + kb + 8];
            al[mt][3] = *(const uint32_t*)&sNl[(r + 8) * TST + kb + 8];
        }
        uint32_t bhf[4][2], blf[4][2];
#pragma unroll
        for (int nt = 0; nt < 4; nt++) {
            int r = warpN * 32 + nt * 8 + (lane >> 2);
            bhf[nt][0] = *(const uint32_t*)&sTh[r * TST + kb];
            bhf[nt][1] = *(const uint32_t*)&sTh[r * TST + kb + 8];
            blf[nt][0] = *(const uint32_t*)&sTl[r * TST + kb];
            blf[nt][1] = *(const uint32_t*)&sTl[r * TST + kb + 8];
        }
#pragma unroll
        for (int mt = 0; mt < 2; mt++)
#pragma unroll
            for (int nt = 0; nt < 4; nt++) {
                mma_bf16(acc2[mt][nt], ah[mt], bhf[nt]);
                mma_bf16(acc2[mt][nt], ah[mt], blf[nt]);
                mma_bf16(acc2[mt][nt], al[mt], bhf[nt]);
            }
    }
    __syncthreads();   // all xw^T reads done before h overwrites R0

    // ---- phase 3b: g_emb partials from fragments + h epilogue -> smem ----
#pragma unroll
    for (int nt = 0; nt < 4; nt++) {
        float v0 = acc2[0][nt][0] + acc2[0][nt][2] + acc2[1][nt][0] + acc2[1][nt][2];
        float v1 = acc2[0][nt][1] + acc2[0][nt][3] + acc2[1][nt][1] + acc2[1][nt][3];
#pragma unroll
        for (int off = 4; off <= 16; off <<= 1) {
            v0 += __shfl_xor_sync(0xffffffffu, v0, off);
            v1 += __shfl_xor_sync(0xffffffffu, v1, off);
        }
        if ((lane >> 2) == 0) {   // lanes 0..3 hold warp-column sums
            int c0 = warpN * 32 + nt * 8 + (lane & 3) * 2;
            atomicAdd(&sgpart[c0], v0);
            atomicAdd(&sgpart[c0 + 1], v1);
        }
    }
#pragma unroll
    for (int mt = 0; mt < 2; mt++) {
        int n0 = warpM * 32 + mt * 16 + (lane >> 2);
#pragma unroll
        for (int nt = 0; nt < 4; nt++) {
            int c0 = warpN * 32 + nt * 8 + (lane & 3) * 2;
            float b0 = sbias[c0], b1 = sbias[c0 + 1];
            uint32_t hA, lA, hB, lB;
            cvt_split2(acc2[mt][nt][0] + b0, acc2[mt][nt][1] + b1, hA, lA);
            cvt_split2(acc2[mt][nt][2] + b0, acc2[mt][nt][3] + b1, hB, lB);
            *(uint32_t*)&shh[n0 * HST + c0]       = hA;
            *(uint32_t*)&shl[n0 * HST + c0]       = lA;
            *(uint32_t*)&shh[(n0 + 8) * HST + c0] = hB;
            *(uint32_t*)&shl[(n0 + 8) * HST + c0] = lB;
        }
    }
    __syncthreads();

    // ---- phase 3c: g_emb = 0.5*(sum + 64*bias) ----
    if (t < DD)
        d_gembs[(size_t)g * 128 + t] = 0.5f * (sgpart[t] + 64.f * sbias[t]);

    // ---- phase 4: a1 = tanh(h @ Wf1 + bf1), logits, softmax -> sS (warps 0-3) ----
    if (warp < 4) {
        int r = lane >> 2, kb2 = (lane & 3) * 2;
        int rowW = warp * 16;
        float a16[2][4];
#pragma unroll
        for (int nt = 0; nt < 2; nt++)
#pragma unroll
            for (int j = 0; j < 4; j++) a16[nt][j] = 0.f;
        const __nv_bfloat16* Bh = d_wth + 237568;
        const __nv_bfloat16* Bl = d_wtl + 237568;
#pragma unroll
        for (int ks = 0; ks < 8; ks++) {
            int k0 = ks * 16 + kb2;
            uint32_t ah[4], al[4];
            ah[0] = *(const uint32_t*)&shh[(rowW + r) * HST + k0];
            ah[1] = *(const uint32_t*)&shh[(rowW + r + 8) * HST + k0];
            ah[2] = *(const uint32_t*)&shh[(rowW + r) * HST + k0 + 8];
            ah[3] = *(const uint32_t*)&shh[(rowW + r + 8) * HST + k0 + 8];
            al[0] = *(const uint32_t*)&shl[(rowW + r) * HST + k0];
            al[1] = *(const uint32_t*)&shl[(rowW + r + 8) * HST + k0];
            al[2] = *(const uint32_t*)&shl[(rowW + r) * HST + k0 + 8];
            al[3] = *(const uint32_t*)&shl[(rowW + r + 8) * HST + k0 + 8];
#pragma unroll
            for (int nt = 0; nt < 2; nt++) {
                int n = nt * 8 + r;
                uint32_t bh[2], bl[2];
                bh[0] = *(const uint32_t*)(Bh + n * 128 + k0);
                bh[1] = *(const uint32_t*)(Bh + n * 128 + k0 + 8);
                bl[0] = *(const uint32_t*)(Bl + n * 128 + k0);
                bl[1] = *(const uint32_t*)(Bl + n * 128 + k0 + 8);
                mma_bf16(a16[nt], ah, bh);
                mma_bf16(a16[nt], ah, bl);
                mma_bf16(a16[nt], al, bh);
            }
        }
        float l0a = 0.f, l1a = 0.f, l0b = 0.f, l1b = 0.f;
#pragma unroll
        for (int nt = 0; nt < 2; nt++) {
            int c0 = nt * 8 + (lane & 3) * 2;
            float b0 = bf1[c0], b1 = bf1[c0 + 1];
            float w00 = Wf2[c0 * 2], w01 = Wf2[c0 * 2 + 1];
            float w10 = Wf2[c0 * 2 + 2], w11 = Wf2[c0 * 2 + 3];
            float t0 = tanhf(a16[nt][0] + b0), t1 = tanhf(a16[nt][1] + b1);
            float t2 = tanhf(a16[nt][2] + b0), t3 = tanhf(a16[nt][3] + b1);
            l0a = fmaf(t0, w00, fmaf(t1, w10, l0a));
            l1a = fmaf(t0, w01, fmaf(t1, w11, l1a));
            l0b = fmaf(t2, w00, fmaf(t3, w10, l0b));
            l1b = fmaf(t2, w01, fmaf(t3, w11, l1b));
        }
#pragma unroll
        for (int off = 1; off <= 2; off <<= 1) {
            l0a += __shfl_xor_sync(0xffffffffu, l0a, off);
            l1a += __shfl_xor_sync(0xffffffffu, l1a, off);
            l0b += __shfl_xor_sync(0xffffffffu, l0b, off);
            l1b += __shfl_xor_sync(0xffffffffu, l1b, off);
        }
        if ((lane & 3) == 0) {
            float b20 = bf2[0], b21 = bf2[1];
            float la0 = l0a + b20, la1 = l1a + b21;
            float m = fmaxf(la0, la1);
            float e0 = expf(la0 - m), e1 = expf(la1 - m);
            float inv = 1.f / (e0 + e1);
            sS[(rowW + r) * 2]     = e0 * inv;
            sS[(rowW + r) * 2 + 1] = e1 * inv;
            float lb0 = l0b + b20, lb1 = l1b + b21;
            float m2 = fmaxf(lb0, lb1);
            float f0 = expf(lb0 - m2), f1 = expf(lb1 - m2);
            float inv2 = 1.f / (f0 + f1);
            sS[(rowW + r + 8) * 2]     = f0 * inv2;
            sS[(rowW + r + 8) * 2 + 1] = f1 * inv2;
        }
    }
    __syncthreads();

    // ---- phase 5: Laplacian penalty ----
    {
        float p[4] = {0, 0, 0, 0};
        if (t < NN) {
            float s0 = sS[t * 2], s1 = sS[t * 2 + 1];
            p[0] = s0 * s0; p[1] = s0 * s1; p[2] = s1 * s0; p[3] = s1 * s1;
        }
        {
            float lw = -sdv2[e_es] * e_w * sdv2[e_ed];
            float q0 = sS[e_es * 2], q1 = sS[e_es * 2 + 1];
            float r0 = sS[e_ed * 2], r1 = sS[e_ed * 2 + 1];
            p[0] = fmaf(lw, q0 * r0, p[0]);
            p[1] = fmaf(lw, q0 * r1, p[1]);
            p[2] = fmaf(lw, q1 * r0, p[2]);
            p[3] = fmaf(lw, q1 * r1, p[3]);
        }
#pragma unroll
        for (int off = 16; off; off >>= 1)
#pragma unroll
            for (int j = 0; j < 4; j++)
                p[j] += __shfl_down_sync(0xffffffffu, p[j], off);
        if (lane == 0) {
#pragma unroll
            for (int j = 0; j < 4; j++) atomicAdd(&sped[j], p[j]);
        }
    }
    __syncthreads();
    if (t == 0) {
        float A00 = sped[0], A01 = sped[1], A10 = sped[2], A11 = sped[3];
        float r0 = fmaxf(fabsf(A00) + fabsf(A01), 1e-12f);
        float r1 = fmaxf(fabsf(A10) + fabsf(A11), 1e-12f);
        float dd0 = A00 / r0 - 1.f, dd1 = A11 / r1 - 1.f;
        atomicAdd(&d_sums[0], 0.5f * (dd0 * dd0 + dd1 * dd1));
    }
}

// ---------------- dual-output mma.sync GEMM: C = act(A @ W + b) ----------------
__global__ void __launch_bounds__(256) k_mma(
    int selA, int K, int nx0,
    int wtoff0, int wtoff1,
    const float* __restrict__ b0v, const float* __restrict__ b1v,
    int selC0, int selC1, int Cs, int act0, int act1)
{
    __shared__ __nv_bfloat16 sAh[128][40];
    __shared__ __nv_bfloat16 sAl[128][40];
    __shared__ __nv_bfloat16 sBh[128][40];
    __shared__ __nv_bfloat16 sBl[128][40];
    __shared__ float sbias[128];

    int t = threadIdx.x;
    const float* A = (selA == 1) ? d_agg1 : (selA == 2) ? d_agg2 : d_zc;
    int bx = blockIdx.x;
    int hsel = bx >= nx0;
    int colBase = (bx - (hsel ? nx0 : 0)) * 128;
    int wtoff = hsel ? wtoff1 : wtoff0;
    const float* bias = hsel ? b1v : b0v;
    int act = hsel ? act1 : act0;
    int selC = hsel ? selC1 : selC0;
    float* C = (selC == 1) ? d_h : (selC == 2) ? d_mu
             : (selC == 3) ? d_ls : (selC == 4) ? d_zl1 : d_zl2;
    int rowBase = blockIdx.y * 128;
    if (t < 128) sbias[t] = bias[colBase + t];

    int lane = t & 31, warp = t >> 5;
    int warpM = warp >> 2, warpN = warp & 3;

    float acc[4][4][4];
#pragma unroll
    for (int mt = 0; mt < 4; mt++)
#pragma unroll
        for (int nt = 0; nt < 4; nt++)
#pragma unroll
            for (int j = 0; j < 4; j++) acc[mt][nt][j] = 0.f;

    int ldr = t >> 1, ldc = (t & 1) * 16;

    for (int kc = 0; kc < K; kc += 32) {
        const float* Ar = A + (size_t)(rowBase + ldr) * K + kc + ldc;
#pragma unroll
        for (int j = 0; j < 4; j++) {
            float4 v = *(const float4*)(Ar + j * 4);
            uint32_t h0, l0, h1, l1;
            cvt_split2(v.x, v.y, h0, l0);
            cvt_split2(v.z, v.w, h1, l1);
            *(uint32_t*)&sAh[ldr][ldc + j * 4]     = h0;
            *(uint32_t*)&sAh[ldr][ldc + j * 4 + 2] = h1;
            *(uint32_t*)&sAl[ldr][ldc + j * 4]     = l0;
            *(uint32_t*)&sAl[ldr][ldc + j * 4 + 2] = l1;
        }
        {
            const __nv_bfloat16* bh = d_wth + wtoff + (size_t)(colBase + ldr) * K + kc + ldc;
            const __nv_bfloat16* bl = d_wtl + wtoff + (size_t)(colBase + ldr) * K + kc + ldc;
            *(uint4*)&sBh[ldr][ldc]     = *(const uint4*)bh;
            *(uint4*)&sBh[ldr][ldc + 8] = *(const uint4*)(bh + 8);
            *(uint4*)&sBl[ldr][ldc]     = *(const uint4*)bl;
            *(uint4*)&sBl[ldr][ldc + 8] = *(const uint4*)(bl + 8);
        }
        __syncthreads();
#pragma unroll
        for (int ks = 0; ks < 32; ks += 16) {
            int kb = ks + (lane & 3) * 2;
            int ar = warpM * 64 + (lane >> 2);
            uint32_t ah[4][4], al[4][4];
#pragma unroll
            for (int mt = 0; mt < 4; mt++) {
                int r = ar + mt * 16;
                ah[mt][0] = *(const uint32_t*)&sAh[r][kb];
                ah[mt][1] = *(const uint32_t*)&sAh[r + 8][kb];
                ah[mt][2] = *(const uint32_t*)&sAh[r][kb + 8];
                ah[mt][3] = *(const uint32_t*)&sAh[r + 8][kb + 8];
                al[mt][0] = *(const uint32_t*)&sAl[r][kb];
                al[mt][1] = *(const uint32_t*)&sAl[r + 8][kb];
                al[mt][2] = *(const uint32_t*)&sAl[r][kb + 8];
                al[mt][3] = *(const uint32_t*)&sAl[r + 8][kb + 8];
            }
            uint32_t bhf[4][2], blf[4][2];
#pragma unroll
            for (int nt = 0; nt < 4; nt++) {
                int r = warpN * 32 + nt * 8 + (lane >> 2);
                bhf[nt][0] = *(const uint32_t*)&sBh[r][kb];
                bhf[nt][1] = *(const uint32_t*)&sBh[r][kb + 8];
                blf[nt][0] = *(const uint32_t*)&sBl[r][kb];
                blf[nt][1] = *(const uint32_t*)&sBl[r][kb + 8];
            }
#pragma unroll
            for (int mt = 0; mt < 4; mt++)
#pragma unroll
                for (int nt = 0; nt < 4; nt++) {
                    mma_bf16(acc[mt][nt], ah[mt], bhf[nt]);
                    mma_bf16(acc[mt][nt], ah[mt], blf[nt]);
                    mma_bf16(acc[mt][nt], al[mt], bhf[nt]);
                }
        }
        __syncthreads();
    }

#pragma unroll
    for (int mt = 0; mt < 4; mt++) {
        int r0 = rowBase + warpM * 64 + mt * 16 + (lane >> 2);
#pragma unroll
        for (int nt = 0; nt < 4; nt++) {
            int cl = warpN * 32 + nt * 8 + (lane & 3) * 2;
            float b0 = sbias[cl], b1 = sbias[cl + 1];
            float2 v0, v1;
            v0.x = acc[mt][nt][0] + b0; v0.y = acc[mt][nt][1] + b1;
            v1.x = acc[mt][nt][2] + b0; v1.y = acc[mt][nt][3] + b1;
            if (act == 1) {
                v0.x = fmaxf(v0.x, 0.f); v0.y = fmaxf(v0.y, 0.f);
                v1.x = fmaxf(v1.x, 0.f); v1.y = fmaxf(v1.y, 0.f);
            } else if (act == 2) {
                v0.x = fminf(v0.x, 10.f); v0.y = fminf(v0.y, 10.f);
                v1.x = fminf(v1.x, 10.f); v1.y = fminf(v1.y, 10.f);
            }
            *(float2*)&C[(size_t)r0 * Cs + colBase + cl] = v0;
            *(float2*)&C[(size_t)(r0 + 8) * Cs + colBase + cl] = v1;
        }
    }
}

// ---------------- scatter (warp/edge), float4 vector atomics ----------------
__global__ void __launch_bounds__(256) k_scatter(const int* __restrict__ pe, int sel) {
    int tid = blockIdx.x * 256 + threadIdx.x;   // 0 .. EPN*32-1
    int gw = tid >> 5, lane = tid & 31;
    int a = pe[gw], b = pe[EPN + gw];
    float norm = d_deg[a] * d_deg[b];
    if (sel == 0) {
        const float4* X = (const float4*)(d_gembs + (size_t)a * DD);
        float4* Ag = (float4*)(d_agg1 + (size_t)b * DD);
        float4 v = X[lane];
        v.x *= norm; v.y *= norm; v.z *= norm; v.w *= norm;
        atomicAdd(&Ag[lane], v);
        if (tid < G * DD / 4) {
            float di = d_deg[tid >> 5];
            float d2 = di * di;
            float4 s = ((const float4*)d_gembs)[tid];
            s.x *= d2; s.y *= d2; s.z *= d2; s.w *= d2;
            atomicAdd(&((float4*)d_agg1)[tid], s);
        }
    } else {
        const float4* X = (const float4*)(d_h + (size_t)a * 256);
        float4* Ag = (float4*)(d_agg2 + (size_t)b * 256);
#pragma unroll
        for (int q = 0; q < 2; q++) {
            float4 v = X[lane + 32 * q];
            v.x *= norm; v.y *= norm; v.z *= norm; v.w *= norm;
            atomicAdd(&Ag[lane + 32 * q], v);
        }
        if (tid < G * 256 / 4) {
            float di = d_deg[tid >> 6];
            float d2 = di * di;
            float4 s = ((const float4*)d_h)[tid];
            s.x *= d2; s.y *= d2; s.z *= d2; s.w *= d2;
            atomicAdd(&((float4*)d_agg2)[tid], s);
        }
    }
}

// ---------------- z, zc, KL ----------------
__global__ void __launch_bounds__(256) k_z(const float* __restrict__ eps_,
                                           const float* __restrict__ emb) {
    int i = blockIdx.x * 256 + threadIdx.x;
    float m = d_mu[i], l = d_ls[i];
    int n = i >> 7, d = i & 127;
    float z = m + eps_[i] * expf(l);
    d_zc[(size_t)n * 256 + d] = emb[i];
    d_zc[(size_t)n * 256 + 128 + d] = z;
    float klt = 1.f + 2.f * l - m * m - expf(2.f * l);
    for (int off = 16; off; off >>= 1) klt += __shfl_down_sync(0xffffffffu, klt, off);
    __shared__ float sw[8];
    if ((threadIdx.x & 31) == 0) sw[threadIdx.x >> 5] = klt;
    __syncthreads();
    if (threadIdx.x == 0) {
        float s = 0;
        for (int j = 0; j < 8; j++) s += sw[j];
        atomicAdd(&d_sums[3], s);
    }
}

// ---------------- edge predictions + log sums ----------------
__global__ void __launch_bounds__(256) k_pred(const int* __restrict__ pe,
                                              const int* __restrict__ ne,
                                              float* __restrict__ out) {
    int gw = (blockIdx.x * 256 + threadIdx.x) >> 5;
    int lane = threadIdx.x & 31;
    int wib = threadIdx.x >> 5;
    bool isneg = gw >= EPN;
    int i = isneg ? gw - EPN : gw;
    const int* e = isneg ? ne : pe;
    int a = e[i], b = e[EPN + i];
    const float4* ra = (const float4*)(d_zl1 + (size_t)a * 256);
    const float4* rb = (const float4*)(d_zl2 + (size_t)b * 256);
    float s = 0.f;
#pragma unroll
    for (int q = 0; q < 2; q++) {
        float4 u = ra[lane + 32 * q], v = rb[lane + 32 * q];
        s += u.x * v.x + u.y * v.y + u.z * v.z + u.w * v.w;
    }
    for (int off = 16; off; off >>= 1) s += __shfl_down_sync(0xffffffffu, s, off);
    __shared__ float sl[8];
    if (lane == 0) {
        float p = 1.f / (1.f + expf(-s));
        out[2 + gw] = p;
        sl[wib] = isneg ? logf(1.f - p + 1e-15f) : logf(p + 1e-15f);
    }
    __syncthreads();
    if (threadIdx.x == 0) {
        float tt = 0;
        for (int j = 0; j < 8; j++) tt += sl[j];
        atomicAdd(isneg ? &d_sums[2] : &d_sums[1], tt);
    }
}

__global__ void k_final(float* __restrict__ out) {
    float rec = -(d_sums[1] / (float)EPN) - (d_sums[2] / (float)EPN);
    float kl = -0.5f * d_sums[3] / (float)G;
    out[0] = rec + kl / (float)G;
    out[1] = d_sums[0] / (float)G;
}

// ---------------- launch ----------------
extern "C" void kernel_launch(void* const* d_in, const int* in_sizes, int n_in,
                              void* d_out, int out_size) {
    const float* x   = (const float*)d_in[0];
    const int*   ei  = (const int*)d_in[1];
    const float* ew  = (const float*)d_in[2];
    const int*   pe  = (const int*)d_in[3];
    const int*   ne  = (const int*)d_in[4];
    const float* eps_= (const float*)d_in[5];
    const float* Wg  = (const float*)d_in[6];
    const float* bg  = (const float*)d_in[7];
    const float* Wf1 = (const float*)d_in[8];
    const float* bf1 = (const float*)d_in[9];
    const float* Wf2 = (const float*)d_in[10];
    const float* bf2 = (const float*)d_in[11];
    const float* Wc1 = (const float*)d_in[12];
    const float* bc1 = (const float*)d_in[13];
    const float* Wmu = (const float*)d_in[14];
    const float* bmu = (const float*)d_in[15];
    const float* Wls = (const float*)d_in[16];
    const float* bls = (const float*)d_in[17];
    const float* emb = (const float*)d_in[18];
    const float* Wl1 = (const float*)d_in[19];
    const float* bl1 = (const float*)d_in[20];
    const float* Wl2 = (const float*)d_in[21];
    const float* bl2 = (const float*)d_in[22];
    float* out = (float*)d_out;

    const int dyn_xw = 36864 + 16384 + 18432;   // 71680 -> 3 CTAs/SM
    cudaFuncSetAttribute(k_xwagg, cudaFuncAttributeMaxDynamicSharedMemorySize, dyn_xw);

    k_zero<<<1024, 256>>>(pe);
    k_prepw<<<234, 1024>>>(Wg, Wc1, Wmu, Wls, Wl1, Wl2, Wf1);
    k_deg<<<EPN / 256, 256>>>(pe);
    k_xwagg<<<G, 256, dyn_xw>>>(x, ei, ew, bg, bf1, Wf2, bf2);
    k_dinv<<<G / 256, 256>>>();
    k_scatter<<<EPN * 32 / 256, 256>>>(pe, 0);
    // h = relu(agg1 @ Wc1 + bc1)   [4096x128]@[128x256]
    k_mma<<<dim3(2, 32), 256>>>(1, 128, 2, 8192, 8192, bc1, bc1, 1, 1, 256, 1, 1);
    k_scatter<<<EPN * 32 / 256, 256>>>(pe, 1);
    // mu | ls   [4096x256]@[256x128] x2 in one launch
    k_mma<<<dim3(2, 32), 256>>>(2, 256, 1, 40960, 73728, bmu, bls, 2, 3, 128, 0, 2);
    k_z<<<G * DD / 256, 256>>>(eps_, emb);
    // zl1 | zl2   [4096x256]@[256x256] x2 in one launch
    k_mma<<<dim3(4, 32), 256>>>(3, 256, 2, 106496, 172032, bl1, bl2, 4, 5, 256, 0, 0);
    k_pred<<<2 * EPN * 32 / 256, 256>>>(pe, ne, out);
    k_final<<<1, 1>>>(out);
}

// round 12
// speedup vs baseline: 1.8940x; 1.0566x over previous
#include <cuda_runtime.h>
#include <cuda_bf16.h>
#include <math.h>
#include <stdint.h>

#define G   4096
#define NN  64
#define EE  256
#define FF  64
#define DD  128
#define EPN 32768

// ---------------- device scratch (static, no allocations) ----------------
__device__ float d_gembs[G * DD];
__device__ float d_deg[G];
__device__ float d_agg1[G * DD];
__device__ float d_h[G * 256];
__device__ float d_agg2[G * 256];
__device__ float d_mu[G * DD];
__device__ float d_ls[G * DD];
__device__ float d_zc[G * 256];
__device__ float d_zl1[G * 256];
__device__ float d_zl2[G * 256];
__device__ float d_sums[8];   // 0:pen 1:plog 2:nlog 3:kl
// transposed bf16 hi/lo weights [N][K]: Wg[0,8192) Wc1[8192,40960) Wmu[40960,73728)
// Wls[73728,106496) Wl1[106496,172032) Wl2[172032,237568) Wf1[237568,239616)
__device__ __nv_bfloat16 d_wth[239616];
__device__ __nv_bfloat16 d_wtl[239616];

// ---------------- helpers ----------------
__device__ __forceinline__ void mma_bf16(float* c, const uint32_t* a, const uint32_t* b) {
    asm volatile("mma.sync.aligned.m16n8k16.row.col.f32.bf16.bf16.f32 "
        "{%0,%1,%2,%3}, {%4,%5,%6,%7}, {%8,%9}, {%0,%1,%2,%3};"
        : "+f"(c[0]), "+f"(c[1]), "+f"(c[2]), "+f"(c[3])
        : "r"(a[0]), "r"(a[1]), "r"(a[2]), "r"(a[3]), "r"(b[0]), "r"(b[1]));
}
__device__ __forceinline__ void cvt_split2(float x, float y, uint32_t& hi, uint32_t& lo) {
    __nv_bfloat162 h = __floats2bfloat162_rn(x, y);
    float rx = x - __bfloat162float(h.x);
    float ry = y - __bfloat162float(h.y);
    __nv_bfloat162 l = __floats2bfloat162_rn(rx, ry);
    hi = *(uint32_t*)&h;
    lo = *(uint32_t*)&l;
}

// ---------------- zero scratch accumulators + graph-level degree ----------------
__global__ void k_zero(const int* __restrict__ pe) {
    int i = blockIdx.x * blockDim.x + threadIdx.x;
    int stride = gridDim.x * blockDim.x;
    for (int j = i; j < G * 256; j += stride) d_agg2[j] = 0.f;
    for (int j = i; j < G * DD; j += stride) d_agg1[j] = 0.f;
    for (int j = i; j < G; j += stride) d_deg[j] = 0.f;
    if (i < 8) d_sums[i] = 0.f;
}
__global__ void k_deg(const int* __restrict__ pe) {
    int i = blockIdx.x * blockDim.x + threadIdx.x;
    if (i < EPN) atomicAdd(&d_deg[pe[EPN + i]], 1.0f);
}
__global__ void k_dinv() {
    int i = blockIdx.x * blockDim.x + threadIdx.x;
    if (i < G) d_deg[i] = rsqrtf(d_deg[i] + 1.0f);
}

// ---------------- weight transpose + bf16 hi/lo split ----------------
__global__ void k_prepw(const float* __restrict__ W0, const float* __restrict__ W1,
                        const float* __restrict__ W2, const float* __restrict__ W3,
                        const float* __restrict__ W4, const float* __restrict__ W5,
                        const float* __restrict__ W6) {
    const float* Ws[7] = {W0, W1, W2, W3, W4, W5, W6};
    const int Ks[7] = {64, 128, 256, 256, 256, 256, 128};
    const int Ns[7] = {128, 256, 128, 128, 256, 256, 16};
    const int offs[8] = {0, 8192, 40960, 73728, 106496, 172032, 237568, 239616};
    int i = blockIdx.x * blockDim.x + threadIdx.x;
    if (i >= 239616) return;
    int s = 0;
    while (i >= offs[s + 1]) s++;
    int local = i - offs[s];
    int K = Ks[s], N = Ns[s];
    int n = local / K, k = local - n * K;
    float v = Ws[s][k * N + n];
    __nv_bfloat16 h = __float2bfloat16(v);
    d_wth[i] = h;
    d_wtl[i] = __float2bfloat16(v - __bfloat162float(h));
}

// ---------------- fully fused per-graph kernel (1 graph / block) ----------------
// Reassociated: Nx = N @ x (64x64x64 HMMA) then h = Nx @ Wg (64x128x64 HMMA).
// Then g_emb (fragment-side), a1 head, S softmax, Laplacian penalty.
// dyn smem 53248 B -> 3 CTAs/SM. All fragment LDS conflict-free.
#define XTS 72    // x^T stride (bf16)
#define TST 72    // stride for N and Nx (bf16)
#define HST 136   // h row stride (bf16)
__global__ void __launch_bounds__(256, 3) k_xwagg(
    const float* __restrict__ x, const int* __restrict__ ei, const float* __restrict__ ew,
    const float* __restrict__ bg, const float* __restrict__ bf1,
    const float* __restrict__ Wf2, const float* __restrict__ bf2)
{
    extern __shared__ char dyn[];
    __nv_bfloat16* sXTh = (__nv_bfloat16*)dyn;          // [64 f][XTS] (x transposed)
    __nv_bfloat16* sXTl = sXTh + 64 * XTS;              // [0, 18432)
    float* Nf = (float*)(dyn + 18432);                  // [64][64] f32, [18432, 34816)
    __nv_bfloat16* sNbh = (__nv_bfloat16*)(dyn + 34816);// [64][TST], [34816, 53248)
    __nv_bfloat16* sNbl = sNbh + 64 * TST;
    __nv_bfloat16* sNxh = (__nv_bfloat16*)dyn;          // [64 n][TST] Nx (aliases xT)
    __nv_bfloat16* sNxl = sNxh + 64 * TST;
    __nv_bfloat16* sWh = (__nv_bfloat16*)(dyn + 18432); // [128 c][40] chunk (aliases Nf)
    __nv_bfloat16* sWl = sWh + 128 * 40;
    __nv_bfloat16* shh = (__nv_bfloat16*)dyn;           // [64][HST] h (after GEMM2)
    __nv_bfloat16* shl = shh + 64 * HST;

    __shared__ float sdeg[NN], sdinv[NN], sdeg2[NN], sdv2[NN];
    __shared__ float sbias[DD];
    __shared__ float sS[NN * 2];
    __shared__ float sgpart[DD];
    __shared__ float sped[4];

    int t = threadIdx.x, lane = t & 31, warp = t >> 5;
    int g = blockIdx.x;
    const float* A = x + (size_t)g * NN * FF;

    // ---- phase 0: edges, init ----
    int e_es = ei[(size_t)g * 512 + t];
    int e_ed = ei[(size_t)g * 512 + 256 + t];
    float e_w = ew[(size_t)g * 256 + t];
    if (t < NN) { sdeg[t] = 0.f; sdeg2[t] = 0.f; }
    if (t < DD) { sbias[t] = bg[t]; sgpart[t] = 0.f; }
    if (t < 4) sped[t] = 0.f;
#pragma unroll
    for (int j = 0; j < 16; j++) Nf[t + j * 256] = 0.f;

    // ---- stage x transposed: sXT[f][s], bf16 hi/lo, shuffle-packed pairs ----
    {
        int s = t & 63;
        int fg = t >> 6;                 // 4 groups of 16 f
        const float* xr = A + (size_t)s * 64 + fg * 16;
        bool evenS = (s & 1) == 0;
        int s0 = s & ~1;
#pragma unroll
        for (int q = 0; q < 4; q++) {
            float4 v = *(const float4*)(xr + q * 4);
            float vv[4] = {v.x, v.y, v.z, v.w};
#pragma unroll
            for (int e = 0; e < 4; e++) {
                int f = fg * 16 + q * 4 + e;
                __nv_bfloat16 hb = __float2bfloat16(vv[e]);
                __nv_bfloat16 lb = __float2bfloat16(vv[e] - __bfloat162float(hb));
                uint32_t u = (uint32_t)*(uint16_t*)&hb | ((uint32_t)*(uint16_t*)&lb << 16);
                uint32_t pu = __shfl_xor_sync(0xffffffffu, u, 1);
                if (evenS) {
                    uint32_t wh = (u & 0xffffu) | ((pu & 0xffffu) << 16);
                    uint32_t wl = (u >> 16) | (pu & 0xffff0000u);
                    *(uint32_t*)&sXTh[f * XTS + s0] = wh;
                    *(uint32_t*)&sXTl[f * XTS + s0] = wl;
                }
            }
        }
    }
    __syncthreads();
    atomicAdd(&sdeg[e_ed], e_w);
    atomicAdd(&sdeg2[e_es], e_w);
    __syncthreads();
    if (t < NN) {
        sdinv[t] = rsqrtf(sdeg[t] + 1.0f);
        float d2 = sdeg2[t];
        sdv2[t] = (d2 > 0.f) ? rsqrtf(fmaxf(d2, 1e-30f)) : 0.f;
    }
    __syncthreads();
    atomicAdd(&Nf[e_ed * 64 + e_es], sdinv[e_es] * e_w * sdinv[e_ed]);
    if (t < NN) atomicAdd(&Nf[t * 65], sdinv[t] * sdinv[t]);
    __syncthreads();

    // ---- convert N to bf16 split ----
#pragma unroll
    for (int j = 0; j < 16; j++) {
        int i = t + j * 256;
        int row = i >> 6, col = i & 63;
        float v = Nf[i];
        __nv_bfloat16 hb = __float2bfloat16(v);
        sNbh[row * TST + col] = hb;
        sNbl[row * TST + col] = __float2bfloat16(v - __bfloat162float(hb));
    }
    __syncthreads();

    // ---- GEMM1: Nx = N @ x  (M=64 n, N=64 f, K=64 s) ----
    int warpM1 = warp >> 2, warpN1 = warp & 3;   // 2 x 4, warp tile 32n x 16f
    float acc1[2][2][4];
#pragma unroll
    for (int mt = 0; mt < 2; mt++)
#pragma unroll
        for (int nt = 0; nt < 2; nt++)
#pragma unroll
            for (int j = 0; j < 4; j++) acc1[mt][nt][j] = 0.f;
#pragma unroll
    for (int ks = 0; ks < 4; ks++) {
        int kb = ks * 16 + (lane & 3) * 2;
        uint32_t ah[2][4], al[2][4];
#pragma unroll
        for (int mt = 0; mt < 2; mt++) {
            int r = warpM1 * 32 + mt * 16 + (lane >> 2);
            ah[mt][0] = *(const uint32_t*)&sNbh[r * TST + kb];
            ah[mt][1] = *(const uint32_t*)&sNbh[(r + 8) * TST + kb];
            ah[mt][2] = *(const uint32_t*)&sNbh[r * TST + kb + 8];
            ah[mt][3] = *(const uint32_t*)&sNbh[(r + 8) * TST + kb + 8];
            al[mt][0] = *(const uint32_t*)&sNbl[r * TST + kb];
            al[mt][1] = *(const uint32_t*)&sNbl[(r + 8) * TST + kb];
            al[mt][2] = *(const uint32_t*)&sNbl[r * TST + kb + 8];
            al[mt][3] = *(const uint32_t*)&sNbl[(r + 8) * TST + kb + 8];
        }
        uint32_t bhf[2][2], blf[2][2];
#pragma unroll
        for (int nt = 0; nt < 2; nt++) {
            int f = warpN1 * 16 + nt * 8 + (lane >> 2);
            bhf[nt][0] = *(const uint32_t*)&sXTh[f * XTS + kb];
            bhf[nt][1] = *(const uint32_t*)&sXTh[f * XTS + kb + 8];
            blf[nt][0] = *(const uint32_t*)&sXTl[f * XTS + kb];
            blf[nt][1] = *(const uint32_t*)&sXTl[f * XTS + kb + 8];
        }
#pragma unroll
        for (int mt = 0; mt < 2; mt++)
#pragma unroll
            for (int nt = 0; nt < 2; nt++) {
                mma_bf16(acc1[mt][nt], ah[mt], bhf[nt]);
                mma_bf16(acc1[mt][nt], ah[mt], blf[nt]);
                mma_bf16(acc1[mt][nt], al[mt], bhf[nt]);
            }
    }
    __syncthreads();   // xT + N reads done; Nx may overwrite region

    // ---- store Nx (bf16 split) [n][f] ----
#pragma unroll
    for (int mt = 0; mt < 2; mt++) {
        int n0 = warpM1 * 32 + mt * 16 + (lane >> 2);
#pragma unroll
        for (int nt = 0; nt < 2; nt++) {
            int f0 = warpN1 * 16 + nt * 8 + (lane & 3) * 2;
            uint32_t hA, lA, hB, lB;
            cvt_split2(acc1[mt][nt][0], acc1[mt][nt][1], hA, lA);
            cvt_split2(acc1[mt][nt][2], acc1[mt][nt][3], hB, lB);
            *(uint32_t*)&sNxh[n0 * TST + f0]       = hA;
            *(uint32_t*)&sNxl[n0 * TST + f0]       = lA;
            *(uint32_t*)&sNxh[(n0 + 8) * TST + f0] = hB;
            *(uint32_t*)&sNxl[(n0 + 8) * TST + f0] = lB;
        }
    }

    // ---- GEMM2: h = Nx @ Wg  (M=64 n, N=128 c, K=64 f) ----
    int warpM = warp >> 2, warpN = warp & 3;   // 2 x 4, warp tile 32n x 32c
    float acc2[2][4][4];
#pragma unroll
    for (int mt = 0; mt < 2; mt++)
#pragma unroll
        for (int nt = 0; nt < 4; nt++)
#pragma unroll
            for (int j = 0; j < 4; j++) acc2[mt][nt][j] = 0.f;

    int lbr = t >> 1, lbc = (t & 1) * 16;   // Wg chunk loader
    for (int kc = 0; kc < 64; kc += 32) {
        {
            const __nv_bfloat16* bh = d_wth + (size_t)lbr * 64 + kc + lbc;
            const __nv_bfloat16* bl = d_wtl + (size_t)lbr * 64 + kc + lbc;
            *(uint4*)&sWh[lbr * 40 + lbc]     = *(const uint4*)bh;
            *(uint4*)&sWh[lbr * 40 + lbc + 8] = *(const uint4*)(bh + 8);
            *(uint4*)&sWl[lbr * 40 + lbc]     = *(const uint4*)bl;
            *(uint4*)&sWl[lbr * 40 + lbc + 8] = *(const uint4*)(bl + 8);
        }
        __syncthreads();   // also orders Nx stores before first use
#pragma unroll
        for (int ks = 0; ks < 32; ks += 16) {
            int kb = ks + (lane & 3) * 2;
            uint32_t ah[2][4], al[2][4];
#pragma unroll
            for (int mt = 0; mt < 2; mt++) {
                int r = warpM * 32 + mt * 16 + (lane >> 2);
                int kf = kc + kb;
                ah[mt][0] = *(const uint32_t*)&sNxh[r * TST + kf];
                ah[mt][1] = *(const uint32_t*)&sNxh[(r + 8) * TST + kf];
                ah[mt][2] = *(const uint32_t*)&sNxh[r * TST + kf + 8];
                ah[mt][3] = *(const uint32_t*)&sNxh[(r + 8) * TST + kf + 8];
                al[mt][0] = *(const uint32_t*)&sNxl[r * TST + kf];
                al[mt][1] = *(const uint32_t*)&sNxl[(r + 8) * TST + kf];
                al[mt][2] = *(const uint32_t*)&sNxl[r * TST + kf + 8];
                al[mt][3] = *(const uint32_t*)&sNxl[(r + 8) * TST + kf + 8];
            }
            uint32_t bhf[4][2], blf[4][2];
#pragma unroll
            for (int nt = 0; nt < 4; nt++) {
                int r = warpN * 32 + nt * 8 + (lane >> 2);
                bhf[nt][0] = *(const uint32_t*)&sWh[r * 40 + kb];
                bhf[nt][1] = *(const uint32_t*)&sWh[r * 40 + kb + 8];
                blf[nt][0] = *(const uint32_t*)&sWl[r * 40 + kb];
                blf[nt][1] = *(const uint32_t*)&sWl[r * 40 + kb + 8];
            }
#pragma unroll
            for (int mt = 0; mt < 2; mt++)
#pragma unroll
                for (int nt = 0; nt < 4; nt++) {
                    mma_bf16(acc2[mt][nt], ah[mt], bhf[nt]);
                    mma_bf16(acc2[mt][nt], ah[mt], blf[nt]);
                    mma_bf16(acc2[mt][nt], al[mt], bhf[nt]);
                }
        }
        __syncthreads();
    }

    // ---- g_emb partials from fragments + h epilogue -> smem (overwrites Nx/W) ----
#pragma unroll
    for (int nt = 0; nt < 4; nt++) {
        float v0 = acc2[0][nt][0] + acc2[0][nt][2] + acc2[1][nt][0] + acc2[1][nt][2];
        float v1 = acc2[0][nt][1] + acc2[0][nt][3] + acc2[1][nt][1] + acc2[1][nt][3];
#pragma unroll
        for (int off = 4; off <= 16; off <<= 1) {
            v0 += __shfl_xor_sync(0xffffffffu, v0, off);
            v1 += __shfl_xor_sync(0xffffffffu, v1, off);
        }
        if ((lane >> 2) == 0) {
            int c0 = warpN * 32 + nt * 8 + (lane & 3) * 2;
            atomicAdd(&sgpart[c0], v0);
            atomicAdd(&sgpart[c0 + 1], v1);
        }
    }
#pragma unroll
    for (int mt = 0; mt < 2; mt++) {
        int n0 = warpM * 32 + mt * 16 + (lane >> 2);
#pragma unroll
        for (int nt = 0; nt < 4; nt++) {
            int c0 = warpN * 32 + nt * 8 + (lane & 3) * 2;
            float b0 = sbias[c0], b1 = sbias[c0 + 1];
            uint32_t hA, lA, hB, lB;
            cvt_split2(acc2[mt][nt][0] + b0, acc2[mt][nt][1] + b1, hA, lA);
            cvt_split2(acc2[mt][nt][2] + b0, acc2[mt][nt][3] + b1, hB, lB);
            *(uint32_t*)&shh[n0 * HST + c0]       = hA;
            *(uint32_t*)&shl[n0 * HST + c0]       = lA;
            *(uint32_t*)&shh[(n0 + 8) * HST + c0] = hB;
            *(uint32_t*)&shl[(n0 + 8) * HST + c0] = lB;
        }
    }
    __syncthreads();

    // ---- g_emb = 0.5*(sum + 64*bias) ----
    if (t < DD)
        d_gembs[(size_t)g * 128 + t] = 0.5f * (sgpart[t] + 64.f * sbias[t]);

    // ---- a1 = tanh(h @ Wf1 + bf1), logits, softmax -> sS (warps 0-3) ----
    if (warp < 4) {
        int r = lane >> 2, kb2 = (lane & 3) * 2;
        int rowW = warp * 16;
        float a16[2][4];
#pragma unroll
        for (int nt = 0; nt < 2; nt++)
#pragma unroll
            for (int j = 0; j < 4; j++) a16[nt][j] = 0.f;
        const __nv_bfloat16* Bh = d_wth + 237568;
        const __nv_bfloat16* Bl = d_wtl + 237568;
#pragma unroll
        for (int ks = 0; ks < 8; ks++) {
            int k0 = ks * 16 + kb2;
            uint32_t ah[4], al[4];
            ah[0] = *(const uint32_t*)&shh[(rowW + r) * HST + k0];
            ah[1] = *(const uint32_t*)&shh[(rowW + r + 8) * HST + k0];
            ah[2] = *(const uint32_t*)&shh[(rowW + r) * HST + k0 + 8];
            ah[3] = *(const uint32_t*)&shh[(rowW + r + 8) * HST + k0 + 8];
            al[0] = *(const uint32_t*)&shl[(rowW + r) * HST + k0];
            al[1] = *(const uint32_t*)&shl[(rowW + r + 8) * HST + k0];
            al[2] = *(const uint32_t*)&shl[(rowW + r) * HST + k0 + 8];
            al[3] = *(const uint32_t*)&shl[(rowW + r + 8) * HST + k0 + 8];
#pragma unroll
            for (int nt = 0; nt < 2; nt++) {
                int n = nt * 8 + r;
                uint32_t bh[2], bl[2];
                bh[0] = *(const uint32_t*)(Bh + n * 128 + k0);
                bh[1] = *(const uint32_t*)(Bh + n * 128 + k0 + 8);
                bl[0] = *(const uint32_t*)(Bl + n * 128 + k0);
                bl[1] = *(const uint32_t*)(Bl + n * 128 + k0 + 8);
                mma_bf16(a16[nt], ah, bh);
                mma_bf16(a16[nt], ah, bl);
                mma_bf16(a16[nt], al, bh);
            }
        }
        float l0a = 0.f, l1a = 0.f, l0b = 0.f, l1b = 0.f;
#pragma unroll
        for (int nt = 0; nt < 2; nt++) {
            int c0 = nt * 8 + (lane & 3) * 2;
            float b0 = bf1[c0], b1 = bf1[c0 + 1];
            float w00 = Wf2[c0 * 2], w01 = Wf2[c0 * 2 + 1];
            float w10 = Wf2[c0 * 2 + 2], w11 = Wf2[c0 * 2 + 3];
            float t0 = tanhf(a16[nt][0] + b0), t1 = tanhf(a16[nt][1] + b1);
            float t2 = tanhf(a16[nt][2] + b0), t3 = tanhf(a16[nt][3] + b1);
            l0a = fmaf(t0, w00, fmaf(t1, w10, l0a));
            l1a = fmaf(t0, w01, fmaf(t1, w11, l1a));
            l0b = fmaf(t2, w00, fmaf(t3, w10, l0b));
            l1b = fmaf(t2, w01, fmaf(t3, w11, l1b));
        }
#pragma unroll
        for (int off = 1; off <= 2; off <<= 1) {
            l0a += __shfl_xor_sync(0xffffffffu, l0a, off);
            l1a += __shfl_xor_sync(0xffffffffu, l1a, off);
            l0b += __shfl_xor_sync(0xffffffffu, l0b, off);
            l1b += __shfl_xor_sync(0xffffffffu, l1b, off);
        }
        if ((lane & 3) == 0) {
            float b20 = bf2[0], b21 = bf2[1];
            float la0 = l0a + b20, la1 = l1a + b21;
            float m = fmaxf(la0, la1);
            float e0 = expf(la0 - m), e1 = expf(la1 - m);
            float inv = 1.f / (e0 + e1);
            sS[(rowW + r) * 2]     = e0 * inv;
            sS[(rowW + r) * 2 + 1] = e1 * inv;
            float lb0 = l0b + b20, lb1 = l1b + b21;
            float m2 = fmaxf(lb0, lb1);
            float f0 = expf(lb0 - m2), f1 = expf(lb1 - m2);
            float inv2 = 1.f / (f0 + f1);
            sS[(rowW + r + 8) * 2]     = f0 * inv2;
            sS[(rowW + r + 8) * 2 + 1] = f1 * inv2;
        }
    }
    __syncthreads();

    // ---- Laplacian penalty ----
    {
        float p[4] = {0, 0, 0, 0};
        if (t < NN) {
            float s0 = sS[t * 2], s1 = sS[t * 2 + 1];
            p[0] = s0 * s0; p[1] = s0 * s1; p[2] = s1 * s0; p[3] = s1 * s1;
        }
        {
            float lw = -sdv2[e_es] * e_w * sdv2[e_ed];
            float q0 = sS[e_es * 2], q1 = sS[e_es * 2 + 1];
            float r0 = sS[e_ed * 2], r1 = sS[e_ed * 2 + 1];
            p[0] = fmaf(lw, q0 * r0, p[0]);
            p[1] = fmaf(lw, q0 * r1, p[1]);
            p[2] = fmaf(lw, q1 * r0, p[2]);
            p[3] = fmaf(lw, q1 * r1, p[3]);
        }
#pragma unroll
        for (int off = 16; off; off >>= 1)
#pragma unroll
            for (int j = 0; j < 4; j++)
                p[j] += __shfl_down_sync(0xffffffffu, p[j], off);
        if (lane == 0) {
#pragma unroll
            for (int j = 0; j < 4; j++) atomicAdd(&sped[j], p[j]);
        }
    }
    __syncthreads();
    if (t == 0) {
        float A00 = sped[0], A01 = sped[1], A10 = sped[2], A11 = sped[3];
        float r0 = fmaxf(fabsf(A00) + fabsf(A01), 1e-12f);
        float r1 = fmaxf(fabsf(A10) + fabsf(A11), 1e-12f);
        float dd0 = A00 / r0 - 1.f, dd1 = A11 / r1 - 1.f;
        atomicAdd(&d_sums[0], 0.5f * (dd0 * dd0 + dd1 * dd1));
    }
}

// ---------------- dual-output mma.sync GEMM: C = act(A @ W + b) ----------------
__global__ void __launch_bounds__(256) k_mma(
    int selA, int K, int nx0,
    int wtoff0, int wtoff1,
    const float* __restrict__ b0v, const float* __restrict__ b1v,
    int selC0, int selC1, int Cs, int act0, int act1)
{
    __shared__ __nv_bfloat16 sAh[128][40];
    __shared__ __nv_bfloat16 sAl[128][40];
    __shared__ __nv_bfloat16 sBh[128][40];
    __shared__ __nv_bfloat16 sBl[128][40];
    __shared__ float sbias[128];

    int t = threadIdx.x;
    const float* A = (selA == 1) ? d_agg1 : (selA == 2) ? d_agg2 : d_zc;
    int bx = blockIdx.x;
    int hsel = bx >= nx0;
    int colBase = (bx - (hsel ? nx0 : 0)) * 128;
    int wtoff = hsel ? wtoff1 : wtoff0;
    const float* bias = hsel ? b1v : b0v;
    int act = hsel ? act1 : act0;
    int selC = hsel ? selC1 : selC0;
    float* C = (selC == 1) ? d_h : (selC == 2) ? d_mu
             : (selC == 3) ? d_ls : (selC == 4) ? d_zl1 : d_zl2;
    int rowBase = blockIdx.y * 128;
    if (t < 128) sbias[t] = bias[colBase + t];

    int lane = t & 31, warp = t >> 5;
    int warpM = warp >> 2, warpN = warp & 3;

    float acc[4][4][4];
#pragma unroll
    for (int mt = 0; mt < 4; mt++)
#pragma unroll
        for (int nt = 0; nt < 4; nt++)
#pragma unroll
            for (int j = 0; j < 4; j++) acc[mt][nt][j] = 0.f;

    int ldr = t >> 1, ldc = (t & 1) * 16;

    for (int kc = 0; kc < K; kc += 32) {
        const float* Ar = A + (size_t)(rowBase + ldr) * K + kc + ldc;
#pragma unroll
        for (int j = 0; j < 4; j++) {
            float4 v = *(const float4*)(Ar + j * 4);
            uint32_t h0, l0, h1, l1;
            cvt_split2(v.x, v.y, h0, l0);
            cvt_split2(v.z, v.w, h1, l1);
            *(uint32_t*)&sAh[ldr][ldc + j * 4]     = h0;
            *(uint32_t*)&sAh[ldr][ldc + j * 4 + 2] = h1;
            *(uint32_t*)&sAl[ldr][ldc + j * 4]     = l0;
            *(uint32_t*)&sAl[ldr][ldc + j * 4 + 2] = l1;
        }
        {
            const __nv_bfloat16* bh = d_wth + wtoff + (size_t)(colBase + ldr) * K + kc + ldc;
            const __nv_bfloat16* bl = d_wtl + wtoff + (size_t)(colBase + ldr) * K + kc + ldc;
            *(uint4*)&sBh[ldr][ldc]     = *(const uint4*)bh;
            *(uint4*)&sBh[ldr][ldc + 8] = *(const uint4*)(bh + 8);
            *(uint4*)&sBl[ldr][ldc]     = *(const uint4*)bl;
            *(uint4*)&sBl[ldr][ldc + 8] = *(const uint4*)(bl + 8);
        }
        __syncthreads();
#pragma unroll
        for (int ks = 0; ks < 32; ks += 16) {
            int kb = ks + (lane & 3) * 2;
            int ar = warpM * 64 + (lane >> 2);
            uint32_t ah[4][4], al[4][4];
#pragma unroll
            for (int mt = 0; mt < 4; mt++) {
                int r = ar + mt * 16;
                ah[mt][0] = *(const uint32_t*)&sAh[r][kb];
                ah[mt][1] = *(const uint32_t*)&sAh[r + 8][kb];
                ah[mt][2] = *(const uint32_t*)&sAh[r][kb + 8];
                ah[mt][3] = *(const uint32_t*)&sAh[r + 8][kb + 8];
                al[mt][0] = *(const uint32_t*)&sAl[r][kb];
                al[mt][1] = *(const uint32_t*)&sAl[r + 8][kb];
                al[mt][2] = *(const uint32_t*)&sAl[r][kb + 8];
                al[mt][3] = *(const uint32_t*)&sAl[r + 8][kb + 8];
            }
            uint32_t bhf[4][2], blf[4][2];
#pragma unroll
            for (int nt = 0; nt < 4; nt++) {
                int r = warpN * 32 + nt * 8 + (lane >> 2);
                bhf[nt][0] = *(const uint32_t*)&sBh[r][kb];
                bhf[nt][1] = *(const uint32_t*)&sBh[r][kb + 8];
                blf[nt][0] = *(const uint32_t*)&sBl[r][kb];
                blf[nt][1] = *(const uint32_t*)&sBl[r][kb + 8];
            }
#pragma unroll
            for (int mt = 0; mt < 4; mt++)
#pragma unroll
                for (int nt = 0; nt < 4; nt++) {
                    mma_bf16(acc[mt][nt], ah[mt], bhf[nt]);
                    mma_bf16(acc[mt][nt], ah[mt], blf[nt]);
                    mma_bf16(acc[mt][nt], al[mt], bhf[nt]);
                }
        }
        __syncthreads();
    }

#pragma unroll
    for (int mt = 0; mt < 4; mt++) {
        int r0 = rowBase + warpM * 64 + mt * 16 + (lane >> 2);
#pragma unroll
        for (int nt = 0; nt < 4; nt++) {
            int cl = warpN * 32 + nt * 8 + (lane & 3) * 2;
            float b0 = sbias[cl], b1 = sbias[cl + 1];
            float2 v0, v1;
            v0.x = acc[mt][nt][0] + b0; v0.y = acc[mt][nt][1] + b1;
            v1.x = acc[mt][nt][2] + b0; v1.y = acc[mt][nt][3] + b1;
            if (act == 1) {
                v0.x = fmaxf(v0.x, 0.f); v0.y = fmaxf(v0.y, 0.f);
                v1.x = fmaxf(v1.x, 0.f); v1.y = fmaxf(v1.y, 0.f);
            } else if (act == 2) {
                v0.x = fminf(v0.x, 10.f); v0.y = fminf(v0.y, 10.f);
                v1.x = fminf(v1.x, 10.f); v1.y = fminf(v1.y, 10.f);
            }
            *(float2*)&C[(size_t)r0 * Cs + colBase + cl] = v0;
            *(float2*)&C[(size_t)(r0 + 8) * Cs + colBase + cl] = v1;
        }
    }
}

// ---------------- scatter (warp/edge), float4 vector atomics ----------------
__global__ void __launch_bounds__(256) k_scatter(const int* __restrict__ pe, int sel) {
    int tid = blockIdx.x * 256 + threadIdx.x;   // 0 .. EPN*32-1
    int gw = tid >> 5, lane = tid & 31;
    int a = pe[gw], b = pe[EPN + gw];
    float norm = d_deg[a] * d_deg[b];
    if (sel == 0) {
        const float4* X = (const float4*)(d_gembs + (size_t)a * DD);
        float4* Ag = (float4*)(d_agg1 + (size_t)b * DD);
        float4 v = X[lane];
        v.x *= norm; v.y *= norm; v.z *= norm; v.w *= norm;
        atomicAdd(&Ag[lane], v);
        if (tid < G * DD / 4) {
            float di = d_deg[tid >> 5];
            float d2 = di * di;
            float4 s = ((const float4*)d_gembs)[tid];
            s.x *= d2; s.y *= d2; s.z *= d2; s.w *= d2;
            atomicAdd(&((float4*)d_agg1)[tid], s);
        }
    } else {
        const float4* X = (const float4*)(d_h + (size_t)a * 256);
        float4* Ag = (float4*)(d_agg2 + (size_t)b * 256);
#pragma unroll
        for (int q = 0; q < 2; q++) {
            float4 v = X[lane + 32 * q];
            v.x *= norm; v.y *= norm; v.z *= norm; v.w *= norm;
            atomicAdd(&Ag[lane + 32 * q], v);
        }
        if (tid < G * 256 / 4) {
            float di = d_deg[tid >> 6];
            float d2 = di * di;
            float4 s = ((const float4*)d_h)[tid];
            s.x *= d2; s.y *= d2; s.z *= d2; s.w *= d2;
            atomicAdd(&((float4*)d_agg2)[tid], s);
        }
    }
}

// ---------------- z, zc, KL ----------------
__global__ void __launch_bounds__(256) k_z(const float* __restrict__ eps_,
                                           const float* __restrict__ emb) {
    int i = blockIdx.x * 256 + threadIdx.x;
    float m = d_mu[i], l = d_ls[i];
    int n = i >> 7, d = i & 127;
    float z = m + eps_[i] * expf(l);
    d_zc[(size_t)n * 256 + d] = emb[i];
    d_zc[(size_t)n * 256 + 128 + d] = z;
    float klt = 1.f + 2.f * l - m * m - expf(2.f * l);
    for (int off = 16; off; off >>= 1) klt += __shfl_down_sync(0xffffffffu, klt, off);
    __shared__ float sw[8];
    if ((threadIdx.x & 31) == 0) sw[threadIdx.x >> 5] = klt;
    __syncthreads();
    if (threadIdx.x == 0) {
        float s = 0;
        for (int j = 0; j < 8; j++) s += sw[j];
        atomicAdd(&d_sums[3], s);
    }
}

// ---------------- edge predictions + log sums ----------------
__global__ void __launch_bounds__(256) k_pred(const int* __restrict__ pe,
                                              const int* __restrict__ ne,
                                              float* __restrict__ out) {
    int gw = (blockIdx.x * 256 + threadIdx.x) >> 5;
    int lane = threadIdx.x & 31;
    int wib = threadIdx.x >> 5;
    bool isneg = gw >= EPN;
    int i = isneg ? gw - EPN : gw;
    const int* e = isneg ? ne : pe;
    int a = e[i], b = e[EPN + i];
    const float4* ra = (const float4*)(d_zl1 + (size_t)a * 256);
    const float4* rb = (const float4*)(d_zl2 + (size_t)b * 256);
    float s = 0.f;
#pragma unroll
    for (int q = 0; q < 2; q++) {
        float4 u = ra[lane + 32 * q], v = rb[lane + 32 * q];
        s += u.x * v.x + u.y * v.y + u.z * v.z + u.w * v.w;
    }
    for (int off = 16; off; off >>= 1) s += __shfl_down_sync(0xffffffffu, s, off);
    __shared__ float sl[8];
    if (lane == 0) {
        float p = 1.f / (1.f + expf(-s));
        out[2 + gw] = p;
        sl[wib] = isneg ? logf(1.f - p + 1e-15f) : logf(p + 1e-15f);
    }
    __syncthreads();
    if (threadIdx.x == 0) {
        float tt = 0;
        for (int j = 0; j < 8; j++) tt += sl[j];
        atomicAdd(isneg ? &d_sums[2] : &d_sums[1], tt);
    }
}

__global__ void k_final(float* __restrict__ out) {
    float rec = -(d_sums[1] / (float)EPN) - (d_sums[2] / (float)EPN);
    float kl = -0.5f * d_sums[3] / (float)G;
    out[0] = rec + kl / (float)G;
    out[1] = d_sums[0] / (float)G;
}

// ---------------- launch ----------------
extern "C" void kernel_launch(void* const* d_in, const int* in_sizes, int n_in,
                              void* d_out, int out_size) {
    const float* x   = (const float*)d_in[0];
    const int*   ei  = (const int*)d_in[1];
    const float* ew  = (const float*)d_in[2];
    const int*   pe  = (const int*)d_in[3];
    const int*   ne  = (const int*)d_in[4];
    const float* eps_= (const float*)d_in[5];
    const float* Wg  = (const float*)d_in[6];
    const float* bg  = (const float*)d_in[7];
    const float* Wf1 = (const float*)d_in[8];
    const float* bf1 = (const float*)d_in[9];
    const float* Wf2 = (const float*)d_in[10];
    const float* bf2 = (const float*)d_in[11];
    const float* Wc1 = (const float*)d_in[12];
    const float* bc1 = (const float*)d_in[13];
    const float* Wmu = (const float*)d_in[14];
    const float* bmu = (const float*)d_in[15];
    const float* Wls = (const float*)d_in[16];
    const float* bls = (const float*)d_in[17];
    const float* emb = (const float*)d_in[18];
    const float* Wl1 = (const float*)d_in[19];
    const float* bl1 = (const float*)d_in[20];
    const float* Wl2 = (const float*)d_in[21];
    const float* bl2 = (const float*)d_in[22];
    float* out = (float*)d_out;

    const int dyn_xw = 53248;   // 3 CTAs/SM
    cudaFuncSetAttribute(k_xwagg, cudaFuncAttributeMaxDynamicSharedMemorySize, dyn_xw);

    k_zero<<<1024, 256>>>(pe);
    k_prepw<<<234, 1024>>>(Wg, Wc1, Wmu, Wls, Wl1, Wl2, Wf1);
    k_deg<<<EPN / 256, 256>>>(pe);
    k_xwagg<<<G, 256, dyn_xw>>>(x, ei, ew, bg, bf1, Wf2, bf2);
    k_dinv<<<G / 256, 256>>>();
    k_scatter<<<EPN * 32 / 256, 256>>>(pe, 0);
    // h = relu(agg1 @ Wc1 + bc1)   [4096x128]@[128x256]
    k_mma<<<dim3(2, 32), 256>>>(1, 128, 2, 8192, 8192, bc1, bc1, 1, 1, 256, 1, 1);
    k_scatter<<<EPN * 32 / 256, 256>>>(pe, 1);
    // mu | ls   [4096x256]@[256x128] x2 in one launch
    k_mma<<<dim3(2, 32), 256>>>(2, 256, 1, 40960, 73728, bmu, bls, 2, 3, 128, 0, 2);
    k_z<<<G * DD / 256, 256>>>(eps_, emb);
    // zl1 | zl2   [4096x256]@[256x256] x2 in one launch
    k_mma<<<dim3(4, 32), 256>>>(3, 256, 2, 106496, 172032, bl1, bl2, 4, 5, 256, 0, 0);
    k_pred<<<2 * EPN * 32 / 256, 256>>>(pe, ne, out);
    k_final<<<1, 1>>>(out);
}